// round 6
// baseline (speedup 1.0000x reference)
#include <cuda_runtime.h>
#include <cuda_bf16.h>
#include <cstdint>
#include <math.h>

#define L_  8
#define D_  1024
#define H_  16
#define DH_ 64
#define DI_ 4096
#define V_  32000
#define B_  2
#define S_  1024
#define T_  (B_*S_)

// ---------------- scratch ----------------
__device__ float g_h   [T_*D_];
__device__ float g_hn  [T_*D_];
__device__ float g_q   [T_*D_];
__device__ float g_k   [T_*D_];
__device__ float g_v   [T_*D_];
__device__ float g_y   [T_*D_];
__device__ float g_gate[T_*DI_];
__device__ float g_up  [T_*DI_];
__device__ float g_att [(size_t)B_*H_*S_*S_];
__device__ float g_cos [S_*32];
__device__ float g_sin [S_*32];

// ---------------- small kernels ----------------
__global__ void embed_kernel(const int* __restrict__ x, const float* __restrict__ emb,
                             float* __restrict__ h) {
    int i = blockIdx.x * blockDim.x + threadIdx.x;
    int t = i / (D_/4);
    int c = i % (D_/4);
    float4 v = *(const float4*)(emb + (size_t)x[t]*D_ + c*4);
    *(float4*)(h + (size_t)t*D_ + c*4) = v;
}

__global__ void rope_cache_kernel() {
    int i = blockIdx.x * blockDim.x + threadIdx.x;
    if (i >= S_*32) return;
    int s = i / 32, j = i % 32;
    double inv = pow(10000.0, -(double)j / 32.0);
    double ph = (double)s * inv;
    g_cos[i] = (float)cos(ph);
    g_sin[i] = (float)sin(ph);
}

__global__ void rope_kernel(float* __restrict__ q, float* __restrict__ k) {
    int i = blockIdx.x * blockDim.x + threadIdx.x;
    int t = i >> 9;
    int r = i & 511;
    int h = r >> 5, d = r & 31;
    int s = t & (S_-1);
    float c  = g_cos[s*32 + d];
    float sn = g_sin[s*32 + d];
    size_t base = (size_t)t*D_ + h*DH_ + d;
    float a, b;
    a = q[base]; b = q[base+32];
    q[base]    = a*c - b*sn;
    q[base+32] = b*c + a*sn;
    a = k[base]; b = k[base+32];
    k[base]    = a*c - b*sn;
    k[base+32] = b*c + a*sn;
}

__global__ void rmsnorm_kernel(const float* __restrict__ x, const float* __restrict__ w,
                               float* __restrict__ o) {
    int t = blockIdx.x;
    int tid = threadIdx.x;
    const float* xp = x + (size_t)t*D_;
    float v[4];
    float s = 0.f;
    #pragma unroll
    for (int i = 0; i < 4; i++) { v[i] = xp[tid + i*256]; s += v[i]*v[i]; }
    #pragma unroll
    for (int off = 16; off; off >>= 1) s += __shfl_xor_sync(0xffffffffu, s, off);
    __shared__ float red[8];
    if ((tid & 31) == 0) red[tid >> 5] = s;
    __syncthreads();
    if (tid < 32) {
        float s2 = (tid < 8) ? red[tid] : 0.f;
        #pragma unroll
        for (int off = 4; off; off >>= 1) s2 += __shfl_xor_sync(0xffffffffu, s2, off);
        if (tid == 0) red[0] = s2;
    }
    __syncthreads();
    float r = rsqrtf(red[0] * (1.f/(float)D_) + 1e-6f);
    float* op = o + (size_t)t*D_;
    #pragma unroll
    for (int i = 0; i < 4; i++) op[tid + i*256] = w[tid + i*256] * v[i] * r;
}

// causal softmax: masks j>row at read, writes zeros beyond row.
__global__ void softmax_kernel(float* __restrict__ att) {
    int row = blockIdx.x & (S_-1);
    float* p = att + (size_t)blockIdx.x * S_;
    int tid = threadIdx.x;
    float vals[4];
    float mx = -INFINITY;
    #pragma unroll
    for (int i = 0; i < 4; i++) {
        int j = tid + i*256;
        vals[i] = (j <= row) ? p[j] : -INFINITY;
        mx = fmaxf(mx, vals[i]);
    }
    #pragma unroll
    for (int off = 16; off; off >>= 1) mx = fmaxf(mx, __shfl_xor_sync(0xffffffffu, mx, off));
    __shared__ float redm[8];
    if ((tid & 31) == 0) redm[tid >> 5] = mx;
    __syncthreads();
    if (tid < 32) {
        float m2 = (tid < 8) ? redm[tid] : -INFINITY;
        #pragma unroll
        for (int off = 4; off; off >>= 1) m2 = fmaxf(m2, __shfl_xor_sync(0xffffffffu, m2, off));
        if (tid == 0) redm[0] = m2;
    }
    __syncthreads();
    float m = redm[0];
    float s = 0.f;
    #pragma unroll
    for (int i = 0; i < 4; i++) { vals[i] = expf(vals[i] - m); s += vals[i]; }
    #pragma unroll
    for (int off = 16; off; off >>= 1) s += __shfl_xor_sync(0xffffffffu, s, off);
    __shared__ float reds[8];
    if ((tid & 31) == 0) reds[tid >> 5] = s;
    __syncthreads();
    if (tid < 32) {
        float s2 = (tid < 8) ? reds[tid] : 0.f;
        #pragma unroll
        for (int off = 4; off; off >>= 1) s2 += __shfl_xor_sync(0xffffffffu, s2, off);
        if (tid == 0) reds[0] = s2;
    }
    __syncthreads();
    float inv = 1.f / reds[0];
    #pragma unroll
    for (int i = 0; i < 4; i++) p[tid + i*256] = vals[i] * inv;
}

// ---------------- bf16x3 split-precision tensor-core GEMM ----------------
enum { EPI_NONE = 0, EPI_BIAS = 1, EPI_BIAS_RES = 2, EPI_RES = 3, EPI_SCORES = 4, EPI_SILU = 5 };

__device__ __forceinline__ void mma_bf16(float* d, const uint32_t* a, const uint32_t* b) {
    asm volatile(
        "mma.sync.aligned.m16n8k16.row.col.f32.bf16.bf16.f32 "
        "{%0,%1,%2,%3}, {%4,%5,%6,%7}, {%8,%9}, {%0,%1,%2,%3};\n"
        : "+f"(d[0]), "+f"(d[1]), "+f"(d[2]), "+f"(d[3])
        : "r"(a[0]), "r"(a[1]), "r"(a[2]), "r"(a[3]),
          "r"(b[0]), "r"(b[1]));
}

// ldmatrix x4: fills 4 regs; addresses from all 32 lanes (16B each)
__device__ __forceinline__ void ldsm_x4(uint32_t* r, const uint32_t* p) {
    uint32_t a = (uint32_t)__cvta_generic_to_shared(p);
    asm volatile("ldmatrix.sync.aligned.m8n8.x4.shared.b16 {%0,%1,%2,%3}, [%4];"
        : "=r"(r[0]), "=r"(r[1]), "=r"(r[2]), "=r"(r[3]) : "r"(a));
}

__device__ __forceinline__ void split2(float a, float b, uint32_t& hi, uint32_t& lo) {
    __nv_bfloat16 ha = __float2bfloat16(a);
    __nv_bfloat16 hb = __float2bfloat16(b);
    __nv_bfloat16 la = __float2bfloat16(a - __bfloat162float(ha));
    __nv_bfloat16 lb = __float2bfloat16(b - __bfloat162float(hb));
    hi = ((uint32_t)__bfloat16_as_ushort(hb) << 16) | __bfloat16_as_ushort(ha);
    lo = ((uint32_t)__bfloat16_as_ushort(lb) << 16) | __bfloat16_as_ushort(la);
}

template<int BM, int BN, int BK, int WM, int WN, bool BT, int EPI, bool TRIMK>
__global__ __launch_bounds__((BM/WM)*(BN/WN)*32)
void gemm_tc(const float* __restrict__ A, const float* __restrict__ Bm,
             float* __restrict__ C, const float* __restrict__ bias,
             int M, int N, int K, int lda, int ldb, int ldc,
             int zinner,
             long long sAo, long long sAi,
             long long sBo, long long sBi,
             long long sCo, long long sCi,
             float scale)
{
    constexpr int WARPS_N = BN/WN;
    constexpr int THREADS = (BM/WM)*(BN/WN)*32;
    constexpr int MT = WM/16;
    constexpr int NT = WN/8;               // even (WN=32 -> NT=4)
    constexpr int SP = BK/2 + 4;           // uint32 stride per row
    constexpr int SZA = BM*SP;
    constexpr int SZB = BN*SP;
    constexpr int STAGE = 2*SZA + 2*SZB;
    constexpr int NA = (BM*BK/4)/THREADS;
    constexpr int NB = BT ? (BN*BK/4)/THREADS : (BK*BN/4)/THREADS;

    extern __shared__ uint32_t smem_u[];

    const int tid = threadIdx.x;
    const int z  = blockIdx.z;
    const int zo = z / zinner, zi = z % zinner;
    const float* Ab = A  + zo*sAo + zi*sAi;
    const float* Bb = Bm + zo*sBo + zi*sBi;
    float*       Cb = C  + zo*sCo + zi*sCi;
    const int m0 = blockIdx.y * BM;
    const int n0 = blockIdx.x * BN;

    if (EPI == EPI_SCORES && n0 >= m0 + BM) return;

    const int warp = tid >> 5;
    const int lane = tid & 31;
    const int g = lane >> 2;
    const int c = lane & 3;
    const int wn = warp % WARPS_N;
    const int wm = warp / WARPS_N;
    const int lrow = lane & 15;            // ldmatrix row select
    const int lkq  = (lane >> 4) << 2;     // ldmatrix k-half (word offset)

    float acc[MT][NT][4];
    #pragma unroll
    for (int i = 0; i < MT; i++)
        #pragma unroll
        for (int j = 0; j < NT; j++)
            #pragma unroll
            for (int r = 0; r < 4; r++) acc[i][j][r] = 0.f;

    const int Kend = TRIMK ? min(K, m0 + BM) : K;
    const int nk = Kend / BK;

    float4 pa[NA], pb[NB];

    auto load_gmem = [&](int kt) {
        #pragma unroll
        for (int i = 0; i < NA; i++) {
            int f  = tid + i*THREADS;
            int r  = f / (BK/4);
            int c4 = f % (BK/4);
            pa[i] = *(const float4*)(Ab + (size_t)(m0+r)*lda + kt + c4*4);
        }
        if (BT) {
            #pragma unroll
            for (int i = 0; i < NB; i++) {
                int f  = tid + i*THREADS;
                int r  = f / (BK/4);
                int c4 = f % (BK/4);
                pb[i] = *(const float4*)(Bb + (size_t)(n0+r)*ldb + kt + c4*4);
            }
        } else {
            #pragma unroll
            for (int i = 0; i < NB; i++) {
                int f  = tid + i*THREADS;
                int r  = f / (BN/4);
                int c4 = f % (BN/4);
                pb[i] = *(const float4*)(Bb + (size_t)(kt+r)*ldb + n0 + c4*4);
            }
        }
    };

    auto store_split = [&](int s) {
        uint32_t* Ah = smem_u + s*STAGE;
        uint32_t* Al = Ah + SZA;
        uint32_t* Bh = Al + SZA;
        uint32_t* Bl = Bh + SZB;
        #pragma unroll
        for (int i = 0; i < NA; i++) {
            int f  = tid + i*THREADS;
            int r  = f / (BK/4);
            int c4 = f % (BK/4);
            uint32_t h0, l0, h1, l1;
            split2(pa[i].x, pa[i].y, h0, l0);
            split2(pa[i].z, pa[i].w, h1, l1);
            Ah[r*SP + c4*2]   = h0; Ah[r*SP + c4*2+1] = h1;
            Al[r*SP + c4*2]   = l0; Al[r*SP + c4*2+1] = l1;
        }
        if (BT) {
            #pragma unroll
            for (int i = 0; i < NB; i++) {
                int f  = tid + i*THREADS;
                int r  = f / (BK/4);
                int c4 = f % (BK/4);
                uint32_t h0, l0, h1, l1;
                split2(pb[i].x, pb[i].y, h0, l0);
                split2(pb[i].z, pb[i].w, h1, l1);
                Bh[r*SP + c4*2]   = h0; Bh[r*SP + c4*2+1] = h1;
                Bl[r*SP + c4*2]   = l0; Bl[r*SP + c4*2+1] = l1;
            }
        } else {
            #pragma unroll
            for (int i = 0; i < NB; i++) {
                int f  = tid + i*THREADS;
                int r  = f / (BN/4);
                int c4 = f % (BN/4);
                float vv[4] = {pb[i].x, pb[i].y, pb[i].z, pb[i].w};
                #pragma unroll
                for (int q = 0; q < 4; q++) {
                    __nv_bfloat16 hb = __float2bfloat16(vv[q]);
                    __nv_bfloat16 lb = __float2bfloat16(vv[q] - __bfloat162float(hb));
                    ((uint16_t*)(Bh + (c4*4+q)*SP))[r] = __bfloat16_as_ushort(hb);
                    ((uint16_t*)(Bl + (c4*4+q)*SP))[r] = __bfloat16_as_ushort(lb);
                }
            }
        }
    };

    load_gmem(0);
    store_split(0);
    __syncthreads();

    for (int t = 0; t < nk; t++) {
        const int cur = t & 1;
        if (t + 1 < nk) load_gmem((t+1)*BK);

        const uint32_t* Ah = smem_u + cur*STAGE;
        const uint32_t* Al = Ah + SZA;
        const uint32_t* Bh = Al + SZA;
        const uint32_t* Bl = Bh + SZB;

        #pragma unroll
        for (int ks = 0; ks < BK; ks += 16) {
            const int kp = (ks >> 1) + lkq;
            uint32_t ah[MT][4], al[MT][4], bh[NT/2][4], bl[NT/2][4];
            // A fragments: one ldmatrix.x4 per 16-row tile (hi and lo)
            #pragma unroll
            for (int i = 0; i < MT; i++) {
                const int ro = (wm*WM + i*16 + lrow)*SP + kp;
                ldsm_x4(ah[i], Ah + ro);
                ldsm_x4(al[i], Al + ro);
            }
            // B fragments: one ldmatrix.x4 covers two adjacent n8 tiles
            #pragma unroll
            for (int jj = 0; jj < NT/2; jj++) {
                const int ro = (wn*WN + jj*16 + lrow)*SP + kp;
                ldsm_x4(bh[jj], Bh + ro);
                ldsm_x4(bl[jj], Bl + ro);
            }
            #pragma unroll
            for (int i = 0; i < MT; i++)
                #pragma unroll
                for (int jj = 0; jj < NT/2; jj++) {
                    uint32_t b0h[2] = {bh[jj][0], bh[jj][2]};
                    uint32_t b1h[2] = {bh[jj][1], bh[jj][3]};
                    uint32_t b0l[2] = {bl[jj][0], bl[jj][2]};
                    uint32_t b1l[2] = {bl[jj][1], bl[jj][3]};
                    mma_bf16(acc[i][2*jj],   ah[i], b0h);
                    mma_bf16(acc[i][2*jj],   ah[i], b0l);
                    mma_bf16(acc[i][2*jj],   al[i], b0h);
                    mma_bf16(acc[i][2*jj+1], ah[i], b1h);
                    mma_bf16(acc[i][2*jj+1], ah[i], b1l);
                    mma_bf16(acc[i][2*jj+1], al[i], b1h);
                }
        }

        if (t + 1 < nk) store_split(cur ^ 1);
        __syncthreads();
    }

    #pragma unroll
    for (int i = 0; i < MT; i++) {
        #pragma unroll
        for (int j = 0; j < NT; j++) {
            int n = n0 + wn*WN + j*8 + 2*c;
            #pragma unroll
            for (int rr = 0; rr < 2; rr++) {
                int m = m0 + wm*WM + i*16 + g + rr*8;
                float v0 = acc[i][j][rr*2 + 0];
                float v1 = acc[i][j][rr*2 + 1];
                size_t off = (size_t)m*ldc + n;
                if (EPI == EPI_BIAS)          { v0 += bias[n]; v1 += bias[n+1]; }
                else if (EPI == EPI_BIAS_RES) { v0 += bias[n]   + Cb[off];
                                                v1 += bias[n+1] + Cb[off+1]; }
                else if (EPI == EPI_RES)      { v0 += Cb[off]; v1 += Cb[off+1]; }
                else if (EPI == EPI_SCORES)   { v0 *= scale; v1 *= scale; }
                else if (EPI == EPI_SILU)     {
                    float g0 = Cb[off], g1 = Cb[off+1];
                    v0 *= g0 / (1.f + expf(-g0));
                    v1 *= g1 / (1.f + expf(-g1));
                }
                *(float2*)(Cb + off) = make_float2(v0, v1);
            }
        }
    }
}

// ---------------- host ----------------
template<int BM, int BN, int BK>
constexpr int smem_bytes() {
    return 2 * (2*BM*(BK/2+4) + 2*BN*(BK/2+4)) * 4;
}

extern "C" void kernel_launch(void* const* d_in, const int* in_sizes, int n_in,
                              void* d_out, int out_size) {
    const int*   x      = (const int*)  d_in[0];
    const float* emb    = (const float*)d_in[1];
    const float* wq     = (const float*)d_in[2];
    const float* bq     = (const float*)d_in[3];
    const float* wk     = (const float*)d_in[4];
    const float* bk     = (const float*)d_in[5];
    const float* wv     = (const float*)d_in[6];
    const float* bv     = (const float*)d_in[7];
    const float* wo     = (const float*)d_in[8];
    const float* bo     = (const float*)d_in[9];
    const float* w_gate = (const float*)d_in[10];
    const float* w_up   = (const float*)d_in[11];
    const float* w_down = (const float*)d_in[12];
    const float* ln1    = (const float*)d_in[13];
    const float* ln2    = (const float*)d_in[14];
    const float* norm_w = (const float*)d_in[15];
    float* out = (float*)d_out;

    float *h, *hn, *q, *k, *v, *y, *gate, *up, *att;
    cudaGetSymbolAddress((void**)&h,    g_h);
    cudaGetSymbolAddress((void**)&hn,   g_hn);
    cudaGetSymbolAddress((void**)&q,    g_q);
    cudaGetSymbolAddress((void**)&k,    g_k);
    cudaGetSymbolAddress((void**)&v,    g_v);
    cudaGetSymbolAddress((void**)&y,    g_y);
    cudaGetSymbolAddress((void**)&gate, g_gate);
    cudaGetSymbolAddress((void**)&up,   g_up);
    cudaGetSymbolAddress((void**)&att,  g_att);

    constexpr int SM_P = smem_bytes<128,64,32>();    // 61440
    constexpr int SM_M = smem_bytes<128,128,32>();   // 81920

    cudaFuncSetAttribute(gemm_tc<128,64,32,32,32,true,EPI_BIAS,false>,     cudaFuncAttributeMaxDynamicSharedMemorySize, SM_P);
    cudaFuncSetAttribute(gemm_tc<128,128,32,64,32,true,EPI_SCORES,false>,  cudaFuncAttributeMaxDynamicSharedMemorySize, SM_M);
    cudaFuncSetAttribute(gemm_tc<128,64,32,32,32,false,EPI_NONE,true>,     cudaFuncAttributeMaxDynamicSharedMemorySize, SM_P);
    cudaFuncSetAttribute(gemm_tc<128,64,32,32,32,true,EPI_BIAS_RES,false>, cudaFuncAttributeMaxDynamicSharedMemorySize, SM_P);
    cudaFuncSetAttribute(gemm_tc<128,128,32,64,32,true,EPI_NONE,false>,    cudaFuncAttributeMaxDynamicSharedMemorySize, SM_M);
    cudaFuncSetAttribute(gemm_tc<128,128,32,64,32,true,EPI_SILU,false>,    cudaFuncAttributeMaxDynamicSharedMemorySize, SM_M);
    cudaFuncSetAttribute(gemm_tc<128,64,32,32,32,true,EPI_RES,false>,      cudaFuncAttributeMaxDynamicSharedMemorySize, SM_P);

    embed_kernel<<<T_*D_/4/256, 256>>>(x, emb, h);
    rope_cache_kernel<<<(S_*32 + 255)/256, 256>>>();

    const dim3 gp(D_/64,   T_/128, 1);
    const dim3 gm(DI_/128, T_/128, 1);
    const dim3 gs(S_/128,  S_/128, B_*H_);
    const dim3 ga(1,       S_/128, B_*H_);

    for (int l = 0; l < L_; l++) {
        rmsnorm_kernel<<<T_, 256>>>(h, ln1 + (size_t)l*D_, hn);

        gemm_tc<128,64,32,32,32,true,EPI_BIAS,false><<<gp,256,SM_P>>>(
            hn, wq + (size_t)l*D_*D_, q, bq + (size_t)l*D_,
            T_, D_, D_, D_, D_, D_, 1, 0,0,0,0,0,0, 0.f);
        gemm_tc<128,64,32,32,32,true,EPI_BIAS,false><<<gp,256,SM_P>>>(
            hn, wk + (size_t)l*D_*D_, k, bk + (size_t)l*D_,
            T_, D_, D_, D_, D_, D_, 1, 0,0,0,0,0,0, 0.f);
        gemm_tc<128,64,32,32,32,true,EPI_BIAS,false><<<gp,256,SM_P>>>(
            hn, wv + (size_t)l*D_*D_, v, bv + (size_t)l*D_,
            T_, D_, D_, D_, D_, D_, 1, 0,0,0,0,0,0, 0.f);

        rope_kernel<<<T_*H_*32/256, 256>>>(q, k);

        gemm_tc<128,128,32,64,32,true,EPI_SCORES,false><<<gs,256,SM_M>>>(
            q, k, att, nullptr,
            S_, S_, DH_, D_, D_, S_,
            H_,
            (long long)S_*D_, (long long)DH_,
            (long long)S_*D_, (long long)DH_,
            (long long)H_*S_*S_, (long long)S_*S_,
            0.125f);

        softmax_kernel<<<B_*H_*S_, 256>>>(att);

        gemm_tc<128,64,32,32,32,false,EPI_NONE,true><<<ga,256,SM_P>>>(
            att, v, y, nullptr,
            S_, DH_, S_, S_, D_, D_,
            H_,
            (long long)H_*S_*S_, (long long)S_*S_,
            (long long)S_*D_, (long long)DH_,
            (long long)S_*D_, (long long)DH_,
            0.f);

        gemm_tc<128,64,32,32,32,true,EPI_BIAS_RES,false><<<gp,256,SM_P>>>(
            y, wo + (size_t)l*D_*D_, h, bo + (size_t)l*D_,
            T_, D_, D_, D_, D_, D_, 1, 0,0,0,0,0,0, 0.f);

        rmsnorm_kernel<<<T_, 256>>>(h, ln2 + (size_t)l*D_, hn);

        gemm_tc<128,128,32,64,32,true,EPI_NONE,false><<<gm,256,SM_M>>>(
            hn, w_gate + (size_t)l*DI_*D_, gate, nullptr,
            T_, DI_, D_, D_, D_, DI_, 1, 0,0,0,0,0,0, 0.f);
        gemm_tc<128,128,32,64,32,true,EPI_SILU,false><<<gm,256,SM_M>>>(
            hn, w_up + (size_t)l*DI_*D_, gate, nullptr,
            T_, DI_, D_, D_, D_, DI_, 1, 0,0,0,0,0,0, 0.f);

        gemm_tc<128,64,32,32,32,true,EPI_RES,false><<<gp,256,SM_P>>>(
            gate, w_down + (size_t)l*D_*DI_, h, nullptr,
            T_, D_, DI_, DI_, DI_, D_, 1, 0,0,0,0,0,0, 0.f);
    }

    rmsnorm_kernel<<<T_, 256>>>(h, norm_w, hn);

    const dim3 gl(V_/128, T_/128, 1);
    gemm_tc<128,128,32,64,32,true,EPI_NONE,false><<<gl,256,SM_M>>>(
        hn, emb, out, nullptr,
        T_, V_, D_, D_, D_, V_, 1, 0,0,0,0,0,0, 0.f);
}

// round 7
// speedup vs baseline: 1.0862x; 1.0862x over previous
#include <cuda_runtime.h>
#include <cuda_bf16.h>
#include <cstdint>
#include <math.h>

#define L_  8
#define D_  1024
#define H_  16
#define DH_ 64
#define DI_ 4096
#define V_  32000
#define B_  2
#define S_  1024
#define T_  (B_*S_)

typedef __nv_bfloat16 bf16;

// ---------------- fp32 scratch ----------------
__device__ float g_h   [T_*D_];
__device__ float g_q   [T_*D_];
__device__ float g_k   [T_*D_];
__device__ float g_gate[T_*DI_];
__device__ float g_att [(size_t)B_*H_*S_*S_];
__device__ float g_cos [S_*32];
__device__ float g_sin [S_*32];

// ---------------- split bf16 scratch (hi/lo) ----------------
__device__ bf16 s_wq_h[L_*D_*D_],   s_wq_l[L_*D_*D_];
__device__ bf16 s_wk_h[L_*D_*D_],   s_wk_l[L_*D_*D_];
__device__ bf16 s_wv_h[L_*D_*D_],   s_wv_l[L_*D_*D_];
__device__ bf16 s_wo_h[L_*D_*D_],   s_wo_l[L_*D_*D_];
__device__ bf16 s_wg_h[L_*DI_*D_],  s_wg_l[L_*DI_*D_];
__device__ bf16 s_wu_h[L_*DI_*D_],  s_wu_l[L_*DI_*D_];
__device__ bf16 s_wd_h[L_*D_*DI_],  s_wd_l[L_*D_*DI_];
__device__ bf16 s_emb_h[V_*D_],     s_emb_l[V_*D_];
__device__ bf16 s_hn_h[T_*D_],      s_hn_l[T_*D_];
__device__ bf16 s_q_h [T_*D_],      s_q_l [T_*D_];
__device__ bf16 s_k_h [T_*D_],      s_k_l [T_*D_];
__device__ bf16 s_v_h [T_*D_],      s_v_l [T_*D_];
__device__ bf16 s_y_h [T_*D_],      s_y_l [T_*D_];
__device__ bf16 s_ga_h[T_*DI_],     s_ga_l[T_*DI_];
__device__ bf16 s_att_h[(size_t)B_*H_*S_*S_], s_att_l[(size_t)B_*H_*S_*S_];

// ---------------- helpers ----------------
__device__ __forceinline__ void split1(float v, bf16& h, bf16& l) {
    h = __float2bfloat16(v);
    l = __float2bfloat16(v - __bfloat162float(h));
}

__device__ __forceinline__ void split_store2(bf16* H, bf16* Lo, size_t off, float v0, float v1) {
    bf16 h0, l0, h1, l1;
    split1(v0, h0, l0);
    split1(v1, h1, l1);
    __nv_bfloat162 th; th.x = h0; th.y = h1;
    __nv_bfloat162 tl; tl.x = l0; tl.y = l1;
    *(__nv_bfloat162*)(H  + off) = th;
    *(__nv_bfloat162*)(Lo + off) = tl;
}

// ---------------- prep: split fp32 tensor into bf16 hi/lo ----------------
__global__ void split_kernel(const float* __restrict__ x, bf16* __restrict__ h,
                             bf16* __restrict__ l, int n4) {
    int i = blockIdx.x * blockDim.x + threadIdx.x;
    if (i >= n4) return;
    float4 v = ((const float4*)x)[i];
    bf16 h0,l0,h1,l1,h2,l2,h3,l3;
    split1(v.x, h0, l0); split1(v.y, h1, l1);
    split1(v.z, h2, l2); split1(v.w, h3, l3);
    ushort4 th = make_ushort4(__bfloat16_as_ushort(h0), __bfloat16_as_ushort(h1),
                              __bfloat16_as_ushort(h2), __bfloat16_as_ushort(h3));
    ushort4 tl = make_ushort4(__bfloat16_as_ushort(l0), __bfloat16_as_ushort(l1),
                              __bfloat16_as_ushort(l2), __bfloat16_as_ushort(l3));
    ((ushort4*)h)[i] = th;
    ((ushort4*)l)[i] = tl;
}

// ---------------- small kernels ----------------
__global__ void embed_kernel(const int* __restrict__ x, const float* __restrict__ emb,
                             float* __restrict__ h) {
    int i = blockIdx.x * blockDim.x + threadIdx.x;
    int t = i / (D_/4);
    int c = i % (D_/4);
    float4 v = *(const float4*)(emb + (size_t)x[t]*D_ + c*4);
    *(float4*)(h + (size_t)t*D_ + c*4) = v;
}

__global__ void rope_cache_kernel() {
    int i = blockIdx.x * blockDim.x + threadIdx.x;
    if (i >= S_*32) return;
    int s = i / 32, j = i % 32;
    double inv = pow(10000.0, -(double)j / 32.0);
    double ph = (double)s * inv;
    g_cos[i] = (float)cos(ph);
    g_sin[i] = (float)sin(ph);
}

// rope: read fp32 q/k, write split bf16
__global__ void rope_kernel(const float* __restrict__ q, const float* __restrict__ k) {
    int i = blockIdx.x * blockDim.x + threadIdx.x;
    int t = i >> 9;
    int r = i & 511;
    int h = r >> 5, d = r & 31;
    int s = t & (S_-1);
    float c  = g_cos[s*32 + d];
    float sn = g_sin[s*32 + d];
    size_t base = (size_t)t*D_ + h*DH_ + d;
    float a, b, r0, r1;
    a = q[base]; b = q[base+32];
    r0 = a*c - b*sn;  r1 = b*c + a*sn;
    split1(r0, s_q_h[base],    s_q_l[base]);
    split1(r1, s_q_h[base+32], s_q_l[base+32]);
    a = k[base]; b = k[base+32];
    r0 = a*c - b*sn;  r1 = b*c + a*sn;
    split1(r0, s_k_h[base],    s_k_l[base]);
    split1(r1, s_k_h[base+32], s_k_l[base+32]);
}

// rmsnorm: fp32 in, split bf16 out
__global__ void rmsnorm_kernel(const float* __restrict__ x, const float* __restrict__ w,
                               bf16* __restrict__ oh, bf16* __restrict__ ol) {
    int t = blockIdx.x;
    int tid = threadIdx.x;
    const float* xp = x + (size_t)t*D_;
    float v[4];
    float s = 0.f;
    #pragma unroll
    for (int i = 0; i < 4; i++) { v[i] = xp[tid + i*256]; s += v[i]*v[i]; }
    #pragma unroll
    for (int off = 16; off; off >>= 1) s += __shfl_xor_sync(0xffffffffu, s, off);
    __shared__ float red[8];
    if ((tid & 31) == 0) red[tid >> 5] = s;
    __syncthreads();
    if (tid < 32) {
        float s2 = (tid < 8) ? red[tid] : 0.f;
        #pragma unroll
        for (int off = 4; off; off >>= 1) s2 += __shfl_xor_sync(0xffffffffu, s2, off);
        if (tid == 0) red[0] = s2;
    }
    __syncthreads();
    float r = rsqrtf(red[0] * (1.f/(float)D_) + 1e-6f);
    size_t base = (size_t)t*D_;
    #pragma unroll
    for (int i = 0; i < 4; i++) {
        int idx = tid + i*256;
        split1(w[idx] * v[i] * r, oh[base+idx], ol[base+idx]);
    }
}

// causal softmax: fp32 scores in, split bf16 probs out (zeros past row)
__global__ void softmax_kernel(const float* __restrict__ att,
                               bf16* __restrict__ oh, bf16* __restrict__ ol) {
    int row = blockIdx.x & (S_-1);
    const float* p = att + (size_t)blockIdx.x * S_;
    int tid = threadIdx.x;
    float vals[4];
    float mx = -INFINITY;
    #pragma unroll
    for (int i = 0; i < 4; i++) {
        int j = tid + i*256;
        vals[i] = (j <= row) ? p[j] : -INFINITY;
        mx = fmaxf(mx, vals[i]);
    }
    #pragma unroll
    for (int off = 16; off; off >>= 1) mx = fmaxf(mx, __shfl_xor_sync(0xffffffffu, mx, off));
    __shared__ float redm[8];
    if ((tid & 31) == 0) redm[tid >> 5] = mx;
    __syncthreads();
    if (tid < 32) {
        float m2 = (tid < 8) ? redm[tid] : -INFINITY;
        #pragma unroll
        for (int off = 4; off; off >>= 1) m2 = fmaxf(m2, __shfl_xor_sync(0xffffffffu, m2, off));
        if (tid == 0) redm[0] = m2;
    }
    __syncthreads();
    float m = redm[0];
    float s = 0.f;
    #pragma unroll
    for (int i = 0; i < 4; i++) { vals[i] = expf(vals[i] - m); s += vals[i]; }
    #pragma unroll
    for (int off = 16; off; off >>= 1) s += __shfl_xor_sync(0xffffffffu, s, off);
    __shared__ float reds[8];
    if ((tid & 31) == 0) reds[tid >> 5] = s;
    __syncthreads();
    if (tid < 32) {
        float s2 = (tid < 8) ? reds[tid] : 0.f;
        #pragma unroll
        for (int off = 4; off; off >>= 1) s2 += __shfl_xor_sync(0xffffffffu, s2, off);
        if (tid == 0) reds[0] = s2;
    }
    __syncthreads();
    float inv = 1.f / reds[0];
    size_t base = (size_t)blockIdx.x * S_;
    #pragma unroll
    for (int i = 0; i < 4; i++) {
        int j = tid + i*256;
        split1(vals[i] * inv, oh[base+j], ol[base+j]);
    }
}

// ---------------- bf16x3 GEMM on pre-split operands ----------------
enum { EPI_NONE = 0, EPI_BIAS = 1, EPI_BIAS_RES = 2, EPI_RES = 3, EPI_SCORES = 4,
       EPI_BIAS_SPLIT = 5, EPI_SPLIT = 6, EPI_SILU_SPLIT = 7 };

__device__ __forceinline__ void mma_bf16(float* d, const uint32_t* a, const uint32_t* b) {
    asm volatile(
        "mma.sync.aligned.m16n8k16.row.col.f32.bf16.bf16.f32 "
        "{%0,%1,%2,%3}, {%4,%5,%6,%7}, {%8,%9}, {%0,%1,%2,%3};\n"
        : "+f"(d[0]), "+f"(d[1]), "+f"(d[2]), "+f"(d[3])
        : "r"(a[0]), "r"(a[1]), "r"(a[2]), "r"(a[3]),
          "r"(b[0]), "r"(b[1]));
}

// A: bf16 [M,K] row-major (hi+lo).  BT=true: B bf16 [N,K]; BT=false: B bf16 [K,N].
template<int BM, int BN, int BK, int WM, int WN, bool BT, int EPI, bool TRIMK>
__global__ __launch_bounds__((BM/WM)*(BN/WN)*32)
void gemm_tc(const bf16* __restrict__ Agh, const bf16* __restrict__ Agl,
             const bf16* __restrict__ Bgh, const bf16* __restrict__ Bgl,
             float* __restrict__ C, bf16* __restrict__ Oh, bf16* __restrict__ Ol,
             const float* __restrict__ bias,
             int M, int N, int K, int lda, int ldb, int ldc,
             int zinner,
             long long sAo, long long sAi,
             long long sBo, long long sBi,
             long long sCo, long long sCi,
             float scale)
{
    constexpr int WARPS_N = BN/WN;
    constexpr int THREADS = (BM/WM)*(BN/WN)*32;
    constexpr int MT = WM/16;
    constexpr int NT = WN/8;
    constexpr int SP = BK/2 + 4;            // uint32 stride per row (20)
    constexpr int SZA = BM*SP;
    constexpr int SZB = BN*SP;
    constexpr int STAGE = 2*SZA + 2*SZB;
    constexpr int NA = (BM*BK/8)/THREADS;   // uint4 loads per split array (A)
    constexpr int NB = (BT ? (BN*BK/8) : (BK*BN/8)) / THREADS;

    extern __shared__ uint32_t smem_u[];

    const int tid = threadIdx.x;
    const int z  = blockIdx.z;
    const int zo = z / zinner, zi = z % zinner;
    const bf16* Abh = Agh + zo*sAo + zi*sAi;
    const bf16* Abl = Agl + zo*sAo + zi*sAi;
    const bf16* Bbh = Bgh + zo*sBo + zi*sBi;
    const bf16* Bbl = Bgl + zo*sBo + zi*sBi;
    float* Cb  = C  ? (C  + zo*sCo + zi*sCi) : nullptr;
    bf16*  Ohb = Oh ? (Oh + zo*sCo + zi*sCi) : nullptr;
    bf16*  Olb = Ol ? (Ol + zo*sCo + zi*sCi) : nullptr;
    const int m0 = blockIdx.y * BM;
    const int n0 = blockIdx.x * BN;

    if (EPI == EPI_SCORES && n0 >= m0 + BM) return;

    const int warp = tid >> 5;
    const int lane = tid & 31;
    const int g = lane >> 2;
    const int c = lane & 3;
    const int wn = warp % WARPS_N;
    const int wm = warp / WARPS_N;

    float acc[MT][NT][4];
    #pragma unroll
    for (int i = 0; i < MT; i++)
        #pragma unroll
        for (int j = 0; j < NT; j++)
            #pragma unroll
            for (int r = 0; r < 4; r++) acc[i][j][r] = 0.f;

    const int Kend = TRIMK ? min(K, m0 + BM) : K;
    const int nk = Kend / BK;

    uint4 pah[NA], pal[NA], pbh[NB], pbl[NB];

    auto load_gmem = [&](int kt) {
        #pragma unroll
        for (int i = 0; i < NA; i++) {
            int f  = tid + i*THREADS;
            int r  = f / (BK/8);
            int c8 = f % (BK/8);
            size_t off = (size_t)(m0+r)*lda + kt + c8*8;
            pah[i] = *(const uint4*)(Abh + off);
            pal[i] = *(const uint4*)(Abl + off);
        }
        if (BT) {
            #pragma unroll
            for (int i = 0; i < NB; i++) {
                int f  = tid + i*THREADS;
                int r  = f / (BK/8);
                int c8 = f % (BK/8);
                size_t off = (size_t)(n0+r)*ldb + kt + c8*8;
                pbh[i] = *(const uint4*)(Bbh + off);
                pbl[i] = *(const uint4*)(Bbl + off);
            }
        } else {
            #pragma unroll
            for (int i = 0; i < NB; i++) {
                int f  = tid + i*THREADS;
                int r  = f / (BN/8);
                int c8 = f % (BN/8);
                size_t off = (size_t)(kt+r)*ldb + n0 + c8*8;
                pbh[i] = *(const uint4*)(Bbh + off);
                pbl[i] = *(const uint4*)(Bbl + off);
            }
        }
    };

    auto store_smem = [&](int s) {
        uint32_t* Ah = smem_u + s*STAGE;
        uint32_t* Al = Ah + SZA;
        uint32_t* Bh = Al + SZA;
        uint32_t* Bl = Bh + SZB;
        #pragma unroll
        for (int i = 0; i < NA; i++) {
            int f  = tid + i*THREADS;
            int r  = f / (BK/8);
            int c8 = f % (BK/8);
            *(uint4*)&Ah[r*SP + c8*4] = pah[i];
            *(uint4*)&Al[r*SP + c8*4] = pal[i];
        }
        if (BT) {
            #pragma unroll
            for (int i = 0; i < NB; i++) {
                int f  = tid + i*THREADS;
                int r  = f / (BK/8);
                int c8 = f % (BK/8);
                *(uint4*)&Bh[r*SP + c8*4] = pbh[i];
                *(uint4*)&Bl[r*SP + c8*4] = pbl[i];
            }
        } else {
            // transpose: independent 16-bit stores (race-free)
            #pragma unroll
            for (int i = 0; i < NB; i++) {
                int f  = tid + i*THREADS;
                int r  = f / (BN/8);          // k within tile
                int c8 = f % (BN/8);
                const uint16_t* uh = (const uint16_t*)&pbh[i];
                const uint16_t* ul = (const uint16_t*)&pbl[i];
                #pragma unroll
                for (int q = 0; q < 8; q++) {
                    ((uint16_t*)(Bh + (c8*8+q)*SP))[r] = uh[q];
                    ((uint16_t*)(Bl + (c8*8+q)*SP))[r] = ul[q];
                }
            }
        }
    };

    load_gmem(0);
    store_smem(0);
    __syncthreads();

    for (int t = 0; t < nk; t++) {
        const int cur = t & 1;
        if (t + 1 < nk) load_gmem((t+1)*BK);

        const uint32_t* Ah = smem_u + cur*STAGE;
        const uint32_t* Al = Ah + SZA;
        const uint32_t* Bh = Al + SZA;
        const uint32_t* Bl = Bh + SZB;

        #pragma unroll
        for (int ks = 0; ks < BK; ks += 16) {
            const int kp = ks >> 1;
            uint32_t ah[MT][4], al[MT][4], bh[NT][2], bl[NT][2];
            #pragma unroll
            for (int i = 0; i < MT; i++) {
                int mr = wm*WM + i*16 + g;
                ah[i][0] = Ah[mr*SP     + kp + c];   al[i][0] = Al[mr*SP     + kp + c];
                ah[i][1] = Ah[(mr+8)*SP + kp + c];   al[i][1] = Al[(mr+8)*SP + kp + c];
                ah[i][2] = Ah[mr*SP     + kp + c+4]; al[i][2] = Al[mr*SP     + kp + c+4];
                ah[i][3] = Ah[(mr+8)*SP + kp + c+4]; al[i][3] = Al[(mr+8)*SP + kp + c+4];
            }
            #pragma unroll
            for (int j = 0; j < NT; j++) {
                int nr = wn*WN + j*8 + g;
                bh[j][0] = Bh[nr*SP + kp + c];   bl[j][0] = Bl[nr*SP + kp + c];
                bh[j][1] = Bh[nr*SP + kp + c+4]; bl[j][1] = Bl[nr*SP + kp + c+4];
            }
            // term-outer: maximize independent MMA chains per accumulator
            #pragma unroll
            for (int i = 0; i < MT; i++)
                #pragma unroll
                for (int j = 0; j < NT; j++)
                    mma_bf16(acc[i][j], ah[i], bh[j]);
            #pragma unroll
            for (int i = 0; i < MT; i++)
                #pragma unroll
                for (int j = 0; j < NT; j++)
                    mma_bf16(acc[i][j], ah[i], bl[j]);
            #pragma unroll
            for (int i = 0; i < MT; i++)
                #pragma unroll
                for (int j = 0; j < NT; j++)
                    mma_bf16(acc[i][j], al[i], bh[j]);
        }

        if (t + 1 < nk) store_smem(cur ^ 1);
        __syncthreads();
    }

    #pragma unroll
    for (int i = 0; i < MT; i++) {
        #pragma unroll
        for (int j = 0; j < NT; j++) {
            int n = n0 + wn*WN + j*8 + 2*c;
            #pragma unroll
            for (int rr = 0; rr < 2; rr++) {
                int m = m0 + wm*WM + i*16 + g + rr*8;
                float v0 = acc[i][j][rr*2 + 0];
                float v1 = acc[i][j][rr*2 + 1];
                size_t off = (size_t)m*ldc + n;
                if (EPI == EPI_BIAS) {
                    v0 += bias[n]; v1 += bias[n+1];
                    *(float2*)(Cb + off) = make_float2(v0, v1);
                } else if (EPI == EPI_BIAS_RES) {
                    v0 += bias[n]   + Cb[off];
                    v1 += bias[n+1] + Cb[off+1];
                    *(float2*)(Cb + off) = make_float2(v0, v1);
                } else if (EPI == EPI_RES) {
                    v0 += Cb[off]; v1 += Cb[off+1];
                    *(float2*)(Cb + off) = make_float2(v0, v1);
                } else if (EPI == EPI_SCORES) {
                    *(float2*)(Cb + off) = make_float2(v0*scale, v1*scale);
                } else if (EPI == EPI_NONE) {
                    *(float2*)(Cb + off) = make_float2(v0, v1);
                } else if (EPI == EPI_BIAS_SPLIT) {
                    split_store2(Ohb, Olb, off, v0 + bias[n], v1 + bias[n+1]);
                } else if (EPI == EPI_SPLIT) {
                    split_store2(Ohb, Olb, off, v0, v1);
                } else if (EPI == EPI_SILU_SPLIT) {
                    float g0 = Cb[off], g1 = Cb[off+1];
                    v0 *= g0 / (1.f + expf(-g0));
                    v1 *= g1 / (1.f + expf(-g1));
                    split_store2(Ohb, Olb, off, v0, v1);
                }
            }
        }
    }
}

// ---------------- host ----------------
template<int BM, int BN, int BK>
constexpr int smem_bytes() {
    return 2 * (2*BM*(BK/2+4) + 2*BN*(BK/2+4)) * 4;
}

extern "C" void kernel_launch(void* const* d_in, const int* in_sizes, int n_in,
                              void* d_out, int out_size) {
    const int*   x      = (const int*)  d_in[0];
    const float* emb    = (const float*)d_in[1];
    const float* wq     = (const float*)d_in[2];
    const float* bq     = (const float*)d_in[3];
    const float* wk     = (const float*)d_in[4];
    const float* bk     = (const float*)d_in[5];
    const float* wv     = (const float*)d_in[6];
    const float* bv     = (const float*)d_in[7];
    const float* wo     = (const float*)d_in[8];
    const float* bo     = (const float*)d_in[9];
    const float* w_gate = (const float*)d_in[10];
    const float* w_up   = (const float*)d_in[11];
    const float* w_down = (const float*)d_in[12];
    const float* ln1    = (const float*)d_in[13];
    const float* ln2    = (const float*)d_in[14];
    const float* norm_w = (const float*)d_in[15];
    float* out = (float*)d_out;

    float *h, *q, *k, *gate, *att;
    cudaGetSymbolAddress((void**)&h,    g_h);
    cudaGetSymbolAddress((void**)&q,    g_q);
    cudaGetSymbolAddress((void**)&k,    g_k);
    cudaGetSymbolAddress((void**)&gate, g_gate);
    cudaGetSymbolAddress((void**)&att,  g_att);

    bf16 *wqh,*wql,*wkh,*wkl,*wvh,*wvl,*woh,*wol,*wgh,*wgl,*wuh,*wul,*wdh,*wdl,*embh,*embl;
    bf16 *hnh,*hnl,*qh,*ql,*kh,*kl,*vh,*vl,*yh,*yl,*gah,*gal,*atth,*attl;
    cudaGetSymbolAddress((void**)&wqh, s_wq_h);  cudaGetSymbolAddress((void**)&wql, s_wq_l);
    cudaGetSymbolAddress((void**)&wkh, s_wk_h);  cudaGetSymbolAddress((void**)&wkl, s_wk_l);
    cudaGetSymbolAddress((void**)&wvh, s_wv_h);  cudaGetSymbolAddress((void**)&wvl, s_wv_l);
    cudaGetSymbolAddress((void**)&woh, s_wo_h);  cudaGetSymbolAddress((void**)&wol, s_wo_l);
    cudaGetSymbolAddress((void**)&wgh, s_wg_h);  cudaGetSymbolAddress((void**)&wgl, s_wg_l);
    cudaGetSymbolAddress((void**)&wuh, s_wu_h);  cudaGetSymbolAddress((void**)&wul, s_wu_l);
    cudaGetSymbolAddress((void**)&wdh, s_wd_h);  cudaGetSymbolAddress((void**)&wdl, s_wd_l);
    cudaGetSymbolAddress((void**)&embh, s_emb_h); cudaGetSymbolAddress((void**)&embl, s_emb_l);
    cudaGetSymbolAddress((void**)&hnh, s_hn_h);  cudaGetSymbolAddress((void**)&hnl, s_hn_l);
    cudaGetSymbolAddress((void**)&qh,  s_q_h);   cudaGetSymbolAddress((void**)&ql,  s_q_l);
    cudaGetSymbolAddress((void**)&kh,  s_k_h);   cudaGetSymbolAddress((void**)&kl,  s_k_l);
    cudaGetSymbolAddress((void**)&vh,  s_v_h);   cudaGetSymbolAddress((void**)&vl,  s_v_l);
    cudaGetSymbolAddress((void**)&yh,  s_y_h);   cudaGetSymbolAddress((void**)&yl,  s_y_l);
    cudaGetSymbolAddress((void**)&gah, s_ga_h);  cudaGetSymbolAddress((void**)&gal, s_ga_l);
    cudaGetSymbolAddress((void**)&atth, s_att_h); cudaGetSymbolAddress((void**)&attl, s_att_l);

    constexpr int SM_P = smem_bytes<128,64,32>();    // 61440
    constexpr int SM_M = smem_bytes<128,128,32>();   // 81920

    cudaFuncSetAttribute(gemm_tc<128,64,32,32,32,true,EPI_BIAS,false>,       cudaFuncAttributeMaxDynamicSharedMemorySize, SM_P);
    cudaFuncSetAttribute(gemm_tc<128,64,32,32,32,true,EPI_BIAS_SPLIT,false>, cudaFuncAttributeMaxDynamicSharedMemorySize, SM_P);
    cudaFuncSetAttribute(gemm_tc<128,128,32,64,32,true,EPI_SCORES,false>,    cudaFuncAttributeMaxDynamicSharedMemorySize, SM_M);
    cudaFuncSetAttribute(gemm_tc<128,64,32,32,32,false,EPI_SPLIT,true>,      cudaFuncAttributeMaxDynamicSharedMemorySize, SM_P);
    cudaFuncSetAttribute(gemm_tc<128,64,32,32,32,true,EPI_BIAS_RES,false>,   cudaFuncAttributeMaxDynamicSharedMemorySize, SM_P);
    cudaFuncSetAttribute(gemm_tc<128,128,32,64,32,true,EPI_NONE,false>,      cudaFuncAttributeMaxDynamicSharedMemorySize, SM_M);
    cudaFuncSetAttribute(gemm_tc<128,128,32,64,32,true,EPI_SILU_SPLIT,false>,cudaFuncAttributeMaxDynamicSharedMemorySize, SM_M);
    cudaFuncSetAttribute(gemm_tc<128,64,32,32,32,true,EPI_RES,false>,        cudaFuncAttributeMaxDynamicSharedMemorySize, SM_P);

    // ---- prep: split weights + embedding ----
    auto split_launch = [](const float* src, bf16* dh, bf16* dl, size_t n) {
        int n4 = (int)(n / 4);
        split_kernel<<<(n4 + 255)/256, 256>>>(src, dh, dl, n4);
    };
    split_launch(wq, wqh, wql, (size_t)L_*D_*D_);
    split_launch(wk, wkh, wkl, (size_t)L_*D_*D_);
    split_launch(wv, wvh, wvl, (size_t)L_*D_*D_);
    split_launch(wo, woh, wol, (size_t)L_*D_*D_);
    split_launch(w_gate, wgh, wgl, (size_t)L_*DI_*D_);
    split_launch(w_up,   wuh, wul, (size_t)L_*DI_*D_);
    split_launch(w_down, wdh, wdl, (size_t)L_*D_*DI_);
    split_launch(emb, embh, embl, (size_t)V_*D_);

    embed_kernel<<<T_*D_/4/256, 256>>>(x, emb, h);
    rope_cache_kernel<<<(S_*32 + 255)/256, 256>>>();

    const dim3 gp(D_/64,   T_/128, 1);
    const dim3 gm(DI_/128, T_/128, 1);
    const dim3 gs(S_/128,  S_/128, B_*H_);
    const dim3 ga(1,       S_/128, B_*H_);

    for (int l = 0; l < L_; l++) {
        rmsnorm_kernel<<<T_, 256>>>(h, ln1 + (size_t)l*D_, hnh, hnl);

        gemm_tc<128,64,32,32,32,true,EPI_BIAS,false><<<gp,256,SM_P>>>(
            hnh, hnl, wqh + (size_t)l*D_*D_, wql + (size_t)l*D_*D_,
            q, nullptr, nullptr, bq + (size_t)l*D_,
            T_, D_, D_, D_, D_, D_, 1, 0,0,0,0,0,0, 0.f);
        gemm_tc<128,64,32,32,32,true,EPI_BIAS,false><<<gp,256,SM_P>>>(
            hnh, hnl, wkh + (size_t)l*D_*D_, wkl + (size_t)l*D_*D_,
            k, nullptr, nullptr, bk + (size_t)l*D_,
            T_, D_, D_, D_, D_, D_, 1, 0,0,0,0,0,0, 0.f);
        gemm_tc<128,64,32,32,32,true,EPI_BIAS_SPLIT,false><<<gp,256,SM_P>>>(
            hnh, hnl, wvh + (size_t)l*D_*D_, wvl + (size_t)l*D_*D_,
            nullptr, vh, vl, bv + (size_t)l*D_,
            T_, D_, D_, D_, D_, D_, 1, 0,0,0,0,0,0, 0.f);

        rope_kernel<<<T_*H_*32/256, 256>>>(q, k);

        gemm_tc<128,128,32,64,32,true,EPI_SCORES,false><<<gs,256,SM_M>>>(
            qh, ql, kh, kl, att, nullptr, nullptr, nullptr,
            S_, S_, DH_, D_, D_, S_,
            H_,
            (long long)S_*D_, (long long)DH_,
            (long long)S_*D_, (long long)DH_,
            (long long)H_*S_*S_, (long long)S_*S_,
            0.125f);

        softmax_kernel<<<B_*H_*S_, 256>>>(att, atth, attl);

        gemm_tc<128,64,32,32,32,false,EPI_SPLIT,true><<<ga,256,SM_P>>>(
            atth, attl, vh, vl, nullptr, yh, yl, nullptr,
            S_, DH_, S_, S_, D_, D_,
            H_,
            (long long)H_*S_*S_, (long long)S_*S_,
            (long long)S_*D_, (long long)DH_,
            (long long)S_*D_, (long long)DH_,
            0.f);

        gemm_tc<128,64,32,32,32,true,EPI_BIAS_RES,false><<<gp,256,SM_P>>>(
            yh, yl, woh + (size_t)l*D_*D_, wol + (size_t)l*D_*D_,
            h, nullptr, nullptr, bo + (size_t)l*D_,
            T_, D_, D_, D_, D_, D_, 1, 0,0,0,0,0,0, 0.f);

        rmsnorm_kernel<<<T_, 256>>>(h, ln2 + (size_t)l*D_, hnh, hnl);

        gemm_tc<128,128,32,64,32,true,EPI_NONE,false><<<gm,256,SM_M>>>(
            hnh, hnl, wgh + (size_t)l*DI_*D_, wgl + (size_t)l*DI_*D_,
            gate, nullptr, nullptr, nullptr,
            T_, DI_, D_, D_, D_, DI_, 1, 0,0,0,0,0,0, 0.f);
        gemm_tc<128,128,32,64,32,true,EPI_SILU_SPLIT,false><<<gm,256,SM_M>>>(
            hnh, hnl, wuh + (size_t)l*DI_*D_, wul + (size_t)l*DI_*D_,
            gate, gah, gal, nullptr,
            T_, DI_, D_, D_, D_, DI_, 1, 0,0,0,0,0,0, 0.f);

        gemm_tc<128,64,32,32,32,true,EPI_RES,false><<<gp,256,SM_P>>>(
            gah, gal, wdh + (size_t)l*D_*DI_, wdl + (size_t)l*D_*DI_,
            h, nullptr, nullptr, nullptr,
            T_, D_, DI_, DI_, DI_, D_, 1, 0,0,0,0,0,0, 0.f);
    }

    rmsnorm_kernel<<<T_, 256>>>(h, norm_w, hnh, hnl);

    const dim3 gl(V_/128, T_/128, 1);
    gemm_tc<128,128,32,64,32,true,EPI_NONE,false><<<gl,256,SM_M>>>(
        hnh, hnl, embh, embl, out, nullptr, nullptr, nullptr,
        T_, V_, D_, D_, D_, V_, 1, 0,0,0,0,0,0, 0.f);
}

// round 9
// speedup vs baseline: 1.2281x; 1.1306x over previous
#include <cuda_runtime.h>
#include <cuda_bf16.h>
#include <cstdint>
#include <math.h>

#define L_  8
#define D_  1024
#define H_  16
#define DH_ 64
#define DI_ 4096
#define V_  32000
#define B_  2
#define S_  1024
#define T_  (B_*S_)

typedef __nv_bfloat16 bf16;

// ---------------- fp32 scratch ----------------
__device__ float g_h   [T_*D_];
__device__ float g_q   [T_*D_];
__device__ float g_k   [T_*D_];
__device__ float g_gate[T_*DI_];
__device__ float g_att [(size_t)B_*H_*S_*S_];
__device__ float g_cos [S_*32];
__device__ float g_sin [S_*32];

// ---------------- split bf16 scratch (hi/lo) ----------------
__device__ bf16 s_wq_h[L_*D_*D_],   s_wq_l[L_*D_*D_];
__device__ bf16 s_wk_h[L_*D_*D_],   s_wk_l[L_*D_*D_];
__device__ bf16 s_wv_h[L_*D_*D_],   s_wv_l[L_*D_*D_];
__device__ bf16 s_wo_h[L_*D_*D_],   s_wo_l[L_*D_*D_];
__device__ bf16 s_wg_h[L_*DI_*D_],  s_wg_l[L_*DI_*D_];
__device__ bf16 s_wu_h[L_*DI_*D_],  s_wu_l[L_*DI_*D_];
__device__ bf16 s_wd_h[L_*D_*DI_],  s_wd_l[L_*D_*DI_];
__device__ bf16 s_emb_h[V_*D_],     s_emb_l[V_*D_];
__device__ bf16 s_hn_h[T_*D_],      s_hn_l[T_*D_];
__device__ bf16 s_q_h [T_*D_],      s_q_l [T_*D_];
__device__ bf16 s_k_h [T_*D_],      s_k_l [T_*D_];
__device__ bf16 s_v_h [T_*D_],      s_v_l [T_*D_];
__device__ bf16 s_y_h [T_*D_],      s_y_l [T_*D_];
__device__ bf16 s_ga_h[T_*DI_],     s_ga_l[T_*DI_];
__device__ bf16 s_att_h[(size_t)B_*H_*S_*S_], s_att_l[(size_t)B_*H_*S_*S_];

// ---------------- helpers ----------------
__device__ __forceinline__ void split1(float v, bf16& h, bf16& l) {
    h = __float2bfloat16(v);
    l = __float2bfloat16(v - __bfloat162float(h));
}

__device__ __forceinline__ void split_store2(bf16* H, bf16* Lo, size_t off, float v0, float v1) {
    bf16 h0, l0, h1, l1;
    split1(v0, h0, l0);
    split1(v1, h1, l1);
    __nv_bfloat162 th; th.x = h0; th.y = h1;
    __nv_bfloat162 tl; tl.x = l0; tl.y = l1;
    *(__nv_bfloat162*)(H  + off) = th;
    *(__nv_bfloat162*)(Lo + off) = tl;
}

__global__ void split_kernel(const float* __restrict__ x, bf16* __restrict__ h,
                             bf16* __restrict__ l, int n4) {
    int i = blockIdx.x * blockDim.x + threadIdx.x;
    if (i >= n4) return;
    float4 v = ((const float4*)x)[i];
    bf16 h0,l0,h1,l1,h2,l2,h3,l3;
    split1(v.x, h0, l0); split1(v.y, h1, l1);
    split1(v.z, h2, l2); split1(v.w, h3, l3);
    ushort4 th = make_ushort4(__bfloat16_as_ushort(h0), __bfloat16_as_ushort(h1),
                              __bfloat16_as_ushort(h2), __bfloat16_as_ushort(h3));
    ushort4 tl = make_ushort4(__bfloat16_as_ushort(l0), __bfloat16_as_ushort(l1),
                              __bfloat16_as_ushort(l2), __bfloat16_as_ushort(l3));
    ((ushort4*)h)[i] = th;
    ((ushort4*)l)[i] = tl;
}

// ---------------- small kernels ----------------
__global__ void embed_kernel(const int* __restrict__ x, const float* __restrict__ emb,
                             float* __restrict__ h) {
    int i = blockIdx.x * blockDim.x + threadIdx.x;
    int t = i / (D_/4);
    int c = i % (D_/4);
    float4 v = *(const float4*)(emb + (size_t)x[t]*D_ + c*4);
    *(float4*)(h + (size_t)t*D_ + c*4) = v;
}

__global__ void rope_cache_kernel() {
    int i = blockIdx.x * blockDim.x + threadIdx.x;
    if (i >= S_*32) return;
    int s = i / 32, j = i % 32;
    double inv = pow(10000.0, -(double)j / 32.0);
    double ph = (double)s * inv;
    g_cos[i] = (float)cos(ph);
    g_sin[i] = (float)sin(ph);
}

__global__ void rope_kernel(const float* __restrict__ q, const float* __restrict__ k) {
    int i = blockIdx.x * blockDim.x + threadIdx.x;
    int t = i >> 9;
    int r = i & 511;
    int h = r >> 5, d = r & 31;
    int s = t & (S_-1);
    float c  = g_cos[s*32 + d];
    float sn = g_sin[s*32 + d];
    size_t base = (size_t)t*D_ + h*DH_ + d;
    float a, b, r0, r1;
    a = q[base]; b = q[base+32];
    r0 = a*c - b*sn;  r1 = b*c + a*sn;
    split1(r0, s_q_h[base],    s_q_l[base]);
    split1(r1, s_q_h[base+32], s_q_l[base+32]);
    a = k[base]; b = k[base+32];
    r0 = a*c - b*sn;  r1 = b*c + a*sn;
    split1(r0, s_k_h[base],    s_k_l[base]);
    split1(r1, s_k_h[base+32], s_k_l[base+32]);
}

__global__ void rmsnorm_kernel(const float* __restrict__ x, const float* __restrict__ w,
                               bf16* __restrict__ oh, bf16* __restrict__ ol) {
    int t = blockIdx.x;
    int tid = threadIdx.x;
    const float* xp = x + (size_t)t*D_;
    float v[4];
    float s = 0.f;
    #pragma unroll
    for (int i = 0; i < 4; i++) { v[i] = xp[tid + i*256]; s += v[i]*v[i]; }
    #pragma unroll
    for (int off = 16; off; off >>= 1) s += __shfl_xor_sync(0xffffffffu, s, off);
    __shared__ float red[8];
    if ((tid & 31) == 0) red[tid >> 5] = s;
    __syncthreads();
    if (tid < 32) {
        float s2 = (tid < 8) ? red[tid] : 0.f;
        #pragma unroll
        for (int off = 4; off; off >>= 1) s2 += __shfl_xor_sync(0xffffffffu, s2, off);
        if (tid == 0) red[0] = s2;
    }
    __syncthreads();
    float r = rsqrtf(red[0] * (1.f/(float)D_) + 1e-6f);
    size_t base = (size_t)t*D_;
    #pragma unroll
    for (int i = 0; i < 4; i++) {
        int idx = tid + i*256;
        split1(w[idx] * v[i] * r, oh[base+idx], ol[base+idx]);
    }
}

__global__ void softmax_kernel(const float* __restrict__ att,
                               bf16* __restrict__ oh, bf16* __restrict__ ol) {
    int row = blockIdx.x & (S_-1);
    const float* p = att + (size_t)blockIdx.x * S_;
    int tid = threadIdx.x;
    float vals[4];
    float mx = -INFINITY;
    #pragma unroll
    for (int i = 0; i < 4; i++) {
        int j = tid + i*256;
        vals[i] = (j <= row) ? p[j] : -INFINITY;
        mx = fmaxf(mx, vals[i]);
    }
    #pragma unroll
    for (int off = 16; off; off >>= 1) mx = fmaxf(mx, __shfl_xor_sync(0xffffffffu, mx, off));
    __shared__ float redm[8];
    if ((tid & 31) == 0) redm[tid >> 5] = mx;
    __syncthreads();
    if (tid < 32) {
        float m2 = (tid < 8) ? redm[tid] : -INFINITY;
        #pragma unroll
        for (int off = 4; off; off >>= 1) m2 = fmaxf(m2, __shfl_xor_sync(0xffffffffu, m2, off));
        if (tid == 0) redm[0] = m2;
    }
    __syncthreads();
    float m = redm[0];
    float s = 0.f;
    #pragma unroll
    for (int i = 0; i < 4; i++) { vals[i] = expf(vals[i] - m); s += vals[i]; }
    #pragma unroll
    for (int off = 16; off; off >>= 1) s += __shfl_xor_sync(0xffffffffu, s, off);
    __shared__ float reds[8];
    if ((tid & 31) == 0) reds[tid >> 5] = s;
    __syncthreads();
    if (tid < 32) {
        float s2 = (tid < 8) ? reds[tid] : 0.f;
        #pragma unroll
        for (int off = 4; off; off >>= 1) s2 += __shfl_xor_sync(0xffffffffu, s2, off);
        if (tid == 0) reds[0] = s2;
    }
    __syncthreads();
    float inv = 1.f / reds[0];
    size_t base = (size_t)blockIdx.x * S_;
    #pragma unroll
    for (int i = 0; i < 4; i++) {
        int j = tid + i*256;
        split1(vals[i] * inv, oh[base+j], ol[base+j]);
    }
}

// ---------------- bf16x3 GEMM on pre-split operands ----------------
enum { EPI_NONE = 0, EPI_BIAS = 1, EPI_BIAS_RES = 2, EPI_RES = 3, EPI_SCORES = 4,
       EPI_BIAS_SPLIT = 5, EPI_SPLIT = 6, EPI_SILU_SPLIT = 7 };

__device__ __forceinline__ void mma_bf16(float* d, const uint32_t* a, const uint32_t* b) {
    asm volatile(
        "mma.sync.aligned.m16n8k16.row.col.f32.bf16.bf16.f32 "
        "{%0,%1,%2,%3}, {%4,%5,%6,%7}, {%8,%9}, {%0,%1,%2,%3};\n"
        : "+f"(d[0]), "+f"(d[1]), "+f"(d[2]), "+f"(d[3])
        : "r"(a[0]), "r"(a[1]), "r"(a[2]), "r"(a[3]),
          "r"(b[0]), "r"(b[1]));
}

#define CP_ASYNC16(dst, src) \
    asm volatile("cp.async.cg.shared.global [%0], [%1], 16;" :: "r"(dst), "l"(src))
#define CP_COMMIT() asm volatile("cp.async.commit_group;" ::: "memory")
#define CP_WAIT0()  asm volatile("cp.async.wait_group 0;"  ::: "memory")

// A: bf16 [M,K] row-major (hi+lo).  BT=true: B bf16 [N,K]; BT=false: B bf16 [K,N].
template<int BM, int BN, int BK, int WM, int WN, bool BT, int EPI, bool TRIMK, int MINB>
__global__ __launch_bounds__((BM/WM)*(BN/WN)*32, MINB)
void gemm_tc(const bf16* __restrict__ Agh, const bf16* __restrict__ Agl,
             const bf16* __restrict__ Bgh, const bf16* __restrict__ Bgl,
             float* __restrict__ C, bf16* __restrict__ Oh, bf16* __restrict__ Ol,
             const float* __restrict__ bias,
             int M, int N, int K, int lda, int ldb, int ldc,
             int zinner,
             long long sAo, long long sAi,
             long long sBo, long long sBi,
             long long sCo, long long sCi,
             float scale)
{
    constexpr int WARPS_N = BN/WN;
    constexpr int THREADS = (BM/WM)*(BN/WN)*32;
    constexpr int MT = WM/16;
    constexpr int NT = WN/8;
    constexpr int SP = BK/2 + 4;
    constexpr int SZA = BM*SP;
    constexpr int SZB = BN*SP;
    constexpr int STAGE = 2*SZA + 2*SZB;
    constexpr int NCA = (BM*BK/8)/THREADS;   // 16B chunks per thread (A, per array)
    constexpr int NCB = (BN*BK/8)/THREADS;   // (BT layout)
    constexpr int NB_T = (BK*BN/8)/THREADS;  // (!BT layout)

    extern __shared__ uint32_t smem_u[];

    const int tid = threadIdx.x;
    const int z  = blockIdx.z;
    const int zo = z / zinner, zi = z % zinner;
    const bf16* Abh = Agh + zo*sAo + zi*sAi;
    const bf16* Abl = Agl + zo*sAo + zi*sAi;
    const bf16* Bbh = Bgh + zo*sBo + zi*sBi;
    const bf16* Bbl = Bgl + zo*sBo + zi*sBi;
    float* Cb  = C  ? (C  + zo*sCo + zi*sCi) : nullptr;
    bf16*  Ohb = Oh ? (Oh + zo*sCo + zi*sCi) : nullptr;
    bf16*  Olb = Ol ? (Ol + zo*sCo + zi*sCi) : nullptr;
    const int m0 = blockIdx.y * BM;
    const int n0 = blockIdx.x * BN;

    if (EPI == EPI_SCORES && n0 >= m0 + BM) return;

    const int warp = tid >> 5;
    const int lane = tid & 31;
    const int g = lane >> 2;
    const int c = lane & 3;
    const int wn = warp % WARPS_N;
    const int wm = warp / WARPS_N;

    float acc[MT][NT][4];
    #pragma unroll
    for (int i = 0; i < MT; i++)
        #pragma unroll
        for (int j = 0; j < NT; j++)
            #pragma unroll
            for (int r = 0; r < 4; r++) acc[i][j][r] = 0.f;

    const int Kend = TRIMK ? min(K, m0 + BM) : K;
    const int nk = Kend / BK;

    auto compute_stage = [&](int cur) {
        const uint32_t* Ah = smem_u + cur*STAGE;
        const uint32_t* Al = Ah + SZA;
        const uint32_t* Bh = Al + SZA;
        const uint32_t* Bl = Bh + SZB;
        #pragma unroll
        for (int ks = 0; ks < BK; ks += 16) {
            const int kp = ks >> 1;
            uint32_t ah[MT][4], al[MT][4], bh[NT][2], bl[NT][2];
            #pragma unroll
            for (int i = 0; i < MT; i++) {
                int mr = wm*WM + i*16 + g;
                ah[i][0] = Ah[mr*SP     + kp + c];   al[i][0] = Al[mr*SP     + kp + c];
                ah[i][1] = Ah[(mr+8)*SP + kp + c];   al[i][1] = Al[(mr+8)*SP + kp + c];
                ah[i][2] = Ah[mr*SP     + kp + c+4]; al[i][2] = Al[mr*SP     + kp + c+4];
                ah[i][3] = Ah[(mr+8)*SP + kp + c+4]; al[i][3] = Al[(mr+8)*SP + kp + c+4];
            }
            #pragma unroll
            for (int j = 0; j < NT; j++) {
                int nr = wn*WN + j*8 + g;
                bh[j][0] = Bh[nr*SP + kp + c];   bl[j][0] = Bl[nr*SP + kp + c];
                bh[j][1] = Bh[nr*SP + kp + c+4]; bl[j][1] = Bl[nr*SP + kp + c+4];
            }
            #pragma unroll
            for (int i = 0; i < MT; i++)
                #pragma unroll
                for (int j = 0; j < NT; j++)
                    mma_bf16(acc[i][j], ah[i], bh[j]);
            #pragma unroll
            for (int i = 0; i < MT; i++)
                #pragma unroll
                for (int j = 0; j < NT; j++)
                    mma_bf16(acc[i][j], ah[i], bl[j]);
            #pragma unroll
            for (int i = 0; i < MT; i++)
                #pragma unroll
                for (int j = 0; j < NT; j++)
                    mma_bf16(acc[i][j], al[i], bh[j]);
        }
    };

    if (BT) {
        // ---- cp.async pipeline (NT-layout GEMMs) ----
        const uint32_t smb = (uint32_t)__cvta_generic_to_shared(smem_u);
        auto cp_tile = [&](int kt, int s) {
            const uint32_t Ah = smb + s*STAGE*4;
            const uint32_t Al = Ah + SZA*4;
            const uint32_t Bh = Al + SZA*4;
            const uint32_t Bl = Bh + SZB*4;
            #pragma unroll
            for (int i = 0; i < NCA; i++) {
                int f  = tid + i*THREADS;
                int r  = f / (BK/8);
                int c8 = f % (BK/8);
                size_t   go = (size_t)(m0+r)*lda + kt + c8*8;
                uint32_t so = (uint32_t)(r*SP + c8*4)*4;
                CP_ASYNC16(Ah + so, Abh + go);
                CP_ASYNC16(Al + so, Abl + go);
            }
            #pragma unroll
            for (int i = 0; i < NCB; i++) {
                int f  = tid + i*THREADS;
                int r  = f / (BK/8);
                int c8 = f % (BK/8);
                size_t   go = (size_t)(n0+r)*ldb + kt + c8*8;
                uint32_t so = (uint32_t)(r*SP + c8*4)*4;
                CP_ASYNC16(Bh + so, Bbh + go);
                CP_ASYNC16(Bl + so, Bbl + go);
            }
            CP_COMMIT();
        };

        cp_tile(0, 0);
        CP_WAIT0();
        __syncthreads();

        for (int t = 0; t < nk; t++) {
            const int cur = t & 1;
            if (t + 1 < nk) cp_tile((t+1)*BK, cur ^ 1);
            compute_stage(cur);
            if (t + 1 < nk) CP_WAIT0();
            __syncthreads();
        }
    } else {
        // ---- register-staged path (transpose layout; attV only) ----
        uint4 pah[NCA], pal[NCA], pbh[NB_T], pbl[NB_T];

        auto load_gmem = [&](int kt) {
            #pragma unroll
            for (int i = 0; i < NCA; i++) {
                int f  = tid + i*THREADS;
                int r  = f / (BK/8);
                int c8 = f % (BK/8);
                size_t off = (size_t)(m0+r)*lda + kt + c8*8;
                pah[i] = *(const uint4*)(Abh + off);
                pal[i] = *(const uint4*)(Abl + off);
            }
            #pragma unroll
            for (int i = 0; i < NB_T; i++) {
                int f  = tid + i*THREADS;
                int r  = f / (BN/8);
                int c8 = f % (BN/8);
                size_t off = (size_t)(kt+r)*ldb + n0 + c8*8;
                pbh[i] = *(const uint4*)(Bbh + off);
                pbl[i] = *(const uint4*)(Bbl + off);
            }
        };

        auto store_smem = [&](int s) {
            uint32_t* Ah = smem_u + s*STAGE;
            uint32_t* Al = Ah + SZA;
            uint32_t* Bh = Al + SZA;
            uint32_t* Bl = Bh + SZB;
            #pragma unroll
            for (int i = 0; i < NCA; i++) {
                int f  = tid + i*THREADS;
                int r  = f / (BK/8);
                int c8 = f % (BK/8);
                *(uint4*)&Ah[r*SP + c8*4] = pah[i];
                *(uint4*)&Al[r*SP + c8*4] = pal[i];
            }
            #pragma unroll
            for (int i = 0; i < NB_T; i++) {
                int f  = tid + i*THREADS;
                int r  = f / (BN/8);
                int c8 = f % (BN/8);
                const uint16_t* uh = (const uint16_t*)&pbh[i];
                const uint16_t* ul = (const uint16_t*)&pbl[i];
                #pragma unroll
                for (int q = 0; q < 8; q++) {
                    ((uint16_t*)(Bh + (c8*8+q)*SP))[r] = uh[q];
                    ((uint16_t*)(Bl + (c8*8+q)*SP))[r] = ul[q];
                }
            }
        };

        load_gmem(0);
        store_smem(0);
        __syncthreads();

        for (int t = 0; t < nk; t++) {
            const int cur = t & 1;
            if (t + 1 < nk) load_gmem((t+1)*BK);
            compute_stage(cur);
            if (t + 1 < nk) store_smem(cur ^ 1);
            __syncthreads();
        }
    }

    #pragma unroll
    for (int i = 0; i < MT; i++) {
        #pragma unroll
        for (int j = 0; j < NT; j++) {
            int n = n0 + wn*WN + j*8 + 2*c;
            #pragma unroll
            for (int rr = 0; rr < 2; rr++) {
                int m = m0 + wm*WM + i*16 + g + rr*8;
                float v0 = acc[i][j][rr*2 + 0];
                float v1 = acc[i][j][rr*2 + 1];
                size_t off = (size_t)m*ldc + n;
                if (EPI == EPI_BIAS) {
                    v0 += bias[n]; v1 += bias[n+1];
                    *(float2*)(Cb + off) = make_float2(v0, v1);
                } else if (EPI == EPI_BIAS_RES) {
                    v0 += bias[n]   + Cb[off];
                    v1 += bias[n+1] + Cb[off+1];
                    *(float2*)(Cb + off) = make_float2(v0, v1);
                } else if (EPI == EPI_RES) {
                    v0 += Cb[off]; v1 += Cb[off+1];
                    *(float2*)(Cb + off) = make_float2(v0, v1);
                } else if (EPI == EPI_SCORES) {
                    *(float2*)(Cb + off) = make_float2(v0*scale, v1*scale);
                } else if (EPI == EPI_NONE) {
                    *(float2*)(Cb + off) = make_float2(v0, v1);
                } else if (EPI == EPI_BIAS_SPLIT) {
                    split_store2(Ohb, Olb, off, v0 + bias[n], v1 + bias[n+1]);
                } else if (EPI == EPI_SPLIT) {
                    split_store2(Ohb, Olb, off, v0, v1);
                } else if (EPI == EPI_SILU_SPLIT) {
                    float g0 = Cb[off], g1 = Cb[off+1];
                    v0 *= g0 / (1.f + expf(-g0));
                    v1 *= g1 / (1.f + expf(-g1));
                    split_store2(Ohb, Olb, off, v0, v1);
                }
            }
        }
    }
}

// ---------------- host ----------------
template<int BM, int BN, int BK>
constexpr int smem_bytes() {
    return 2 * (2*BM*(BK/2+4) + 2*BN*(BK/2+4)) * 4;
}

extern "C" void kernel_launch(void* const* d_in, const int* in_sizes, int n_in,
                              void* d_out, int out_size) {
    const int*   x      = (const int*)  d_in[0];
    const float* emb    = (const float*)d_in[1];
    const float* wq     = (const float*)d_in[2];
    const float* bq     = (const float*)d_in[3];
    const float* wk     = (const float*)d_in[4];
    const float* bk     = (const float*)d_in[5];
    const float* wv     = (const float*)d_in[6];
    const float* bv     = (const float*)d_in[7];
    const float* wo     = (const float*)d_in[8];
    const float* bo     = (const float*)d_in[9];
    const float* w_gate = (const float*)d_in[10];
    const float* w_up   = (const float*)d_in[11];
    const float* w_down = (const float*)d_in[12];
    const float* ln1    = (const float*)d_in[13];
    const float* ln2    = (const float*)d_in[14];
    const float* norm_w = (const float*)d_in[15];
    float* out = (float*)d_out;

    float *h, *q, *k, *gate, *att;
    cudaGetSymbolAddress((void**)&h,    g_h);
    cudaGetSymbolAddress((void**)&q,    g_q);
    cudaGetSymbolAddress((void**)&k,    g_k);
    cudaGetSymbolAddress((void**)&gate, g_gate);
    cudaGetSymbolAddress((void**)&att,  g_att);

    bf16 *wqh,*wql,*wkh,*wkl,*wvh,*wvl,*woh,*wol,*wgh,*wgl,*wuh,*wul,*wdh,*wdl,*embh,*embl;
    bf16 *hnh,*hnl,*qh,*ql,*kh,*kl,*vh,*vl,*yh,*yl,*gah,*gal,*atth,*attl;
    cudaGetSymbolAddress((void**)&wqh, s_wq_h);  cudaGetSymbolAddress((void**)&wql, s_wq_l);
    cudaGetSymbolAddress((void**)&wkh, s_wk_h);  cudaGetSymbolAddress((void**)&wkl, s_wk_l);
    cudaGetSymbolAddress((void**)&wvh, s_wv_h);  cudaGetSymbolAddress((void**)&wvl, s_wv_l);
    cudaGetSymbolAddress((void**)&woh, s_wo_h);  cudaGetSymbolAddress((void**)&wol, s_wo_l);
    cudaGetSymbolAddress((void**)&wgh, s_wg_h);  cudaGetSymbolAddress((void**)&wgl, s_wg_l);
    cudaGetSymbolAddress((void**)&wuh, s_wu_h);  cudaGetSymbolAddress((void**)&wul, s_wu_l);
    cudaGetSymbolAddress((void**)&wdh, s_wd_h);  cudaGetSymbolAddress((void**)&wdl, s_wd_l);
    cudaGetSymbolAddress((void**)&embh, s_emb_h); cudaGetSymbolAddress((void**)&embl, s_emb_l);
    cudaGetSymbolAddress((void**)&hnh, s_hn_h);  cudaGetSymbolAddress((void**)&hnl, s_hn_l);
    cudaGetSymbolAddress((void**)&qh,  s_q_h);   cudaGetSymbolAddress((void**)&ql,  s_q_l);
    cudaGetSymbolAddress((void**)&kh,  s_k_h);   cudaGetSymbolAddress((void**)&kl,  s_k_l);
    cudaGetSymbolAddress((void**)&vh,  s_v_h);   cudaGetSymbolAddress((void**)&vl,  s_v_l);
    cudaGetSymbolAddress((void**)&yh,  s_y_h);   cudaGetSymbolAddress((void**)&yl,  s_y_l);
    cudaGetSymbolAddress((void**)&gah, s_ga_h);  cudaGetSymbolAddress((void**)&gal, s_ga_l);
    cudaGetSymbolAddress((void**)&atth, s_att_h); cudaGetSymbolAddress((void**)&attl, s_att_l);

    constexpr int SM_S = smem_bytes<128,128,32>();   // 81920
    constexpr int SM_P = smem_bytes<128,64,32>();    // 61440

    cudaFuncSetAttribute(gemm_tc<128,64,32,32,32,true,EPI_BIAS,false,3>,       cudaFuncAttributeMaxDynamicSharedMemorySize, SM_P);
    cudaFuncSetAttribute(gemm_tc<128,64,32,32,32,true,EPI_BIAS_SPLIT,false,3>, cudaFuncAttributeMaxDynamicSharedMemorySize, SM_P);
    cudaFuncSetAttribute(gemm_tc<128,128,32,64,32,true,EPI_SCORES,false,2>,    cudaFuncAttributeMaxDynamicSharedMemorySize, SM_S);
    cudaFuncSetAttribute(gemm_tc<128,64,32,32,32,false,EPI_SPLIT,true,1>,      cudaFuncAttributeMaxDynamicSharedMemorySize, SM_P);
    cudaFuncSetAttribute(gemm_tc<128,64,32,32,32,true,EPI_BIAS_RES,false,3>,   cudaFuncAttributeMaxDynamicSharedMemorySize, SM_P);
    cudaFuncSetAttribute(gemm_tc<128,128,32,64,32,true,EPI_NONE,false,2>,      cudaFuncAttributeMaxDynamicSharedMemorySize, SM_S);
    cudaFuncSetAttribute(gemm_tc<128,128,32,64,32,true,EPI_SILU_SPLIT,false,2>,cudaFuncAttributeMaxDynamicSharedMemorySize, SM_S);
    cudaFuncSetAttribute(gemm_tc<128,64,32,32,32,true,EPI_RES,false,3>,        cudaFuncAttributeMaxDynamicSharedMemorySize, SM_P);

    // ---- prep: split weights + embedding ----
    auto split_launch = [](const float* src, bf16* dh, bf16* dl, size_t n) {
        int n4 = (int)(n / 4);
        split_kernel<<<(n4 + 255)/256, 256>>>(src, dh, dl, n4);
    };
    split_launch(wq, wqh, wql, (size_t)L_*D_*D_);
    split_launch(wk, wkh, wkl, (size_t)L_*D_*D_);
    split_launch(wv, wvh, wvl, (size_t)L_*D_*D_);
    split_launch(wo, woh, wol, (size_t)L_*D_*D_);
    split_launch(w_gate, wgh, wgl, (size_t)L_*DI_*D_);
    split_launch(w_up,   wuh, wul, (size_t)L_*DI_*D_);
    split_launch(w_down, wdh, wdl, (size_t)L_*D_*DI_);
    split_launch(emb, embh, embl, (size_t)V_*D_);

    embed_kernel<<<T_*D_/4/256, 256>>>(x, emb, h);
    rope_cache_kernel<<<(S_*32 + 255)/256, 256>>>();

    const dim3 gp(D_/64,   T_/128, 1);
    const dim3 gm(DI_/128, T_/128, 1);
    const dim3 gs(S_/128, S_/128, B_*H_);
    const dim3 ga(1,      S_/128, B_*H_);

    for (int l = 0; l < L_; l++) {
        rmsnorm_kernel<<<T_, 256>>>(h, ln1 + (size_t)l*D_, hnh, hnl);

        gemm_tc<128,64,32,32,32,true,EPI_BIAS,false,3><<<gp,256,SM_P>>>(
            hnh, hnl, wqh + (size_t)l*D_*D_, wql + (size_t)l*D_*D_,
            q, nullptr, nullptr, bq + (size_t)l*D_,
            T_, D_, D_, D_, D_, D_, 1, 0,0,0,0,0,0, 0.f);
        gemm_tc<128,64,32,32,32,true,EPI_BIAS,false,3><<<gp,256,SM_P>>>(
            hnh, hnl, wkh + (size_t)l*D_*D_, wkl + (size_t)l*D_*D_,
            k, nullptr, nullptr, bk + (size_t)l*D_,
            T_, D_, D_, D_, D_, D_, 1, 0,0,0,0,0,0, 0.f);
        gemm_tc<128,64,32,32,32,true,EPI_BIAS_SPLIT,false,3><<<gp,256,SM_P>>>(
            hnh, hnl, wvh + (size_t)l*D_*D_, wvl + (size_t)l*D_*D_,
            nullptr, vh, vl, bv + (size_t)l*D_,
            T_, D_, D_, D_, D_, D_, 1, 0,0,0,0,0,0, 0.f);

        rope_kernel<<<T_*H_*32/256, 256>>>(q, k);

        gemm_tc<128,128,32,64,32,true,EPI_SCORES,false,2><<<gs,256,SM_S>>>(
            qh, ql, kh, kl, att, nullptr, nullptr, nullptr,
            S_, S_, DH_, D_, D_, S_,
            H_,
            (long long)S_*D_, (long long)DH_,
            (long long)S_*D_, (long long)DH_,
            (long long)H_*S_*S_, (long long)S_*S_,
            0.125f);

        softmax_kernel<<<B_*H_*S_, 256>>>(att, atth, attl);

        gemm_tc<128,64,32,32,32,false,EPI_SPLIT,true,1><<<ga,256,SM_P>>>(
            atth, attl, vh, vl, nullptr, yh, yl, nullptr,
            S_, DH_, S_, S_, D_, D_,
            H_,
            (long long)H_*S_*S_, (long long)S_*S_,
            (long long)S_*D_, (long long)DH_,
            (long long)S_*D_, (long long)DH_,
            0.f);

        gemm_tc<128,64,32,32,32,true,EPI_BIAS_RES,false,3><<<gp,256,SM_P>>>(
            yh, yl, woh + (size_t)l*D_*D_, wol + (size_t)l*D_*D_,
            h, nullptr, nullptr, bo + (size_t)l*D_,
            T_, D_, D_, D_, D_, D_, 1, 0,0,0,0,0,0, 0.f);

        rmsnorm_kernel<<<T_, 256>>>(h, ln2 + (size_t)l*D_, hnh, hnl);

        gemm_tc<128,128,32,64,32,true,EPI_NONE,false,2><<<gm,256,SM_S>>>(
            hnh, hnl, wgh + (size_t)l*DI_*D_, wgl + (size_t)l*DI_*D_,
            gate, nullptr, nullptr, nullptr,
            T_, DI_, D_, D_, D_, DI_, 1, 0,0,0,0,0,0, 0.f);
        gemm_tc<128,128,32,64,32,true,EPI_SILU_SPLIT,false,2><<<gm,256,SM_S>>>(
            hnh, hnl, wuh + (size_t)l*DI_*D_, wul + (size_t)l*DI_*D_,
            gate, gah, gal, nullptr,
            T_, DI_, D_, D_, D_, DI_, 1, 0,0,0,0,0,0, 0.f);

        gemm_tc<128,64,32,32,32,true,EPI_RES,false,3><<<gp,256,SM_P>>>(
            gah, gal, wdh + (size_t)l*D_*DI_, wdl + (size_t)l*D_*DI_,
            h, nullptr, nullptr, nullptr,
            T_, D_, DI_, DI_, DI_, D_, 1, 0,0,0,0,0,0, 0.f);
    }

    rmsnorm_kernel<<<T_, 256>>>(h, norm_w, hnh, hnl);

    const dim3 gl(V_/128, T_/128, 1);
    gemm_tc<128,128,32,64,32,true,EPI_NONE,false,2><<<gl,256,SM_S>>>(
        hnh, hnl, embh, embl, out, nullptr, nullptr, nullptr,
        T_, V_, D_, D_, D_, V_, 1, 0,0,0,0,0,0, 0.f);
}

// round 10
// speedup vs baseline: 1.2693x; 1.0336x over previous
#include <cuda_runtime.h>
#include <cuda_bf16.h>
#include <cstdint>
#include <math.h>

#define L_  8
#define D_  1024
#define H_  16
#define DH_ 64
#define DI_ 4096
#define V_  32000
#define B_  2
#define S_  1024
#define T_  (B_*S_)

typedef __nv_bfloat16 bf16;

// ---------------- fp32 scratch ----------------
__device__ float g_h   [T_*D_];
__device__ float g_qk  [T_*2048];
__device__ float g_gate[T_*DI_];
__device__ float g_att [(size_t)B_*H_*S_*S_];
__device__ float g_cos [S_*32];
__device__ float g_sin [S_*32];
__device__ float g_bqkv[L_*3*D_];

// ---------------- split bf16 scratch (hi/lo) ----------------
__device__ bf16 s_wqkv_h[L_*3*D_*D_], s_wqkv_l[L_*3*D_*D_];
__device__ bf16 s_wo_h[L_*D_*D_],   s_wo_l[L_*D_*D_];
__device__ bf16 s_wg_h[L_*DI_*D_],  s_wg_l[L_*DI_*D_];
__device__ bf16 s_wu_h[L_*DI_*D_],  s_wu_l[L_*DI_*D_];
__device__ bf16 s_wd_h[L_*D_*DI_],  s_wd_l[L_*D_*DI_];
__device__ bf16 s_emb_h[V_*D_],     s_emb_l[V_*D_];
__device__ bf16 s_hn_h[T_*D_],      s_hn_l[T_*D_];
__device__ bf16 s_q_h [T_*D_],      s_q_l [T_*D_];
__device__ bf16 s_k_h [T_*D_],      s_k_l [T_*D_];
__device__ bf16 s_vt_h[T_*D_],      s_vt_l[T_*D_];     // [b][h][d][s]
__device__ bf16 s_y_h [T_*D_],      s_y_l [T_*D_];
__device__ bf16 s_ga_h[T_*DI_],     s_ga_l[T_*DI_];
__device__ bf16 s_att_h[(size_t)B_*H_*S_*S_], s_att_l[(size_t)B_*H_*S_*S_];

// ---------------- helpers ----------------
__device__ __forceinline__ void split1(float v, bf16& h, bf16& l) {
    h = __float2bfloat16(v);
    l = __float2bfloat16(v - __bfloat162float(h));
}

__device__ __forceinline__ void split_store2(bf16* H, bf16* Lo, size_t off, float v0, float v1) {
    bf16 h0, l0, h1, l1;
    split1(v0, h0, l0);
    split1(v1, h1, l1);
    __nv_bfloat162 th; th.x = h0; th.y = h1;
    __nv_bfloat162 tl; tl.x = l0; tl.y = l1;
    *(__nv_bfloat162*)(H  + off) = th;
    *(__nv_bfloat162*)(Lo + off) = tl;
}

__global__ void split_kernel(const float* __restrict__ x, bf16* __restrict__ h,
                             bf16* __restrict__ l, int n4) {
    int i = blockIdx.x * blockDim.x + threadIdx.x;
    if (i >= n4) return;
    float4 v = ((const float4*)x)[i];
    bf16 h0,l0,h1,l1,h2,l2,h3,l3;
    split1(v.x, h0, l0); split1(v.y, h1, l1);
    split1(v.z, h2, l2); split1(v.w, h3, l3);
    ushort4 th = make_ushort4(__bfloat16_as_ushort(h0), __bfloat16_as_ushort(h1),
                              __bfloat16_as_ushort(h2), __bfloat16_as_ushort(h3));
    ushort4 tl = make_ushort4(__bfloat16_as_ushort(l0), __bfloat16_as_ushort(l1),
                              __bfloat16_as_ushort(l2), __bfloat16_as_ushort(l3));
    ((ushort4*)h)[i] = th;
    ((ushort4*)l)[i] = tl;
}

// split [L,D,D] source into packed [L,3D,D] dst at given row offset
__global__ void split_pack_kernel(const float* __restrict__ x, bf16* __restrict__ h,
                                  bf16* __restrict__ l, int row_off) {
    int i = blockIdx.x * blockDim.x + threadIdx.x;   // over L_*D_*D_/4
    if (i >= L_*D_*D_/4) return;
    int lay = i / (D_*D_/4);
    int rem = i % (D_*D_/4);
    int r   = rem / (D_/4);
    int c4  = rem % (D_/4);
    float4 v = ((const float4*)x)[i];
    int d4 = lay*(3*D_*D_/4) + (row_off + r)*(D_/4) + c4;
    bf16 h0,l0,h1,l1,h2,l2,h3,l3;
    split1(v.x, h0, l0); split1(v.y, h1, l1);
    split1(v.z, h2, l2); split1(v.w, h3, l3);
    ((ushort4*)h)[d4] = make_ushort4(__bfloat16_as_ushort(h0), __bfloat16_as_ushort(h1),
                                     __bfloat16_as_ushort(h2), __bfloat16_as_ushort(h3));
    ((ushort4*)l)[d4] = make_ushort4(__bfloat16_as_ushort(l0), __bfloat16_as_ushort(l1),
                                     __bfloat16_as_ushort(l2), __bfloat16_as_ushort(l3));
}

__global__ void pack_bias_kernel(const float* __restrict__ bq, const float* __restrict__ bk,
                                 const float* __restrict__ bv, float* __restrict__ dst) {
    int i = blockIdx.x * blockDim.x + threadIdx.x;   // L_*3072
    if (i >= L_*3*D_) return;
    int lay = i / (3*D_);
    int j   = i % (3*D_);
    float v = (j < D_) ? bq[lay*D_ + j]
            : (j < 2*D_) ? bk[lay*D_ + j - D_]
            : bv[lay*D_ + j - 2*D_];
    dst[i] = v;
}

// ---------------- small kernels ----------------
__global__ void embed_kernel(const int* __restrict__ x, const float* __restrict__ emb,
                             float* __restrict__ h) {
    int i = blockIdx.x * blockDim.x + threadIdx.x;
    int t = i / (D_/4);
    int c = i % (D_/4);
    float4 v = *(const float4*)(emb + (size_t)x[t]*D_ + c*4);
    *(float4*)(h + (size_t)t*D_ + c*4) = v;
}

__global__ void rope_cache_kernel() {
    int i = blockIdx.x * blockDim.x + threadIdx.x;
    if (i >= S_*32) return;
    int s = i / 32, j = i % 32;
    double inv = pow(10000.0, -(double)j / 32.0);
    double ph = (double)s * inv;
    g_cos[i] = (float)cos(ph);
    g_sin[i] = (float)sin(ph);
}

// rope: reads fused qk fp32 buffer [T,2048], writes split q/k [T,1024]
__global__ void rope_kernel() {
    int i = blockIdx.x * blockDim.x + threadIdx.x;   // T_*H_*32
    int t = i >> 9;
    int r = i & 511;
    int h = r >> 5, d = r & 31;
    int s = t & (S_-1);
    float c  = g_cos[s*32 + d];
    float sn = g_sin[s*32 + d];
    size_t qkb = (size_t)t*2048 + h*DH_ + d;
    size_t ob  = (size_t)t*D_   + h*DH_ + d;
    float a, b, r0, r1;
    a = g_qk[qkb]; b = g_qk[qkb+32];
    r0 = a*c - b*sn;  r1 = b*c + a*sn;
    split1(r0, s_q_h[ob],    s_q_l[ob]);
    split1(r1, s_q_h[ob+32], s_q_l[ob+32]);
    a = g_qk[qkb+1024]; b = g_qk[qkb+1024+32];
    r0 = a*c - b*sn;  r1 = b*c + a*sn;
    split1(r0, s_k_h[ob],    s_k_l[ob]);
    split1(r1, s_k_h[ob+32], s_k_l[ob+32]);
}

__global__ void rmsnorm_kernel(const float* __restrict__ x, const float* __restrict__ w,
                               bf16* __restrict__ oh, bf16* __restrict__ ol) {
    int t = blockIdx.x;
    int tid = threadIdx.x;
    const float* xp = x + (size_t)t*D_;
    float v[4];
    float s = 0.f;
    #pragma unroll
    for (int i = 0; i < 4; i++) { v[i] = xp[tid + i*256]; s += v[i]*v[i]; }
    #pragma unroll
    for (int off = 16; off; off >>= 1) s += __shfl_xor_sync(0xffffffffu, s, off);
    __shared__ float red[8];
    if ((tid & 31) == 0) red[tid >> 5] = s;
    __syncthreads();
    if (tid < 32) {
        float s2 = (tid < 8) ? red[tid] : 0.f;
        #pragma unroll
        for (int off = 4; off; off >>= 1) s2 += __shfl_xor_sync(0xffffffffu, s2, off);
        if (tid == 0) red[0] = s2;
    }
    __syncthreads();
    float r = rsqrtf(red[0] * (1.f/(float)D_) + 1e-6f);
    size_t base = (size_t)t*D_;
    #pragma unroll
    for (int i = 0; i < 4; i++) {
        int idx = tid + i*256;
        split1(w[idx] * v[i] * r, oh[base+idx], ol[base+idx]);
    }
}

__global__ void softmax_kernel(const float* __restrict__ att,
                               bf16* __restrict__ oh, bf16* __restrict__ ol) {
    int row = blockIdx.x & (S_-1);
    const float* p = att + (size_t)blockIdx.x * S_;
    int tid = threadIdx.x;
    float vals[4];
    float mx = -INFINITY;
    #pragma unroll
    for (int i = 0; i < 4; i++) {
        int j = tid + i*256;
        vals[i] = (j <= row) ? p[j] : -INFINITY;
        mx = fmaxf(mx, vals[i]);
    }
    #pragma unroll
    for (int off = 16; off; off >>= 1) mx = fmaxf(mx, __shfl_xor_sync(0xffffffffu, mx, off));
    __shared__ float redm[8];
    if ((tid & 31) == 0) redm[tid >> 5] = mx;
    __syncthreads();
    if (tid < 32) {
        float m2 = (tid < 8) ? redm[tid] : -INFINITY;
        #pragma unroll
        for (int off = 4; off; off >>= 1) m2 = fmaxf(m2, __shfl_xor_sync(0xffffffffu, m2, off));
        if (tid == 0) redm[0] = m2;
    }
    __syncthreads();
    float m = redm[0];
    float s = 0.f;
    #pragma unroll
    for (int i = 0; i < 4; i++) { vals[i] = expf(vals[i] - m); s += vals[i]; }
    #pragma unroll
    for (int off = 16; off; off >>= 1) s += __shfl_xor_sync(0xffffffffu, s, off);
    __shared__ float reds[8];
    if ((tid & 31) == 0) reds[tid >> 5] = s;
    __syncthreads();
    if (tid < 32) {
        float s2 = (tid < 8) ? reds[tid] : 0.f;
        #pragma unroll
        for (int off = 4; off; off >>= 1) s2 += __shfl_xor_sync(0xffffffffu, s2, off);
        if (tid == 0) reds[0] = s2;
    }
    __syncthreads();
    float inv = 1.f / reds[0];
    size_t base = (size_t)blockIdx.x * S_;
    #pragma unroll
    for (int i = 0; i < 4; i++) {
        int j = tid + i*256;
        split1(vals[i] * inv, oh[base+j], ol[base+j]);
    }
}

// ---------------- bf16x3 GEMM on pre-split operands ----------------
enum { EPI_NONE = 0, EPI_BIAS = 1, EPI_BIAS_RES = 2, EPI_RES = 3, EPI_SCORES = 4,
       EPI_BIAS_SPLIT = 5, EPI_SPLIT = 6, EPI_SILU_SPLIT = 7, EPI_QKV = 8 };

__device__ __forceinline__ void mma_bf16(float* d, const uint32_t* a, const uint32_t* b) {
    asm volatile(
        "mma.sync.aligned.m16n8k16.row.col.f32.bf16.bf16.f32 "
        "{%0,%1,%2,%3}, {%4,%5,%6,%7}, {%8,%9}, {%0,%1,%2,%3};\n"
        : "+f"(d[0]), "+f"(d[1]), "+f"(d[2]), "+f"(d[3])
        : "r"(a[0]), "r"(a[1]), "r"(a[2]), "r"(a[3]),
          "r"(b[0]), "r"(b[1]));
}

#define CP_ASYNC16(dst, src) \
    asm volatile("cp.async.cg.shared.global [%0], [%1], 16;" :: "r"(dst), "l"(src))
#define CP_COMMIT() asm volatile("cp.async.commit_group;" ::: "memory")
#define CP_WAIT0()  asm volatile("cp.async.wait_group 0;"  ::: "memory")

// A: bf16 [M,K] row-major (hi+lo).  B bf16 [N,K] row-major (NT). cp.async pipeline.
template<int BM, int BN, int BK, int WM, int WN, int EPI, bool TRIMK, int MINB>
__global__ __launch_bounds__((BM/WM)*(BN/WN)*32, MINB)
void gemm_tc(const bf16* __restrict__ Agh, const bf16* __restrict__ Agl,
             const bf16* __restrict__ Bgh, const bf16* __restrict__ Bgl,
             float* __restrict__ C, bf16* __restrict__ Oh, bf16* __restrict__ Ol,
             const float* __restrict__ bias,
             int M, int N, int K, int lda, int ldb, int ldc,
             int zinner,
             long long sAo, long long sAi,
             long long sBo, long long sBi,
             long long sCo, long long sCi,
             float scale)
{
    constexpr int WARPS_N = BN/WN;
    constexpr int THREADS = (BM/WM)*(BN/WN)*32;
    constexpr int MT = WM/16;
    constexpr int NT = WN/8;
    constexpr int SP = BK/2 + 4;
    constexpr int SZA = BM*SP;
    constexpr int SZB = BN*SP;
    constexpr int STAGE = 2*SZA + 2*SZB;
    constexpr int NCA = (BM*BK/8)/THREADS;
    constexpr int NCB = (BN*BK/8)/THREADS;

    extern __shared__ uint32_t smem_u[];

    const int tid = threadIdx.x;
    const int z  = blockIdx.z;
    const int zo = z / zinner, zi = z % zinner;
    const bf16* Abh = Agh + zo*sAo + zi*sAi;
    const bf16* Abl = Agl + zo*sAo + zi*sAi;
    const bf16* Bbh = Bgh + zo*sBo + zi*sBi;
    const bf16* Bbl = Bgl + zo*sBo + zi*sBi;
    float* Cb  = C  ? (C  + zo*sCo + zi*sCi) : nullptr;
    bf16*  Ohb = Oh ? (Oh + zo*sCo + zi*sCi) : nullptr;
    bf16*  Olb = Ol ? (Ol + zo*sCo + zi*sCi) : nullptr;
    const int m0 = blockIdx.y * BM;
    const int n0 = blockIdx.x * BN;

    if (EPI == EPI_SCORES && n0 >= m0 + BM) return;

    const int warp = tid >> 5;
    const int lane = tid & 31;
    const int g = lane >> 2;
    const int c = lane & 3;
    const int wn = warp % WARPS_N;
    const int wm = warp / WARPS_N;

    float acc[MT][NT][4];
    #pragma unroll
    for (int i = 0; i < MT; i++)
        #pragma unroll
        for (int j = 0; j < NT; j++)
            #pragma unroll
            for (int r = 0; r < 4; r++) acc[i][j][r] = 0.f;

    const int Kend = TRIMK ? min(K, m0 + BM) : K;
    const int nk = Kend / BK;

    const uint32_t smb = (uint32_t)__cvta_generic_to_shared(smem_u);
    auto cp_tile = [&](int kt, int s) {
        const uint32_t Ah = smb + s*STAGE*4;
        const uint32_t Al = Ah + SZA*4;
        const uint32_t Bh = Al + SZA*4;
        const uint32_t Bl = Bh + SZB*4;
        #pragma unroll
        for (int i = 0; i < NCA; i++) {
            int f  = tid + i*THREADS;
            int r  = f / (BK/8);
            int c8 = f % (BK/8);
            size_t   go = (size_t)(m0+r)*lda + kt + c8*8;
            uint32_t so = (uint32_t)(r*SP + c8*4)*4;
            CP_ASYNC16(Ah + so, Abh + go);
            CP_ASYNC16(Al + so, Abl + go);
        }
        #pragma unroll
        for (int i = 0; i < NCB; i++) {
            int f  = tid + i*THREADS;
            int r  = f / (BK/8);
            int c8 = f % (BK/8);
            size_t   go = (size_t)(n0+r)*ldb + kt + c8*8;
            uint32_t so = (uint32_t)(r*SP + c8*4)*4;
            CP_ASYNC16(Bh + so, Bbh + go);
            CP_ASYNC16(Bl + so, Bbl + go);
        }
        CP_COMMIT();
    };

    auto compute_stage = [&](int cur) {
        const uint32_t* Ah = smem_u + cur*STAGE;
        const uint32_t* Al = Ah + SZA;
        const uint32_t* Bh = Al + SZA;
        const uint32_t* Bl = Bh + SZB;
        #pragma unroll
        for (int ks = 0; ks < BK; ks += 16) {
            const int kp = ks >> 1;
            uint32_t ah[MT][4], al[MT][4], bh[NT][2], bl[NT][2];
            #pragma unroll
            for (int i = 0; i < MT; i++) {
                int mr = wm*WM + i*16 + g;
                ah[i][0] = Ah[mr*SP     + kp + c];   al[i][0] = Al[mr*SP     + kp + c];
                ah[i][1] = Ah[(mr+8)*SP + kp + c];   al[i][1] = Al[(mr+8)*SP + kp + c];
                ah[i][2] = Ah[mr*SP     + kp + c+4]; al[i][2] = Al[mr*SP     + kp + c+4];
                ah[i][3] = Ah[(mr+8)*SP + kp + c+4]; al[i][3] = Al[(mr+8)*SP + kp + c+4];
            }
            #pragma unroll
            for (int j = 0; j < NT; j++) {
                int nr = wn*WN + j*8 + g;
                bh[j][0] = Bh[nr*SP + kp + c];   bl[j][0] = Bl[nr*SP + kp + c];
                bh[j][1] = Bh[nr*SP + kp + c+4]; bl[j][1] = Bl[nr*SP + kp + c+4];
            }
            #pragma unroll
            for (int i = 0; i < MT; i++)
                #pragma unroll
                for (int j = 0; j < NT; j++)
                    mma_bf16(acc[i][j], ah[i], bh[j]);
            #pragma unroll
            for (int i = 0; i < MT; i++)
                #pragma unroll
                for (int j = 0; j < NT; j++)
                    mma_bf16(acc[i][j], ah[i], bl[j]);
            #pragma unroll
            for (int i = 0; i < MT; i++)
                #pragma unroll
                for (int j = 0; j < NT; j++)
                    mma_bf16(acc[i][j], al[i], bh[j]);
        }
    };

    cp_tile(0, 0);
    CP_WAIT0();
    __syncthreads();

    for (int t = 0; t < nk; t++) {
        const int cur = t & 1;
        if (t + 1 < nk) cp_tile((t+1)*BK, cur ^ 1);
        compute_stage(cur);
        if (t + 1 < nk) CP_WAIT0();
        __syncthreads();
    }

    #pragma unroll
    for (int i = 0; i < MT; i++) {
        #pragma unroll
        for (int j = 0; j < NT; j++) {
            int n = n0 + wn*WN + j*8 + 2*c;
            #pragma unroll
            for (int rr = 0; rr < 2; rr++) {
                int m = m0 + wm*WM + i*16 + g + rr*8;
                float v0 = acc[i][j][rr*2 + 0];
                float v1 = acc[i][j][rr*2 + 1];
                if (EPI == EPI_QKV) {
                    v0 += bias[n]; v1 += bias[n+1];
                    if (n < 2*D_) {
                        *(float2*)(Cb + (size_t)m*ldc + n) = make_float2(v0, v1);
                    } else {
                        // split-store V transposed: [b][h][d][s]
                        int dg = n - 2*D_;
                        int hh = dg >> 6, dd = dg & 63;
                        int b  = m >> 10, s = m & 1023;
                        size_t o0 = (((size_t)b*H_ + hh)*DH_ + dd)*S_ + s;
                        split1(v0, Oh[o0],      Ol[o0]);
                        split1(v1, Oh[o0+S_],   Ol[o0+S_]);
                    }
                    continue;
                }
                size_t off = (size_t)m*ldc + n;
                if (EPI == EPI_BIAS) {
                    v0 += bias[n]; v1 += bias[n+1];
                    *(float2*)(Cb + off) = make_float2(v0, v1);
                } else if (EPI == EPI_BIAS_RES) {
                    v0 += bias[n]   + Cb[off];
                    v1 += bias[n+1] + Cb[off+1];
                    *(float2*)(Cb + off) = make_float2(v0, v1);
                } else if (EPI == EPI_RES) {
                    v0 += Cb[off]; v1 += Cb[off+1];
                    *(float2*)(Cb + off) = make_float2(v0, v1);
                } else if (EPI == EPI_SCORES) {
                    *(float2*)(Cb + off) = make_float2(v0*scale, v1*scale);
                } else if (EPI == EPI_NONE) {
                    *(float2*)(Cb + off) = make_float2(v0, v1);
                } else if (EPI == EPI_BIAS_SPLIT) {
                    split_store2(Ohb, Olb, off, v0 + bias[n], v1 + bias[n+1]);
                } else if (EPI == EPI_SPLIT) {
                    split_store2(Ohb, Olb, off, v0, v1);
                } else if (EPI == EPI_SILU_SPLIT) {
                    float g0 = Cb[off], g1 = Cb[off+1];
                    v0 *= g0 / (1.f + expf(-g0));
                    v1 *= g1 / (1.f + expf(-g1));
                    split_store2(Ohb, Olb, off, v0, v1);
                }
            }
        }
    }
}

// ---------------- host ----------------
template<int BM, int BN, int BK>
constexpr int smem_bytes() {
    return 2 * (2*BM*(BK/2+4) + 2*BN*(BK/2+4)) * 4;
}

extern "C" void kernel_launch(void* const* d_in, const int* in_sizes, int n_in,
                              void* d_out, int out_size) {
    const int*   x      = (const int*)  d_in[0];
    const float* emb    = (const float*)d_in[1];
    const float* wq     = (const float*)d_in[2];
    const float* bq     = (const float*)d_in[3];
    const float* wk     = (const float*)d_in[4];
    const float* bk     = (const float*)d_in[5];
    const float* wv     = (const float*)d_in[6];
    const float* bv     = (const float*)d_in[7];
    const float* wo     = (const float*)d_in[8];
    const float* bo     = (const float*)d_in[9];
    const float* w_gate = (const float*)d_in[10];
    const float* w_up   = (const float*)d_in[11];
    const float* w_down = (const float*)d_in[12];
    const float* ln1    = (const float*)d_in[13];
    const float* ln2    = (const float*)d_in[14];
    const float* norm_w = (const float*)d_in[15];
    float* out = (float*)d_out;

    float *h, *qk, *gate, *att, *bqkv;
    cudaGetSymbolAddress((void**)&h,    g_h);
    cudaGetSymbolAddress((void**)&qk,   g_qk);
    cudaGetSymbolAddress((void**)&gate, g_gate);
    cudaGetSymbolAddress((void**)&att,  g_att);
    cudaGetSymbolAddress((void**)&bqkv, g_bqkv);

    bf16 *wqkvh,*wqkvl,*woh,*wol,*wgh,*wgl,*wuh,*wul,*wdh,*wdl,*embh,*embl;
    bf16 *hnh,*hnl,*qh,*ql,*kh,*kl,*vth,*vtl,*yh,*yl,*gah,*gal,*atth,*attl;
    cudaGetSymbolAddress((void**)&wqkvh, s_wqkv_h); cudaGetSymbolAddress((void**)&wqkvl, s_wqkv_l);
    cudaGetSymbolAddress((void**)&woh, s_wo_h);  cudaGetSymbolAddress((void**)&wol, s_wo_l);
    cudaGetSymbolAddress((void**)&wgh, s_wg_h);  cudaGetSymbolAddress((void**)&wgl, s_wg_l);
    cudaGetSymbolAddress((void**)&wuh, s_wu_h);  cudaGetSymbolAddress((void**)&wul, s_wu_l);
    cudaGetSymbolAddress((void**)&wdh, s_wd_h);  cudaGetSymbolAddress((void**)&wdl, s_wd_l);
    cudaGetSymbolAddress((void**)&embh, s_emb_h); cudaGetSymbolAddress((void**)&embl, s_emb_l);
    cudaGetSymbolAddress((void**)&hnh, s_hn_h);  cudaGetSymbolAddress((void**)&hnl, s_hn_l);
    cudaGetSymbolAddress((void**)&qh,  s_q_h);   cudaGetSymbolAddress((void**)&ql,  s_q_l);
    cudaGetSymbolAddress((void**)&kh,  s_k_h);   cudaGetSymbolAddress((void**)&kl,  s_k_l);
    cudaGetSymbolAddress((void**)&vth, s_vt_h);  cudaGetSymbolAddress((void**)&vtl, s_vt_l);
    cudaGetSymbolAddress((void**)&yh,  s_y_h);   cudaGetSymbolAddress((void**)&yl,  s_y_l);
    cudaGetSymbolAddress((void**)&gah, s_ga_h);  cudaGetSymbolAddress((void**)&gal, s_ga_l);
    cudaGetSymbolAddress((void**)&atth, s_att_h); cudaGetSymbolAddress((void**)&attl, s_att_l);

    constexpr int SM_S = smem_bytes<128,128,32>();   // 81920
    constexpr int SM_P = smem_bytes<128,64,32>();    // 61440

    cudaFuncSetAttribute(gemm_tc<128,64,32,32,32,EPI_QKV,false,3>,      cudaFuncAttributeMaxDynamicSharedMemorySize, SM_P);
    cudaFuncSetAttribute(gemm_tc<128,128,32,64,32,EPI_SCORES,false,2>,  cudaFuncAttributeMaxDynamicSharedMemorySize, SM_S);
    cudaFuncSetAttribute(gemm_tc<128,64,32,32,32,EPI_SPLIT,true,2>,     cudaFuncAttributeMaxDynamicSharedMemorySize, SM_P);
    cudaFuncSetAttribute(gemm_tc<128,64,32,32,32,EPI_BIAS_RES,false,3>, cudaFuncAttributeMaxDynamicSharedMemorySize, SM_P);
    cudaFuncSetAttribute(gemm_tc<128,128,32,64,32,EPI_NONE,false,2>,    cudaFuncAttributeMaxDynamicSharedMemorySize, SM_S);
    cudaFuncSetAttribute(gemm_tc<128,128,32,64,32,EPI_SILU_SPLIT,false,2>, cudaFuncAttributeMaxDynamicSharedMemorySize, SM_S);
    cudaFuncSetAttribute(gemm_tc<128,64,32,32,32,EPI_RES,false,3>,      cudaFuncAttributeMaxDynamicSharedMemorySize, SM_P);

    // ---- prep: split weights + embedding; pack QKV ----
    auto split_launch = [](const float* src, bf16* dh, bf16* dl, size_t n) {
        int n4 = (int)(n / 4);
        split_kernel<<<(n4 + 255)/256, 256>>>(src, dh, dl, n4);
    };
    int nw4 = L_*D_*D_/4;
    split_pack_kernel<<<(nw4+255)/256, 256>>>(wq, wqkvh, wqkvl, 0);
    split_pack_kernel<<<(nw4+255)/256, 256>>>(wk, wqkvh, wqkvl, D_);
    split_pack_kernel<<<(nw4+255)/256, 256>>>(wv, wqkvh, wqkvl, 2*D_);
    pack_bias_kernel<<<(L_*3*D_+255)/256, 256>>>(bq, bk, bv, bqkv);
    split_launch(wo, woh, wol, (size_t)L_*D_*D_);
    split_launch(w_gate, wgh, wgl, (size_t)L_*DI_*D_);
    split_launch(w_up,   wuh, wul, (size_t)L_*DI_*D_);
    split_launch(w_down, wdh, wdl, (size_t)L_*D_*DI_);
    split_launch(emb, embh, embl, (size_t)V_*D_);

    embed_kernel<<<T_*D_/4/256, 256>>>(x, emb, h);
    rope_cache_kernel<<<(S_*32 + 255)/256, 256>>>();

    const dim3 gqkv(3*D_/64, T_/128, 1);   // 48 x 16 = 768 blocks
    const dim3 gp(D_/64,   T_/128, 1);     // 256 blocks
    const dim3 gm(DI_/128, T_/128, 1);     // 512 blocks
    const dim3 gs(S_/128, S_/128, B_*H_);
    const dim3 ga(1,      S_/128, B_*H_);

    for (int l = 0; l < L_; l++) {
        rmsnorm_kernel<<<T_, 256>>>(h, ln1 + (size_t)l*D_, hnh, hnl);

        // fused QKV: q,k -> fp32 [T,2048]; v -> split vT [b][h][d][s]
        gemm_tc<128,64,32,32,32,EPI_QKV,false,3><<<gqkv,256,SM_P>>>(
            hnh, hnl, wqkvh + (size_t)l*3*D_*D_, wqkvl + (size_t)l*3*D_*D_,
            qk, vth, vtl, bqkv + (size_t)l*3*D_,
            T_, 3*D_, D_, D_, D_, 2*D_, 1, 0,0,0,0,0,0, 0.f);

        rope_kernel<<<T_*H_*32/256, 256>>>();

        gemm_tc<128,128,32,64,32,EPI_SCORES,false,2><<<gs,256,SM_S>>>(
            qh, ql, kh, kl, att, nullptr, nullptr, nullptr,
            S_, S_, DH_, D_, D_, S_,
            H_,
            (long long)S_*D_, (long long)DH_,
            (long long)S_*D_, (long long)DH_,
            (long long)H_*S_*S_, (long long)S_*S_,
            0.125f);

        softmax_kernel<<<B_*H_*S_, 256>>>(att, atth, attl);

        // attV: NT gemm against vT, causal-trimmed K, cp.async pipeline
        gemm_tc<128,64,32,32,32,EPI_SPLIT,true,2><<<ga,256,SM_P>>>(
            atth, attl, vth, vtl, nullptr, yh, yl, nullptr,
            S_, DH_, S_, S_, S_, D_,
            H_,
            (long long)H_*S_*S_, (long long)S_*S_,
            (long long)H_*DH_*S_, (long long)DH_*S_,
            (long long)S_*D_, (long long)DH_,
            0.f);

        gemm_tc<128,64,32,32,32,EPI_BIAS_RES,false,3><<<gp,256,SM_P>>>(
            yh, yl, woh + (size_t)l*D_*D_, wol + (size_t)l*D_*D_,
            h, nullptr, nullptr, bo + (size_t)l*D_,
            T_, D_, D_, D_, D_, D_, 1, 0,0,0,0,0,0, 0.f);

        rmsnorm_kernel<<<T_, 256>>>(h, ln2 + (size_t)l*D_, hnh, hnl);

        gemm_tc<128,128,32,64,32,EPI_NONE,false,2><<<gm,256,SM_S>>>(
            hnh, hnl, wgh + (size_t)l*DI_*D_, wgl + (size_t)l*DI_*D_,
            gate, nullptr, nullptr, nullptr,
            T_, DI_, D_, D_, D_, DI_, 1, 0,0,0,0,0,0, 0.f);
        gemm_tc<128,128,32,64,32,EPI_SILU_SPLIT,false,2><<<gm,256,SM_S>>>(
            hnh, hnl, wuh + (size_t)l*DI_*D_, wul + (size_t)l*DI_*D_,
            gate, gah, gal, nullptr,
            T_, DI_, D_, D_, D_, DI_, 1, 0,0,0,0,0,0, 0.f);

        gemm_tc<128,64,32,32,32,EPI_RES,false,3><<<gp,256,SM_P>>>(
            gah, gal, wdh + (size_t)l*D_*DI_, wdl + (size_t)l*D_*DI_,
            h, nullptr, nullptr, nullptr,
            T_, D_, DI_, DI_, DI_, D_, 1, 0,0,0,0,0,0, 0.f);
    }

    rmsnorm_kernel<<<T_, 256>>>(h, norm_w, hnh, hnl);

    const dim3 gl(V_/128, T_/128, 1);
    gemm_tc<128,128,32,64,32,EPI_NONE,false,2><<<gl,256,SM_S>>>(
        hnh, hnl, embh, embl, out, nullptr, nullptr, nullptr,
        T_, V_, D_, D_, D_, V_, 1, 0,0,0,0,0,0, 0.f);
}

// round 11
// speedup vs baseline: 1.2700x; 1.0006x over previous
#include <cuda_runtime.h>
#include <cuda_bf16.h>
#include <cstdint>
#include <math.h>

#define L_  8
#define D_  1024
#define H_  16
#define DH_ 64
#define DI_ 4096
#define V_  32000
#define B_  2
#define S_  1024
#define T_  (B_*S_)

typedef __nv_bfloat16 bf16;

// ---------------- fp32 scratch ----------------
__device__ float g_h   [T_*D_];
__device__ float g_qk  [T_*2048];
__device__ float g_gate[T_*DI_];
__device__ float g_att [(size_t)B_*H_*S_*S_];
__device__ float g_cos [S_*32];
__device__ float g_sin [S_*32];
__device__ float g_bqkv[L_*3*D_];

// ---------------- split bf16 scratch (hi/lo) ----------------
__device__ bf16 s_wqkv_h[L_*3*D_*D_], s_wqkv_l[L_*3*D_*D_];
__device__ bf16 s_wo_h[L_*D_*D_],   s_wo_l[L_*D_*D_];
__device__ bf16 s_wg_h[L_*DI_*D_],  s_wg_l[L_*DI_*D_];
__device__ bf16 s_wu_h[L_*DI_*D_],  s_wu_l[L_*DI_*D_];
__device__ bf16 s_wd_h[L_*D_*DI_],  s_wd_l[L_*D_*DI_];
__device__ bf16 s_emb_h[V_*D_],     s_emb_l[V_*D_];
__device__ bf16 s_hn_h[T_*D_],      s_hn_l[T_*D_];
__device__ bf16 s_q_h [T_*D_],      s_q_l [T_*D_];
__device__ bf16 s_k_h [T_*D_],      s_k_l [T_*D_];
__device__ bf16 s_vt_h[T_*D_],      s_vt_l[T_*D_];     // [b][h][d][s]
__device__ bf16 s_y_h [T_*D_],      s_y_l [T_*D_];
__device__ bf16 s_ga_h[T_*DI_],     s_ga_l[T_*DI_];
__device__ bf16 s_att_h[(size_t)B_*H_*S_*S_], s_att_l[(size_t)B_*H_*S_*S_];

// ---------------- helpers ----------------
__device__ __forceinline__ void split1(float v, bf16& h, bf16& l) {
    h = __float2bfloat16(v);
    l = __float2bfloat16(v - __bfloat162float(h));
}

__device__ __forceinline__ void split_store2(bf16* H, bf16* Lo, size_t off, float v0, float v1) {
    bf16 h0, l0, h1, l1;
    split1(v0, h0, l0);
    split1(v1, h1, l1);
    __nv_bfloat162 th; th.x = h0; th.y = h1;
    __nv_bfloat162 tl; tl.x = l0; tl.y = l1;
    *(__nv_bfloat162*)(H  + off) = th;
    *(__nv_bfloat162*)(Lo + off) = tl;
}

__global__ void split_kernel(const float* __restrict__ x, bf16* __restrict__ h,
                             bf16* __restrict__ l, int n4) {
    int i = blockIdx.x * blockDim.x + threadIdx.x;
    if (i >= n4) return;
    float4 v = ((const float4*)x)[i];
    bf16 h0,l0,h1,l1,h2,l2,h3,l3;
    split1(v.x, h0, l0); split1(v.y, h1, l1);
    split1(v.z, h2, l2); split1(v.w, h3, l3);
    ushort4 th = make_ushort4(__bfloat16_as_ushort(h0), __bfloat16_as_ushort(h1),
                              __bfloat16_as_ushort(h2), __bfloat16_as_ushort(h3));
    ushort4 tl = make_ushort4(__bfloat16_as_ushort(l0), __bfloat16_as_ushort(l1),
                              __bfloat16_as_ushort(l2), __bfloat16_as_ushort(l3));
    ((ushort4*)h)[i] = th;
    ((ushort4*)l)[i] = tl;
}

// split [L,D,D] source into packed [L,3D,D] dst at given row offset
__global__ void split_pack_kernel(const float* __restrict__ x, bf16* __restrict__ h,
                                  bf16* __restrict__ l, int row_off) {
    int i = blockIdx.x * blockDim.x + threadIdx.x;   // over L_*D_*D_/4
    if (i >= L_*D_*D_/4) return;
    int lay = i / (D_*D_/4);
    int rem = i % (D_*D_/4);
    int r   = rem / (D_/4);
    int c4  = rem % (D_/4);
    float4 v = ((const float4*)x)[i];
    int d4 = lay*(3*D_*D_/4) + (row_off + r)*(D_/4) + c4;
    bf16 h0,l0,h1,l1,h2,l2,h3,l3;
    split1(v.x, h0, l0); split1(v.y, h1, l1);
    split1(v.z, h2, l2); split1(v.w, h3, l3);
    ((ushort4*)h)[d4] = make_ushort4(__bfloat16_as_ushort(h0), __bfloat16_as_ushort(h1),
                                     __bfloat16_as_ushort(h2), __bfloat16_as_ushort(h3));
    ((ushort4*)l)[d4] = make_ushort4(__bfloat16_as_ushort(l0), __bfloat16_as_ushort(l1),
                                     __bfloat16_as_ushort(l2), __bfloat16_as_ushort(l3));
}

__global__ void pack_bias_kernel(const float* __restrict__ bq, const float* __restrict__ bk,
                                 const float* __restrict__ bv, float* __restrict__ dst) {
    int i = blockIdx.x * blockDim.x + threadIdx.x;   // L_*3072
    if (i >= L_*3*D_) return;
    int lay = i / (3*D_);
    int j   = i % (3*D_);
    float v = (j < D_) ? bq[lay*D_ + j]
            : (j < 2*D_) ? bk[lay*D_ + j - D_]
            : bv[lay*D_ + j - 2*D_];
    dst[i] = v;
}

// ---------------- small kernels ----------------
__global__ void embed_kernel(const int* __restrict__ x, const float* __restrict__ emb,
                             float* __restrict__ h) {
    int i = blockIdx.x * blockDim.x + threadIdx.x;
    int t = i / (D_/4);
    int c = i % (D_/4);
    float4 v = *(const float4*)(emb + (size_t)x[t]*D_ + c*4);
    *(float4*)(h + (size_t)t*D_ + c*4) = v;
}

__global__ void rope_cache_kernel() {
    int i = blockIdx.x * blockDim.x + threadIdx.x;
    if (i >= S_*32) return;
    int s = i / 32, j = i % 32;
    double inv = pow(10000.0, -(double)j / 32.0);
    double ph = (double)s * inv;
    g_cos[i] = (float)cos(ph);
    g_sin[i] = (float)sin(ph);
}

// rope: reads fused qk fp32 buffer [T,2048], writes split q/k [T,1024]
__global__ void rope_kernel() {
    int i = blockIdx.x * blockDim.x + threadIdx.x;   // T_*H_*32
    int t = i >> 9;
    int r = i & 511;
    int h = r >> 5, d = r & 31;
    int s = t & (S_-1);
    float c  = g_cos[s*32 + d];
    float sn = g_sin[s*32 + d];
    size_t qkb = (size_t)t*2048 + h*DH_ + d;
    size_t ob  = (size_t)t*D_   + h*DH_ + d;
    float a, b, r0, r1;
    a = g_qk[qkb]; b = g_qk[qkb+32];
    r0 = a*c - b*sn;  r1 = b*c + a*sn;
    split1(r0, s_q_h[ob],    s_q_l[ob]);
    split1(r1, s_q_h[ob+32], s_q_l[ob+32]);
    a = g_qk[qkb+1024]; b = g_qk[qkb+1024+32];
    r0 = a*c - b*sn;  r1 = b*c + a*sn;
    split1(r0, s_k_h[ob],    s_k_l[ob]);
    split1(r1, s_k_h[ob+32], s_k_l[ob+32]);
}

__global__ void rmsnorm_kernel(const float* __restrict__ x, const float* __restrict__ w,
                               bf16* __restrict__ oh, bf16* __restrict__ ol) {
    int t = blockIdx.x;
    int tid = threadIdx.x;
    const float* xp = x + (size_t)t*D_;
    float v[4];
    float s = 0.f;
    #pragma unroll
    for (int i = 0; i < 4; i++) { v[i] = xp[tid + i*256]; s += v[i]*v[i]; }
    #pragma unroll
    for (int off = 16; off; off >>= 1) s += __shfl_xor_sync(0xffffffffu, s, off);
    __shared__ float red[8];
    if ((tid & 31) == 0) red[tid >> 5] = s;
    __syncthreads();
    if (tid < 32) {
        float s2 = (tid < 8) ? red[tid] : 0.f;
        #pragma unroll
        for (int off = 4; off; off >>= 1) s2 += __shfl_xor_sync(0xffffffffu, s2, off);
        if (tid == 0) red[0] = s2;
    }
    __syncthreads();
    float r = rsqrtf(red[0] * (1.f/(float)D_) + 1e-6f);
    size_t base = (size_t)t*D_;
    #pragma unroll
    for (int i = 0; i < 4; i++) {
        int idx = tid + i*256;
        split1(w[idx] * v[i] * r, oh[base+idx], ol[base+idx]);
    }
}

__global__ void softmax_kernel(const float* __restrict__ att,
                               bf16* __restrict__ oh, bf16* __restrict__ ol) {
    int row = blockIdx.x & (S_-1);
    const float* p = att + (size_t)blockIdx.x * S_;
    int tid = threadIdx.x;
    float vals[4];
    float mx = -INFINITY;
    #pragma unroll
    for (int i = 0; i < 4; i++) {
        int j = tid + i*256;
        vals[i] = (j <= row) ? p[j] : -INFINITY;
        mx = fmaxf(mx, vals[i]);
    }
    #pragma unroll
    for (int off = 16; off; off >>= 1) mx = fmaxf(mx, __shfl_xor_sync(0xffffffffu, mx, off));
    __shared__ float redm[8];
    if ((tid & 31) == 0) redm[tid >> 5] = mx;
    __syncthreads();
    if (tid < 32) {
        float m2 = (tid < 8) ? redm[tid] : -INFINITY;
        #pragma unroll
        for (int off = 4; off; off >>= 1) m2 = fmaxf(m2, __shfl_xor_sync(0xffffffffu, m2, off));
        if (tid == 0) redm[0] = m2;
    }
    __syncthreads();
    float m = redm[0];
    float s = 0.f;
    #pragma unroll
    for (int i = 0; i < 4; i++) { vals[i] = expf(vals[i] - m); s += vals[i]; }
    #pragma unroll
    for (int off = 16; off; off >>= 1) s += __shfl_xor_sync(0xffffffffu, s, off);
    __shared__ float reds[8];
    if ((tid & 31) == 0) reds[tid >> 5] = s;
    __syncthreads();
    if (tid < 32) {
        float s2 = (tid < 8) ? reds[tid] : 0.f;
        #pragma unroll
        for (int off = 4; off; off >>= 1) s2 += __shfl_xor_sync(0xffffffffu, s2, off);
        if (tid == 0) reds[0] = s2;
    }
    __syncthreads();
    float inv = 1.f / reds[0];
    size_t base = (size_t)blockIdx.x * S_;
    #pragma unroll
    for (int i = 0; i < 4; i++) {
        int j = tid + i*256;
        split1(vals[i] * inv, oh[base+j], ol[base+j]);
    }
}

// ---------------- bf16x3 GEMM on pre-split operands ----------------
enum { EPI_NONE = 0, EPI_BIAS = 1, EPI_BIAS_RES = 2, EPI_RES = 3, EPI_SCORES = 4,
       EPI_BIAS_SPLIT = 5, EPI_SPLIT = 6, EPI_SILU_SPLIT = 7, EPI_QKV = 8 };

__device__ __forceinline__ void mma_bf16(float* d, const uint32_t* a, const uint32_t* b) {
    asm volatile(
        "mma.sync.aligned.m16n8k16.row.col.f32.bf16.bf16.f32 "
        "{%0,%1,%2,%3}, {%4,%5,%6,%7}, {%8,%9}, {%0,%1,%2,%3};\n"
        : "+f"(d[0]), "+f"(d[1]), "+f"(d[2]), "+f"(d[3])
        : "r"(a[0]), "r"(a[1]), "r"(a[2]), "r"(a[3]),
          "r"(b[0]), "r"(b[1]));
}

#define CP_ASYNC16(dst, src) \
    asm volatile("cp.async.cg.shared.global [%0], [%1], 16;" :: "r"(dst), "l"(src))
#define CP_COMMIT() asm volatile("cp.async.commit_group;" ::: "memory")
#define CP_WAIT0()  asm volatile("cp.async.wait_group 0;"  ::: "memory")

// A: bf16 [M,K] row-major (hi+lo).  B bf16 [N,K] row-major (NT). cp.async pipeline.
template<int BM, int BN, int BK, int WM, int WN, int EPI, bool TRIMK, int MINB>
__global__ __launch_bounds__((BM/WM)*(BN/WN)*32, MINB)
void gemm_tc(const bf16* __restrict__ Agh, const bf16* __restrict__ Agl,
             const bf16* __restrict__ Bgh, const bf16* __restrict__ Bgl,
             float* __restrict__ C, bf16* __restrict__ Oh, bf16* __restrict__ Ol,
             const float* __restrict__ bias,
             int M, int N, int K, int lda, int ldb, int ldc,
             int zinner,
             long long sAo, long long sAi,
             long long sBo, long long sBi,
             long long sCo, long long sCi,
             float scale)
{
    constexpr int WARPS_N = BN/WN;
    constexpr int THREADS = (BM/WM)*(BN/WN)*32;
    constexpr int MT = WM/16;
    constexpr int NT = WN/8;
    constexpr int SP = BK/2 + 4;
    constexpr int SZA = BM*SP;
    constexpr int SZB = BN*SP;
    constexpr int STAGE = 2*SZA + 2*SZB;
    constexpr int NCA = (BM*BK/8)/THREADS;
    constexpr int NCB = (BN*BK/8)/THREADS;

    extern __shared__ uint32_t smem_u[];

    const int tid = threadIdx.x;
    const int z  = blockIdx.z;
    const int zo = z / zinner, zi = z % zinner;
    const bf16* Abh = Agh + zo*sAo + zi*sAi;
    const bf16* Abl = Agl + zo*sAo + zi*sAi;
    const bf16* Bbh = Bgh + zo*sBo + zi*sBi;
    const bf16* Bbl = Bgl + zo*sBo + zi*sBi;
    float* Cb  = C  ? (C  + zo*sCo + zi*sCi) : nullptr;
    bf16*  Ohb = Oh ? (Oh + zo*sCo + zi*sCi) : nullptr;
    bf16*  Olb = Ol ? (Ol + zo*sCo + zi*sCi) : nullptr;
    const int m0 = blockIdx.y * BM;
    const int n0 = blockIdx.x * BN;

    if (EPI == EPI_SCORES && n0 >= m0 + BM) return;

    const int warp = tid >> 5;
    const int lane = tid & 31;
    const int g = lane >> 2;
    const int c = lane & 3;
    const int wn = warp % WARPS_N;
    const int wm = warp / WARPS_N;

    float acc[MT][NT][4];
    #pragma unroll
    for (int i = 0; i < MT; i++)
        #pragma unroll
        for (int j = 0; j < NT; j++)
            #pragma unroll
            for (int r = 0; r < 4; r++) acc[i][j][r] = 0.f;

    const int Kend = TRIMK ? min(K, m0 + BM) : K;
    const int nk = Kend / BK;

    const uint32_t smb = (uint32_t)__cvta_generic_to_shared(smem_u);
    auto cp_tile = [&](int kt, int s) {
        const uint32_t Ah = smb + s*STAGE*4;
        const uint32_t Al = Ah + SZA*4;
        const uint32_t Bh = Al + SZA*4;
        const uint32_t Bl = Bh + SZB*4;
        #pragma unroll
        for (int i = 0; i < NCA; i++) {
            int f  = tid + i*THREADS;
            int r  = f / (BK/8);
            int c8 = f % (BK/8);
            size_t   go = (size_t)(m0+r)*lda + kt + c8*8;
            uint32_t so = (uint32_t)(r*SP + c8*4)*4;
            CP_ASYNC16(Ah + so, Abh + go);
            CP_ASYNC16(Al + so, Abl + go);
        }
        #pragma unroll
        for (int i = 0; i < NCB; i++) {
            int f  = tid + i*THREADS;
            int r  = f / (BK/8);
            int c8 = f % (BK/8);
            size_t   go = (size_t)(n0+r)*ldb + kt + c8*8;
            uint32_t so = (uint32_t)(r*SP + c8*4)*4;
            CP_ASYNC16(Bh + so, Bbh + go);
            CP_ASYNC16(Bl + so, Bbl + go);
        }
        CP_COMMIT();
    };

    auto compute_stage = [&](int cur) {
        const uint32_t* Ah = smem_u + cur*STAGE;
        const uint32_t* Al = Ah + SZA;
        const uint32_t* Bh = Al + SZA;
        const uint32_t* Bl = Bh + SZB;
        #pragma unroll
        for (int ks = 0; ks < BK; ks += 16) {
            const int kp = ks >> 1;
            uint32_t ah[MT][4], al[MT][4], bh[NT][2], bl[NT][2];
            #pragma unroll
            for (int i = 0; i < MT; i++) {
                int mr = wm*WM + i*16 + g;
                ah[i][0] = Ah[mr*SP     + kp + c];   al[i][0] = Al[mr*SP     + kp + c];
                ah[i][1] = Ah[(mr+8)*SP + kp + c];   al[i][1] = Al[(mr+8)*SP + kp + c];
                ah[i][2] = Ah[mr*SP     + kp + c+4]; al[i][2] = Al[mr*SP     + kp + c+4];
                ah[i][3] = Ah[(mr+8)*SP + kp + c+4]; al[i][3] = Al[(mr+8)*SP + kp + c+4];
            }
            #pragma unroll
            for (int j = 0; j < NT; j++) {
                int nr = wn*WN + j*8 + g;
                bh[j][0] = Bh[nr*SP + kp + c];   bl[j][0] = Bl[nr*SP + kp + c];
                bh[j][1] = Bh[nr*SP + kp + c+4]; bl[j][1] = Bl[nr*SP + kp + c+4];
            }
            #pragma unroll
            for (int i = 0; i < MT; i++)
                #pragma unroll
                for (int j = 0; j < NT; j++)
                    mma_bf16(acc[i][j], ah[i], bh[j]);
            #pragma unroll
            for (int i = 0; i < MT; i++)
                #pragma unroll
                for (int j = 0; j < NT; j++)
                    mma_bf16(acc[i][j], ah[i], bl[j]);
            #pragma unroll
            for (int i = 0; i < MT; i++)
                #pragma unroll
                for (int j = 0; j < NT; j++)
                    mma_bf16(acc[i][j], al[i], bh[j]);
        }
    };

    cp_tile(0, 0);
    CP_WAIT0();
    __syncthreads();

    for (int t = 0; t < nk; t++) {
        const int cur = t & 1;
        if (t + 1 < nk) cp_tile((t+1)*BK, cur ^ 1);
        compute_stage(cur);
        if (t + 1 < nk) CP_WAIT0();
        __syncthreads();
    }

    #pragma unroll
    for (int i = 0; i < MT; i++) {
        #pragma unroll
        for (int j = 0; j < NT; j++) {
            int n = n0 + wn*WN + j*8 + 2*c;
            #pragma unroll
            for (int rr = 0; rr < 2; rr++) {
                int m = m0 + wm*WM + i*16 + g + rr*8;
                float v0 = acc[i][j][rr*2 + 0];
                float v1 = acc[i][j][rr*2 + 1];
                if (EPI == EPI_QKV) {
                    v0 += bias[n]; v1 += bias[n+1];
                    if (n < 2*D_) {
                        *(float2*)(Cb + (size_t)m*ldc + n) = make_float2(v0, v1);
                    } else {
                        // split-store V transposed: [b][h][d][s]
                        int dg = n - 2*D_;
                        int hh = dg >> 6, dd = dg & 63;
                        int b  = m >> 10, s = m & 1023;
                        size_t o0 = (((size_t)b*H_ + hh)*DH_ + dd)*S_ + s;
                        split1(v0, Oh[o0],      Ol[o0]);
                        split1(v1, Oh[o0+S_],   Ol[o0+S_]);
                    }
                    continue;
                }
                size_t off = (size_t)m*ldc + n;
                if (EPI == EPI_BIAS) {
                    v0 += bias[n]; v1 += bias[n+1];
                    *(float2*)(Cb + off) = make_float2(v0, v1);
                } else if (EPI == EPI_BIAS_RES) {
                    v0 += bias[n]   + Cb[off];
                    v1 += bias[n+1] + Cb[off+1];
                    *(float2*)(Cb + off) = make_float2(v0, v1);
                } else if (EPI == EPI_RES) {
                    v0 += Cb[off]; v1 += Cb[off+1];
                    *(float2*)(Cb + off) = make_float2(v0, v1);
                } else if (EPI == EPI_SCORES) {
                    *(float2*)(Cb + off) = make_float2(v0*scale, v1*scale);
                } else if (EPI == EPI_NONE) {
                    *(float2*)(Cb + off) = make_float2(v0, v1);
                } else if (EPI == EPI_BIAS_SPLIT) {
                    split_store2(Ohb, Olb, off, v0 + bias[n], v1 + bias[n+1]);
                } else if (EPI == EPI_SPLIT) {
                    split_store2(Ohb, Olb, off, v0, v1);
                } else if (EPI == EPI_SILU_SPLIT) {
                    float g0 = Cb[off], g1 = Cb[off+1];
                    v0 *= g0 / (1.f + expf(-g0));
                    v1 *= g1 / (1.f + expf(-g1));
                    split_store2(Ohb, Olb, off, v0, v1);
                }
            }
        }
    }
}

// ---------------- host ----------------
template<int BM, int BN, int BK>
constexpr int smem_bytes() {
    return 2 * (2*BM*(BK/2+4) + 2*BN*(BK/2+4)) * 4;
}

extern "C" void kernel_launch(void* const* d_in, const int* in_sizes, int n_in,
                              void* d_out, int out_size) {
    const int*   x      = (const int*)  d_in[0];
    const float* emb    = (const float*)d_in[1];
    const float* wq     = (const float*)d_in[2];
    const float* bq     = (const float*)d_in[3];
    const float* wk     = (const float*)d_in[4];
    const float* bk     = (const float*)d_in[5];
    const float* wv     = (const float*)d_in[6];
    const float* bv     = (const float*)d_in[7];
    const float* wo     = (const float*)d_in[8];
    const float* bo     = (const float*)d_in[9];
    const float* w_gate = (const float*)d_in[10];
    const float* w_up   = (const float*)d_in[11];
    const float* w_down = (const float*)d_in[12];
    const float* ln1    = (const float*)d_in[13];
    const float* ln2    = (const float*)d_in[14];
    const float* norm_w = (const float*)d_in[15];
    float* out = (float*)d_out;

    float *h, *qk, *gate, *att, *bqkv;
    cudaGetSymbolAddress((void**)&h,    g_h);
    cudaGetSymbolAddress((void**)&qk,   g_qk);
    cudaGetSymbolAddress((void**)&gate, g_gate);
    cudaGetSymbolAddress((void**)&att,  g_att);
    cudaGetSymbolAddress((void**)&bqkv, g_bqkv);

    bf16 *wqkvh,*wqkvl,*woh,*wol,*wgh,*wgl,*wuh,*wul,*wdh,*wdl,*embh,*embl;
    bf16 *hnh,*hnl,*qh,*ql,*kh,*kl,*vth,*vtl,*yh,*yl,*gah,*gal,*atth,*attl;
    cudaGetSymbolAddress((void**)&wqkvh, s_wqkv_h); cudaGetSymbolAddress((void**)&wqkvl, s_wqkv_l);
    cudaGetSymbolAddress((void**)&woh, s_wo_h);  cudaGetSymbolAddress((void**)&wol, s_wo_l);
    cudaGetSymbolAddress((void**)&wgh, s_wg_h);  cudaGetSymbolAddress((void**)&wgl, s_wg_l);
    cudaGetSymbolAddress((void**)&wuh, s_wu_h);  cudaGetSymbolAddress((void**)&wul, s_wu_l);
    cudaGetSymbolAddress((void**)&wdh, s_wd_h);  cudaGetSymbolAddress((void**)&wdl, s_wd_l);
    cudaGetSymbolAddress((void**)&embh, s_emb_h); cudaGetSymbolAddress((void**)&embl, s_emb_l);
    cudaGetSymbolAddress((void**)&hnh, s_hn_h);  cudaGetSymbolAddress((void**)&hnl, s_hn_l);
    cudaGetSymbolAddress((void**)&qh,  s_q_h);   cudaGetSymbolAddress((void**)&ql,  s_q_l);
    cudaGetSymbolAddress((void**)&kh,  s_k_h);   cudaGetSymbolAddress((void**)&kl,  s_k_l);
    cudaGetSymbolAddress((void**)&vth, s_vt_h);  cudaGetSymbolAddress((void**)&vtl, s_vt_l);
    cudaGetSymbolAddress((void**)&yh,  s_y_h);   cudaGetSymbolAddress((void**)&yl,  s_y_l);
    cudaGetSymbolAddress((void**)&gah, s_ga_h);  cudaGetSymbolAddress((void**)&gal, s_ga_l);
    cudaGetSymbolAddress((void**)&atth, s_att_h); cudaGetSymbolAddress((void**)&attl, s_att_l);

    constexpr int SM_S = smem_bytes<128,128,32>();   // 81920
    constexpr int SM_P = smem_bytes<128,64,32>();    // 61440

    cudaFuncSetAttribute(gemm_tc<128,64,32,32,32,EPI_QKV,false,3>,      cudaFuncAttributeMaxDynamicSharedMemorySize, SM_P);
    cudaFuncSetAttribute(gemm_tc<128,128,32,64,32,EPI_SCORES,false,2>,  cudaFuncAttributeMaxDynamicSharedMemorySize, SM_S);
    cudaFuncSetAttribute(gemm_tc<128,64,32,32,32,EPI_SPLIT,true,2>,     cudaFuncAttributeMaxDynamicSharedMemorySize, SM_P);
    cudaFuncSetAttribute(gemm_tc<128,64,32,32,32,EPI_BIAS_RES,false,3>, cudaFuncAttributeMaxDynamicSharedMemorySize, SM_P);
    cudaFuncSetAttribute(gemm_tc<128,128,32,64,32,EPI_NONE,false,2>,    cudaFuncAttributeMaxDynamicSharedMemorySize, SM_S);
    cudaFuncSetAttribute(gemm_tc<128,128,32,64,32,EPI_SILU_SPLIT,false,2>, cudaFuncAttributeMaxDynamicSharedMemorySize, SM_S);
    cudaFuncSetAttribute(gemm_tc<128,64,32,32,32,EPI_RES,false,3>,      cudaFuncAttributeMaxDynamicSharedMemorySize, SM_P);

    // ---- prep: split weights + embedding; pack QKV ----
    auto split_launch = [](const float* src, bf16* dh, bf16* dl, size_t n) {
        int n4 = (int)(n / 4);
        split_kernel<<<(n4 + 255)/256, 256>>>(src, dh, dl, n4);
    };
    int nw4 = L_*D_*D_/4;
    split_pack_kernel<<<(nw4+255)/256, 256>>>(wq, wqkvh, wqkvl, 0);
    split_pack_kernel<<<(nw4+255)/256, 256>>>(wk, wqkvh, wqkvl, D_);
    split_pack_kernel<<<(nw4+255)/256, 256>>>(wv, wqkvh, wqkvl, 2*D_);
    pack_bias_kernel<<<(L_*3*D_+255)/256, 256>>>(bq, bk, bv, bqkv);
    split_launch(wo, woh, wol, (size_t)L_*D_*D_);
    split_launch(w_gate, wgh, wgl, (size_t)L_*DI_*D_);
    split_launch(w_up,   wuh, wul, (size_t)L_*DI_*D_);
    split_launch(w_down, wdh, wdl, (size_t)L_*D_*DI_);
    split_launch(emb, embh, embl, (size_t)V_*D_);

    embed_kernel<<<T_*D_/4/256, 256>>>(x, emb, h);
    rope_cache_kernel<<<(S_*32 + 255)/256, 256>>>();

    const dim3 gqkv(3*D_/64, T_/128, 1);   // 48 x 16 = 768 blocks
    const dim3 gp(D_/64,   T_/128, 1);     // 256 blocks
    const dim3 gm(DI_/128, T_/128, 1);     // 512 blocks
    const dim3 gs(S_/128, S_/128, B_*H_);
    const dim3 ga(1,      S_/128, B_*H_);

    for (int l = 0; l < L_; l++) {
        rmsnorm_kernel<<<T_, 256>>>(h, ln1 + (size_t)l*D_, hnh, hnl);

        // fused QKV: q,k -> fp32 [T,2048]; v -> split vT [b][h][d][s]
        gemm_tc<128,64,32,32,32,EPI_QKV,false,3><<<gqkv,256,SM_P>>>(
            hnh, hnl, wqkvh + (size_t)l*3*D_*D_, wqkvl + (size_t)l*3*D_*D_,
            qk, vth, vtl, bqkv + (size_t)l*3*D_,
            T_, 3*D_, D_, D_, D_, 2*D_, 1, 0,0,0,0,0,0, 0.f);

        rope_kernel<<<T_*H_*32/256, 256>>>();

        gemm_tc<128,128,32,64,32,EPI_SCORES,false,2><<<gs,256,SM_S>>>(
            qh, ql, kh, kl, att, nullptr, nullptr, nullptr,
            S_, S_, DH_, D_, D_, S_,
            H_,
            (long long)S_*D_, (long long)DH_,
            (long long)S_*D_, (long long)DH_,
            (long long)H_*S_*S_, (long long)S_*S_,
            0.125f);

        softmax_kernel<<<B_*H_*S_, 256>>>(att, atth, attl);

        // attV: NT gemm against vT, causal-trimmed K, cp.async pipeline
        gemm_tc<128,64,32,32,32,EPI_SPLIT,true,2><<<ga,256,SM_P>>>(
            atth, attl, vth, vtl, nullptr, yh, yl, nullptr,
            S_, DH_, S_, S_, S_, D_,
            H_,
            (long long)H_*S_*S_, (long long)S_*S_,
            (long long)H_*DH_*S_, (long long)DH_*S_,
            (long long)S_*D_, (long long)DH_,
            0.f);

        gemm_tc<128,64,32,32,32,EPI_BIAS_RES,false,3><<<gp,256,SM_P>>>(
            yh, yl, woh + (size_t)l*D_*D_, wol + (size_t)l*D_*D_,
            h, nullptr, nullptr, bo + (size_t)l*D_,
            T_, D_, D_, D_, D_, D_, 1, 0,0,0,0,0,0, 0.f);

        rmsnorm_kernel<<<T_, 256>>>(h, ln2 + (size_t)l*D_, hnh, hnl);

        gemm_tc<128,128,32,64,32,EPI_NONE,false,2><<<gm,256,SM_S>>>(
            hnh, hnl, wgh + (size_t)l*DI_*D_, wgl + (size_t)l*DI_*D_,
            gate, nullptr, nullptr, nullptr,
            T_, DI_, D_, D_, D_, DI_, 1, 0,0,0,0,0,0, 0.f);
        gemm_tc<128,128,32,64,32,EPI_SILU_SPLIT,false,2><<<gm,256,SM_S>>>(
            hnh, hnl, wuh + (size_t)l*DI_*D_, wul + (size_t)l*DI_*D_,
            gate, gah, gal, nullptr,
            T_, DI_, D_, D_, D_, DI_, 1, 0,0,0,0,0,0, 0.f);

        gemm_tc<128,64,32,32,32,EPI_RES,false,3><<<gp,256,SM_P>>>(
            gah, gal, wdh + (size_t)l*D_*DI_, wdl + (size_t)l*D_*DI_,
            h, nullptr, nullptr, nullptr,
            T_, D_, DI_, DI_, DI_, D_, 1, 0,0,0,0,0,0, 0.f);
    }

    rmsnorm_kernel<<<T_, 256>>>(h, norm_w, hnh, hnl);

    const dim3 gl(V_/128, T_/128, 1);
    gemm_tc<128,128,32,64,32,EPI_NONE,false,2><<<gl,256,SM_S>>>(
        hnh, hnl, embh, embl, out, nullptr, nullptr, nullptr,
        T_, V_, D_, D_, D_, V_, 1, 0,0,0,0,0,0, 0.f);
}

// round 12
// speedup vs baseline: 1.3349x; 1.0511x over previous
#include <cuda_runtime.h>
#include <cuda_bf16.h>
#include <cstdint>
#include <math.h>

#define L_  8
#define D_  1024
#define H_  16
#define DH_ 64
#define DI_ 4096
#define V_  32000
#define B_  2
#define S_  1024
#define T_  (B_*S_)

typedef __nv_bfloat16 bf16;

// ---------------- fp32 scratch ----------------
__device__ float g_h   [T_*D_];
__device__ float g_qk  [T_*2048];
__device__ float g_att [(size_t)B_*H_*S_*S_];
__device__ float g_cos [S_*32];
__device__ float g_sin [S_*32];
__device__ float g_bqkv[L_*3*D_];

// ---------------- split bf16 scratch (hi/lo) ----------------
__device__ bf16 s_wqkv_h[L_*3*D_*D_], s_wqkv_l[L_*3*D_*D_];
__device__ bf16 s_wo_h[L_*D_*D_],   s_wo_l[L_*D_*D_];
__device__ bf16 s_wgu_h[(size_t)L_*2*DI_*D_], s_wgu_l[(size_t)L_*2*DI_*D_];  // interleaved gate/up
__device__ bf16 s_wd_h[L_*D_*DI_],  s_wd_l[L_*D_*DI_];
__device__ bf16 s_emb_h[V_*D_],     s_emb_l[V_*D_];
__device__ bf16 s_hn_h[T_*D_],      s_hn_l[T_*D_];
__device__ bf16 s_q_h [T_*D_],      s_q_l [T_*D_];
__device__ bf16 s_k_h [T_*D_],      s_k_l [T_*D_];
__device__ bf16 s_vt_h[T_*D_],      s_vt_l[T_*D_];     // [b][h][d][s]
__device__ bf16 s_y_h [T_*D_],      s_y_l [T_*D_];
__device__ bf16 s_ga_h[T_*DI_],     s_ga_l[T_*DI_];
__device__ bf16 s_att_h[(size_t)B_*H_*S_*S_], s_att_l[(size_t)B_*H_*S_*S_];

// ---------------- helpers ----------------
__device__ __forceinline__ void split1(float v, bf16& h, bf16& l) {
    h = __float2bfloat16(v);
    l = __float2bfloat16(v - __bfloat162float(h));
}

__device__ __forceinline__ void split_store2(bf16* H, bf16* Lo, size_t off, float v0, float v1) {
    bf16 h0, l0, h1, l1;
    split1(v0, h0, l0);
    split1(v1, h1, l1);
    __nv_bfloat162 th; th.x = h0; th.y = h1;
    __nv_bfloat162 tl; tl.x = l0; tl.y = l1;
    *(__nv_bfloat162*)(H  + off) = th;
    *(__nv_bfloat162*)(Lo + off) = tl;
}

__global__ void split_kernel(const float* __restrict__ x, bf16* __restrict__ h,
                             bf16* __restrict__ l, int n4) {
    int i = blockIdx.x * blockDim.x + threadIdx.x;
    if (i >= n4) return;
    float4 v = ((const float4*)x)[i];
    bf16 h0,l0,h1,l1,h2,l2,h3,l3;
    split1(v.x, h0, l0); split1(v.y, h1, l1);
    split1(v.z, h2, l2); split1(v.w, h3, l3);
    ((ushort4*)h)[i] = make_ushort4(__bfloat16_as_ushort(h0), __bfloat16_as_ushort(h1),
                                    __bfloat16_as_ushort(h2), __bfloat16_as_ushort(h3));
    ((ushort4*)l)[i] = make_ushort4(__bfloat16_as_ushort(l0), __bfloat16_as_ushort(l1),
                                    __bfloat16_as_ushort(l2), __bfloat16_as_ushort(l3));
}

// split [L,D,D] source into packed [L,3D,D] dst at given row offset
__global__ void split_pack_kernel(const float* __restrict__ x, bf16* __restrict__ h,
                                  bf16* __restrict__ l, int row_off) {
    int i = blockIdx.x * blockDim.x + threadIdx.x;
    if (i >= L_*D_*D_/4) return;
    int lay = i / (D_*D_/4);
    int rem = i % (D_*D_/4);
    int r   = rem / (D_/4);
    int c4  = rem % (D_/4);
    float4 v = ((const float4*)x)[i];
    int d4 = lay*(3*D_*D_/4) + (row_off + r)*(D_/4) + c4;
    bf16 h0,l0,h1,l1,h2,l2,h3,l3;
    split1(v.x, h0, l0); split1(v.y, h1, l1);
    split1(v.z, h2, l2); split1(v.w, h3, l3);
    ((ushort4*)h)[d4] = make_ushort4(__bfloat16_as_ushort(h0), __bfloat16_as_ushort(h1),
                                     __bfloat16_as_ushort(h2), __bfloat16_as_ushort(h3));
    ((ushort4*)l)[d4] = make_ushort4(__bfloat16_as_ushort(l0), __bfloat16_as_ushort(l1),
                                     __bfloat16_as_ushort(l2), __bfloat16_as_ushort(l3));
}

// interleave gate/up rows: dst row 2j = gate_j, 2j+1 = up_j, per layer. [L, 2*DI, D]
__global__ void split_pack_gu_kernel(const float* __restrict__ wg, const float* __restrict__ wu,
                                     bf16* __restrict__ h, bf16* __restrict__ l) {
    int i = blockIdx.x * blockDim.x + threadIdx.x;   // over L_*DI_*D_/4 (per source)
    if (i >= L_*DI_*D_/4) return;
    int lay = i / (DI_*D_/4);
    int rem = i % (DI_*D_/4);
    int r   = rem / (D_/4);
    int c4  = rem % (D_/4);
    float4 vg = ((const float4*)wg)[i];
    float4 vu = ((const float4*)wu)[i];
    size_t base = (size_t)lay*(2*DI_*D_/4);
    size_t dg = base + (size_t)(2*r)  *(D_/4) + c4;
    size_t du = base + (size_t)(2*r+1)*(D_/4) + c4;
    bf16 h0,l0,h1,l1,h2,l2,h3,l3;
    split1(vg.x, h0, l0); split1(vg.y, h1, l1);
    split1(vg.z, h2, l2); split1(vg.w, h3, l3);
    ((ushort4*)h)[dg] = make_ushort4(__bfloat16_as_ushort(h0), __bfloat16_as_ushort(h1),
                                     __bfloat16_as_ushort(h2), __bfloat16_as_ushort(h3));
    ((ushort4*)l)[dg] = make_ushort4(__bfloat16_as_ushort(l0), __bfloat16_as_ushort(l1),
                                     __bfloat16_as_ushort(l2), __bfloat16_as_ushort(l3));
    split1(vu.x, h0, l0); split1(vu.y, h1, l1);
    split1(vu.z, h2, l2); split1(vu.w, h3, l3);
    ((ushort4*)h)[du] = make_ushort4(__bfloat16_as_ushort(h0), __bfloat16_as_ushort(h1),
                                     __bfloat16_as_ushort(h2), __bfloat16_as_ushort(h3));
    ((ushort4*)l)[du] = make_ushort4(__bfloat16_as_ushort(l0), __bfloat16_as_ushort(l1),
                                     __bfloat16_as_ushort(l2), __bfloat16_as_ushort(l3));
}

__global__ void pack_bias_kernel(const float* __restrict__ bq, const float* __restrict__ bk,
                                 const float* __restrict__ bv, float* __restrict__ dst) {
    int i = blockIdx.x * blockDim.x + threadIdx.x;
    if (i >= L_*3*D_) return;
    int lay = i / (3*D_);
    int j   = i % (3*D_);
    float v = (j < D_) ? bq[lay*D_ + j]
            : (j < 2*D_) ? bk[lay*D_ + j - D_]
            : bv[lay*D_ + j - 2*D_];
    dst[i] = v;
}

// ---------------- small kernels ----------------
__global__ void embed_kernel(const int* __restrict__ x, const float* __restrict__ emb,
                             float* __restrict__ h) {
    int i = blockIdx.x * blockDim.x + threadIdx.x;
    int t = i / (D_/4);
    int c = i % (D_/4);
    float4 v = *(const float4*)(emb + (size_t)x[t]*D_ + c*4);
    *(float4*)(h + (size_t)t*D_ + c*4) = v;
}

__global__ void rope_cache_kernel() {
    int i = blockIdx.x * blockDim.x + threadIdx.x;
    if (i >= S_*32) return;
    int s = i / 32, j = i % 32;
    double inv = pow(10000.0, -(double)j / 32.0);
    double ph = (double)s * inv;
    g_cos[i] = (float)cos(ph);
    g_sin[i] = (float)sin(ph);
}

__global__ void rope_kernel() {
    int i = blockIdx.x * blockDim.x + threadIdx.x;
    int t = i >> 9;
    int r = i & 511;
    int h = r >> 5, d = r & 31;
    int s = t & (S_-1);
    float c  = g_cos[s*32 + d];
    float sn = g_sin[s*32 + d];
    size_t qkb = (size_t)t*2048 + h*DH_ + d;
    size_t ob  = (size_t)t*D_   + h*DH_ + d;
    float a, b, r0, r1;
    a = g_qk[qkb]; b = g_qk[qkb+32];
    r0 = a*c - b*sn;  r1 = b*c + a*sn;
    split1(r0, s_q_h[ob],    s_q_l[ob]);
    split1(r1, s_q_h[ob+32], s_q_l[ob+32]);
    a = g_qk[qkb+1024]; b = g_qk[qkb+1024+32];
    r0 = a*c - b*sn;  r1 = b*c + a*sn;
    split1(r0, s_k_h[ob],    s_k_l[ob]);
    split1(r1, s_k_h[ob+32], s_k_l[ob+32]);
}

__global__ void rmsnorm_kernel(const float* __restrict__ x, const float* __restrict__ w,
                               bf16* __restrict__ oh, bf16* __restrict__ ol) {
    int t = blockIdx.x;
    int tid = threadIdx.x;
    const float* xp = x + (size_t)t*D_;
    float v[4];
    float s = 0.f;
    #pragma unroll
    for (int i = 0; i < 4; i++) { v[i] = xp[tid + i*256]; s += v[i]*v[i]; }
    #pragma unroll
    for (int off = 16; off; off >>= 1) s += __shfl_xor_sync(0xffffffffu, s, off);
    __shared__ float red[8];
    if ((tid & 31) == 0) red[tid >> 5] = s;
    __syncthreads();
    if (tid < 32) {
        float s2 = (tid < 8) ? red[tid] : 0.f;
        #pragma unroll
        for (int off = 4; off; off >>= 1) s2 += __shfl_xor_sync(0xffffffffu, s2, off);
        if (tid == 0) red[0] = s2;
    }
    __syncthreads();
    float r = rsqrtf(red[0] * (1.f/(float)D_) + 1e-6f);
    size_t base = (size_t)t*D_;
    #pragma unroll
    for (int i = 0; i < 4; i++) {
        int idx = tid + i*256;
        split1(w[idx] * v[i] * r, oh[base+idx], ol[base+idx]);
    }
}

// causal softmax; writes split bf16 only up to the 128-aligned bound attV reads
__global__ void softmax_kernel(const float* __restrict__ att,
                               bf16* __restrict__ oh, bf16* __restrict__ ol) {
    int row = blockIdx.x & (S_-1);
    const float* p = att + (size_t)blockIdx.x * S_;
    int tid = threadIdx.x;
    const int bound = ((row >> 7) + 1) << 7;
    float vals[4];
    float mx = -INFINITY;
    #pragma unroll
    for (int i = 0; i < 4; i++) {
        int j = tid + i*256;
        vals[i] = (j <= row) ? p[j] : -INFINITY;
        mx = fmaxf(mx, vals[i]);
    }
    #pragma unroll
    for (int off = 16; off; off >>= 1) mx = fmaxf(mx, __shfl_xor_sync(0xffffffffu, mx, off));
    __shared__ float redm[8];
    if ((tid & 31) == 0) redm[tid >> 5] = mx;
    __syncthreads();
    if (tid < 32) {
        float m2 = (tid < 8) ? redm[tid] : -INFINITY;
        #pragma unroll
        for (int off = 4; off; off >>= 1) m2 = fmaxf(m2, __shfl_xor_sync(0xffffffffu, m2, off));
        if (tid == 0) redm[0] = m2;
    }
    __syncthreads();
    float m = redm[0];
    float s = 0.f;
    #pragma unroll
    for (int i = 0; i < 4; i++) { vals[i] = expf(vals[i] - m); s += vals[i]; }
    #pragma unroll
    for (int off = 16; off; off >>= 1) s += __shfl_xor_sync(0xffffffffu, s, off);
    __shared__ float reds[8];
    if ((tid & 31) == 0) reds[tid >> 5] = s;
    __syncthreads();
    if (tid < 32) {
        float s2 = (tid < 8) ? reds[tid] : 0.f;
        #pragma unroll
        for (int off = 4; off; off >>= 1) s2 += __shfl_xor_sync(0xffffffffu, s2, off);
        if (tid == 0) reds[0] = s2;
    }
    __syncthreads();
    float inv = 1.f / reds[0];
    size_t base = (size_t)blockIdx.x * S_;
    #pragma unroll
    for (int i = 0; i < 4; i++) {
        int j = tid + i*256;
        if (j < bound) split1(vals[i] * inv, oh[base+j], ol[base+j]);
    }
}

// ---------------- bf16x3 GEMM on pre-split operands ----------------
enum { EPI_NONE = 0, EPI_BIAS_RES = 2, EPI_RES = 3, EPI_SCORES = 4,
       EPI_SPLIT = 6, EPI_QKV = 8, EPI_SWIGLU = 9 };

__device__ __forceinline__ void mma_bf16(float* d, const uint32_t* a, const uint32_t* b) {
    asm volatile(
        "mma.sync.aligned.m16n8k16.row.col.f32.bf16.bf16.f32 "
        "{%0,%1,%2,%3}, {%4,%5,%6,%7}, {%8,%9}, {%0,%1,%2,%3};\n"
        : "+f"(d[0]), "+f"(d[1]), "+f"(d[2]), "+f"(d[3])
        : "r"(a[0]), "r"(a[1]), "r"(a[2]), "r"(a[3]),
          "r"(b[0]), "r"(b[1]));
}

#define CP_ASYNC16(dst, src) \
    asm volatile("cp.async.cg.shared.global [%0], [%1], 16;" :: "r"(dst), "l"(src))
#define CP_COMMIT() asm volatile("cp.async.commit_group;" ::: "memory")
#define CP_WAIT0()  asm volatile("cp.async.wait_group 0;"  ::: "memory")

// A: bf16 [M,K] row-major (hi+lo).  B bf16 [N,K] row-major (NT). cp.async pipeline.
template<int BM, int BN, int BK, int WM, int WN, int EPI, bool TRIMK, int MINB>
__global__ __launch_bounds__((BM/WM)*(BN/WN)*32, MINB)
void gemm_tc(const bf16* __restrict__ Agh, const bf16* __restrict__ Agl,
             const bf16* __restrict__ Bgh, const bf16* __restrict__ Bgl,
             float* __restrict__ C, bf16* __restrict__ Oh, bf16* __restrict__ Ol,
             const float* __restrict__ bias,
             int M, int N, int K, int lda, int ldb, int ldc,
             int zinner,
             long long sAo, long long sAi,
             long long sBo, long long sBi,
             long long sCo, long long sCi,
             float scale)
{
    constexpr int WARPS_N = BN/WN;
    constexpr int THREADS = (BM/WM)*(BN/WN)*32;
    constexpr int MT = WM/16;
    constexpr int NT = WN/8;
    constexpr int SP = BK/2 + 4;
    constexpr int SZA = BM*SP;
    constexpr int SZB = BN*SP;
    constexpr int STAGE = 2*SZA + 2*SZB;
    constexpr int NCA = (BM*BK/8)/THREADS;
    constexpr int NCB = (BN*BK/8)/THREADS;

    extern __shared__ uint32_t smem_u[];

    const int tid = threadIdx.x;
    const int z  = blockIdx.z;
    const int zo = z / zinner, zi = z % zinner;
    const bf16* Abh = Agh + zo*sAo + zi*sAi;
    const bf16* Abl = Agl + zo*sAo + zi*sAi;
    const bf16* Bbh = Bgh + zo*sBo + zi*sBi;
    const bf16* Bbl = Bgl + zo*sBo + zi*sBi;
    float* Cb  = C  ? (C  + zo*sCo + zi*sCi) : nullptr;
    bf16*  Ohb = Oh ? (Oh + zo*sCo + zi*sCi) : nullptr;
    bf16*  Olb = Ol ? (Ol + zo*sCo + zi*sCi) : nullptr;
    const int m0 = blockIdx.y * BM;
    const int n0 = blockIdx.x * BN;

    if (EPI == EPI_SCORES && n0 >= m0 + BM) return;

    const int warp = tid >> 5;
    const int lane = tid & 31;
    const int g = lane >> 2;
    const int c = lane & 3;
    const int wn = warp % WARPS_N;
    const int wm = warp / WARPS_N;

    float acc[MT][NT][4];
    #pragma unroll
    for (int i = 0; i < MT; i++)
        #pragma unroll
        for (int j = 0; j < NT; j++)
            #pragma unroll
            for (int r = 0; r < 4; r++) acc[i][j][r] = 0.f;

    const int Kend = TRIMK ? min(K, m0 + BM) : K;
    const int nk = Kend / BK;

    const uint32_t smb = (uint32_t)__cvta_generic_to_shared(smem_u);
    auto cp_tile = [&](int kt, int s) {
        const uint32_t Ah = smb + s*STAGE*4;
        const uint32_t Al = Ah + SZA*4;
        const uint32_t Bh = Al + SZA*4;
        const uint32_t Bl = Bh + SZB*4;
        #pragma unroll
        for (int i = 0; i < NCA; i++) {
            int f  = tid + i*THREADS;
            int r  = f / (BK/8);
            int c8 = f % (BK/8);
            size_t   go = (size_t)(m0+r)*lda + kt + c8*8;
            uint32_t so = (uint32_t)(r*SP + c8*4)*4;
            CP_ASYNC16(Ah + so, Abh + go);
            CP_ASYNC16(Al + so, Abl + go);
        }
        #pragma unroll
        for (int i = 0; i < NCB; i++) {
            int f  = tid + i*THREADS;
            int r  = f / (BK/8);
            int c8 = f % (BK/8);
            size_t   go = (size_t)(n0+r)*ldb + kt + c8*8;
            uint32_t so = (uint32_t)(r*SP + c8*4)*4;
            CP_ASYNC16(Bh + so, Bbh + go);
            CP_ASYNC16(Bl + so, Bbl + go);
        }
        CP_COMMIT();
    };

    auto compute_stage = [&](int cur) {
        const uint32_t* Ah = smem_u + cur*STAGE;
        const uint32_t* Al = Ah + SZA;
        const uint32_t* Bh = Al + SZA;
        const uint32_t* Bl = Bh + SZB;
        #pragma unroll
        for (int ks = 0; ks < BK; ks += 16) {
            const int kp = ks >> 1;
            uint32_t ah[MT][4], al[MT][4], bh[NT][2], bl[NT][2];
            #pragma unroll
            for (int i = 0; i < MT; i++) {
                int mr = wm*WM + i*16 + g;
                ah[i][0] = Ah[mr*SP     + kp + c];   al[i][0] = Al[mr*SP     + kp + c];
                ah[i][1] = Ah[(mr+8)*SP + kp + c];   al[i][1] = Al[(mr+8)*SP + kp + c];
                ah[i][2] = Ah[mr*SP     + kp + c+4]; al[i][2] = Al[mr*SP     + kp + c+4];
                ah[i][3] = Ah[(mr+8)*SP + kp + c+4]; al[i][3] = Al[(mr+8)*SP + kp + c+4];
            }
            #pragma unroll
            for (int j = 0; j < NT; j++) {
                int nr = wn*WN + j*8 + g;
                bh[j][0] = Bh[nr*SP + kp + c];   bl[j][0] = Bl[nr*SP + kp + c];
                bh[j][1] = Bh[nr*SP + kp + c+4]; bl[j][1] = Bl[nr*SP + kp + c+4];
            }
            #pragma unroll
            for (int i = 0; i < MT; i++)
                #pragma unroll
                for (int j = 0; j < NT; j++)
                    mma_bf16(acc[i][j], ah[i], bh[j]);
            #pragma unroll
            for (int i = 0; i < MT; i++)
                #pragma unroll
                for (int j = 0; j < NT; j++)
                    mma_bf16(acc[i][j], ah[i], bl[j]);
            #pragma unroll
            for (int i = 0; i < MT; i++)
                #pragma unroll
                for (int j = 0; j < NT; j++)
                    mma_bf16(acc[i][j], al[i], bh[j]);
        }
    };

    cp_tile(0, 0);
    CP_WAIT0();
    __syncthreads();

    for (int t = 0; t < nk; t++) {
        const int cur = t & 1;
        if (t + 1 < nk) cp_tile((t+1)*BK, cur ^ 1);
        compute_stage(cur);
        if (t + 1 < nk) CP_WAIT0();
        __syncthreads();
    }

    #pragma unroll
    for (int i = 0; i < MT; i++) {
        #pragma unroll
        for (int j = 0; j < NT; j++) {
            int n = n0 + wn*WN + j*8 + 2*c;
            #pragma unroll
            for (int rr = 0; rr < 2; rr++) {
                int m = m0 + wm*WM + i*16 + g + rr*8;
                float v0 = acc[i][j][rr*2 + 0];
                float v1 = acc[i][j][rr*2 + 1];
                if (EPI == EPI_QKV) {
                    v0 += bias[n]; v1 += bias[n+1];
                    if (n < 2*D_) {
                        *(float2*)(Cb + (size_t)m*ldc + n) = make_float2(v0, v1);
                    } else {
                        int dg = n - 2*D_;
                        int hh = dg >> 6, dd = dg & 63;
                        int b  = m >> 10, s = m & 1023;
                        size_t o0 = (((size_t)b*H_ + hh)*DH_ + dd)*S_ + s;
                        split1(v0, Oh[o0],      Ol[o0]);
                        split1(v1, Oh[o0+S_],   Ol[o0+S_]);
                    }
                    continue;
                }
                if (EPI == EPI_SWIGLU) {
                    // v0 = gate_j, v1 = up_j (interleaved weight rows); output col = n/2
                    float sw = v0 / (1.f + expf(-v0)) * v1;
                    size_t oo = (size_t)m*(ldc >> 1) + (n >> 1);
                    split1(sw, Ohb[oo], Olb[oo]);
                    continue;
                }
                size_t off = (size_t)m*ldc + n;
                if (EPI == EPI_BIAS_RES) {
                    v0 += bias[n]   + Cb[off];
                    v1 += bias[n+1] + Cb[off+1];
                    *(float2*)(Cb + off) = make_float2(v0, v1);
                } else if (EPI == EPI_RES) {
                    v0 += Cb[off]; v1 += Cb[off+1];
                    *(float2*)(Cb + off) = make_float2(v0, v1);
                } else if (EPI == EPI_SCORES) {
                    *(float2*)(Cb + off) = make_float2(v0*scale, v1*scale);
                } else if (EPI == EPI_NONE) {
                    *(float2*)(Cb + off) = make_float2(v0, v1);
                } else if (EPI == EPI_SPLIT) {
                    split_store2(Ohb, Olb, off, v0, v1);
                }
            }
        }
    }
}

// ---------------- host ----------------
template<int BM, int BN, int BK>
constexpr int smem_bytes() {
    return 2 * (2*BM*(BK/2+4) + 2*BN*(BK/2+4)) * 4;
}

extern "C" void kernel_launch(void* const* d_in, const int* in_sizes, int n_in,
                              void* d_out, int out_size) {
    const int*   x      = (const int*)  d_in[0];
    const float* emb    = (const float*)d_in[1];
    const float* wq     = (const float*)d_in[2];
    const float* bq     = (const float*)d_in[3];
    const float* wk     = (const float*)d_in[4];
    const float* bk     = (const float*)d_in[5];
    const float* wv     = (const float*)d_in[6];
    const float* bv     = (const float*)d_in[7];
    const float* wo     = (const float*)d_in[8];
    const float* bo     = (const float*)d_in[9];
    const float* w_gate = (const float*)d_in[10];
    const float* w_up   = (const float*)d_in[11];
    const float* w_down = (const float*)d_in[12];
    const float* ln1    = (const float*)d_in[13];
    const float* ln2    = (const float*)d_in[14];
    const float* norm_w = (const float*)d_in[15];
    float* out = (float*)d_out;

    float *h, *qk, *att, *bqkv;
    cudaGetSymbolAddress((void**)&h,    g_h);
    cudaGetSymbolAddress((void**)&qk,   g_qk);
    cudaGetSymbolAddress((void**)&att,  g_att);
    cudaGetSymbolAddress((void**)&bqkv, g_bqkv);

    bf16 *wqkvh,*wqkvl,*woh,*wol,*wguh,*wgul,*wdh,*wdl,*embh,*embl;
    bf16 *hnh,*hnl,*qh,*ql,*kh,*kl,*vth,*vtl,*yh,*yl,*gah,*gal,*atth,*attl;
    cudaGetSymbolAddress((void**)&wqkvh, s_wqkv_h); cudaGetSymbolAddress((void**)&wqkvl, s_wqkv_l);
    cudaGetSymbolAddress((void**)&woh, s_wo_h);  cudaGetSymbolAddress((void**)&wol, s_wo_l);
    cudaGetSymbolAddress((void**)&wguh, s_wgu_h); cudaGetSymbolAddress((void**)&wgul, s_wgu_l);
    cudaGetSymbolAddress((void**)&wdh, s_wd_h);  cudaGetSymbolAddress((void**)&wdl, s_wd_l);
    cudaGetSymbolAddress((void**)&embh, s_emb_h); cudaGetSymbolAddress((void**)&embl, s_emb_l);
    cudaGetSymbolAddress((void**)&hnh, s_hn_h);  cudaGetSymbolAddress((void**)&hnl, s_hn_l);
    cudaGetSymbolAddress((void**)&qh,  s_q_h);   cudaGetSymbolAddress((void**)&ql,  s_q_l);
    cudaGetSymbolAddress((void**)&kh,  s_k_h);   cudaGetSymbolAddress((void**)&kl,  s_k_l);
    cudaGetSymbolAddress((void**)&vth, s_vt_h);  cudaGetSymbolAddress((void**)&vtl, s_vt_l);
    cudaGetSymbolAddress((void**)&yh,  s_y_h);   cudaGetSymbolAddress((void**)&yl,  s_y_l);
    cudaGetSymbolAddress((void**)&gah, s_ga_h);  cudaGetSymbolAddress((void**)&gal, s_ga_l);
    cudaGetSymbolAddress((void**)&atth, s_att_h); cudaGetSymbolAddress((void**)&attl, s_att_l);

    constexpr int SM_S = smem_bytes<128,128,32>();   // 81920
    constexpr int SM_P = smem_bytes<128,64,32>();    // 61440

    cudaFuncSetAttribute(gemm_tc<128,64,32,64,32,EPI_QKV,false,3>,      cudaFuncAttributeMaxDynamicSharedMemorySize, SM_P);
    cudaFuncSetAttribute(gemm_tc<128,128,32,64,32,EPI_SCORES,false,2>,  cudaFuncAttributeMaxDynamicSharedMemorySize, SM_S);
    cudaFuncSetAttribute(gemm_tc<128,64,32,64,32,EPI_SPLIT,true,3>,     cudaFuncAttributeMaxDynamicSharedMemorySize, SM_P);
    cudaFuncSetAttribute(gemm_tc<128,64,32,64,32,EPI_BIAS_RES,false,3>, cudaFuncAttributeMaxDynamicSharedMemorySize, SM_P);
    cudaFuncSetAttribute(gemm_tc<128,128,32,64,32,EPI_SWIGLU,false,2>,  cudaFuncAttributeMaxDynamicSharedMemorySize, SM_S);
    cudaFuncSetAttribute(gemm_tc<128,64,32,64,32,EPI_RES,false,3>,      cudaFuncAttributeMaxDynamicSharedMemorySize, SM_P);
    cudaFuncSetAttribute(gemm_tc<128,128,32,64,32,EPI_NONE,false,2>,    cudaFuncAttributeMaxDynamicSharedMemorySize, SM_S);

    // ---- prep ----
    auto split_launch = [](const float* src, bf16* dh, bf16* dl, size_t n) {
        int n4 = (int)(n / 4);
        split_kernel<<<(n4 + 255)/256, 256>>>(src, dh, dl, n4);
    };
    int nw4 = L_*D_*D_/4;
    split_pack_kernel<<<(nw4+255)/256, 256>>>(wq, wqkvh, wqkvl, 0);
    split_pack_kernel<<<(nw4+255)/256, 256>>>(wk, wqkvh, wqkvl, D_);
    split_pack_kernel<<<(nw4+255)/256, 256>>>(wv, wqkvh, wqkvl, 2*D_);
    pack_bias_kernel<<<(L_*3*D_+255)/256, 256>>>(bq, bk, bv, bqkv);
    split_launch(wo, woh, wol, (size_t)L_*D_*D_);
    int ngu4 = L_*DI_*D_/4;
    split_pack_gu_kernel<<<(ngu4+255)/256, 256>>>(w_gate, w_up, wguh, wgul);
    split_launch(w_down, wdh, wdl, (size_t)L_*D_*DI_);
    split_launch(emb, embh, embl, (size_t)V_*D_);

    embed_kernel<<<T_*D_/4/256, 256>>>(x, emb, h);
    rope_cache_kernel<<<(S_*32 + 255)/256, 256>>>();

    const dim3 gqkv(3*D_/64, T_/128, 1);    // 48 x 16, 128 thr
    const dim3 gp(D_/64,   T_/128, 1);      // 16 x 16, 128 thr
    const dim3 ggu(2*DI_/128, T_/128, 1);   // 64 x 16, 256 thr
    const dim3 gs(S_/128, S_/128, B_*H_);   // 256 thr
    const dim3 ga(1,      S_/128, B_*H_);   // 128 thr

    for (int l = 0; l < L_; l++) {
        rmsnorm_kernel<<<T_, 256>>>(h, ln1 + (size_t)l*D_, hnh, hnl);

        gemm_tc<128,64,32,64,32,EPI_QKV,false,3><<<gqkv,128,SM_P>>>(
            hnh, hnl, wqkvh + (size_t)l*3*D_*D_, wqkvl + (size_t)l*3*D_*D_,
            qk, vth, vtl, bqkv + (size_t)l*3*D_,
            T_, 3*D_, D_, D_, D_, 2*D_, 1, 0,0,0,0,0,0, 0.f);

        rope_kernel<<<T_*H_*32/256, 256>>>();

        gemm_tc<128,128,32,64,32,EPI_SCORES,false,2><<<gs,256,SM_S>>>(
            qh, ql, kh, kl, att, nullptr, nullptr, nullptr,
            S_, S_, DH_, D_, D_, S_,
            H_,
            (long long)S_*D_, (long long)DH_,
            (long long)S_*D_, (long long)DH_,
            (long long)H_*S_*S_, (long long)S_*S_,
            0.125f);

        softmax_kernel<<<B_*H_*S_, 256>>>(att, atth, attl);

        gemm_tc<128,64,32,64,32,EPI_SPLIT,true,3><<<ga,128,SM_P>>>(
            atth, attl, vth, vtl, nullptr, yh, yl, nullptr,
            S_, DH_, S_, S_, S_, D_,
            H_,
            (long long)H_*S_*S_, (long long)S_*S_,
            (long long)H_*DH_*S_, (long long)DH_*S_,
            (long long)S_*D_, (long long)DH_,
            0.f);

        gemm_tc<128,64,32,64,32,EPI_BIAS_RES,false,3><<<gp,128,SM_P>>>(
            yh, yl, woh + (size_t)l*D_*D_, wol + (size_t)l*D_*D_,
            h, nullptr, nullptr, bo + (size_t)l*D_,
            T_, D_, D_, D_, D_, D_, 1, 0,0,0,0,0,0, 0.f);

        rmsnorm_kernel<<<T_, 256>>>(h, ln2 + (size_t)l*D_, hnh, hnl);

        // fused gate+up+silu: N = 2*DI interleaved; output [T, DI] split bf16
        gemm_tc<128,128,32,64,32,EPI_SWIGLU,false,2><<<ggu,256,SM_S>>>(
            hnh, hnl, wguh + (size_t)l*2*DI_*D_, wgul + (size_t)l*2*DI_*D_,
            nullptr, gah, gal, nullptr,
            T_, 2*DI_, D_, D_, D_, 2*DI_, 1, 0,0,0,0,0,0, 0.f);

        gemm_tc<128,64,32,64,32,EPI_RES,false,3><<<gp,128,SM_P>>>(
            gah, gal, wdh + (size_t)l*D_*DI_, wdl + (size_t)l*D_*DI_,
            h, nullptr, nullptr, nullptr,
            T_, D_, DI_, DI_, DI_, D_, 1, 0,0,0,0,0,0, 0.f);
    }

    rmsnorm_kernel<<<T_, 256>>>(h, norm_w, hnh, hnl);

    const dim3 gl(V_/128, T_/128, 1);
    gemm_tc<128,128,32,64,32,EPI_NONE,false,2><<<gl,256,SM_S>>>(
        hnh, hnl, embh, embl, out, nullptr, nullptr, nullptr,
        T_, V_, D_, D_, D_, V_, 1, 0,0,0,0,0,0, 0.f);
}

// round 13
// speedup vs baseline: 1.4452x; 1.0826x over previous
#include <cuda_runtime.h>
#include <cuda_bf16.h>
#include <cstdint>
#include <math.h>

#define L_  8
#define D_  1024
#define H_  16
#define DH_ 64
#define DI_ 4096
#define V_  32000
#define B_  2
#define S_  1024
#define T_  (B_*S_)

typedef __nv_bfloat16 bf16;

// ---------------- fp32 scratch ----------------
__device__ float g_h   [T_*D_];
__device__ float g_qk  [T_*2048];
__device__ float g_cos [S_*32];
__device__ float g_sin [S_*32];
__device__ float g_bqkv[L_*3*D_];

// ---------------- split bf16 scratch (hi/lo) ----------------
__device__ bf16 s_wqkv_h[L_*3*D_*D_], s_wqkv_l[L_*3*D_*D_];
__device__ bf16 s_wo_h[L_*D_*D_],   s_wo_l[L_*D_*D_];
__device__ bf16 s_wgu_h[(size_t)L_*2*DI_*D_], s_wgu_l[(size_t)L_*2*DI_*D_];
__device__ bf16 s_wd_h[L_*D_*DI_],  s_wd_l[L_*D_*DI_];
__device__ bf16 s_emb_h[V_*D_],     s_emb_l[V_*D_];
__device__ bf16 s_hn_h[T_*D_],      s_hn_l[T_*D_];
__device__ bf16 s_q_h [T_*D_],      s_q_l [T_*D_];
__device__ bf16 s_k_h [T_*D_],      s_k_l [T_*D_];
__device__ bf16 s_vt_h[T_*D_],      s_vt_l[T_*D_];     // [b][h][d][s]
__device__ bf16 s_y_h [T_*D_],      s_y_l [T_*D_];
__device__ bf16 s_ga_h[T_*DI_],     s_ga_l[T_*DI_];

// ---------------- helpers ----------------
__device__ __forceinline__ void split1(float v, bf16& h, bf16& l) {
    h = __float2bfloat16(v);
    l = __float2bfloat16(v - __bfloat162float(h));
}

__device__ __forceinline__ void split_store2(bf16* H, bf16* Lo, size_t off, float v0, float v1) {
    bf16 h0, l0, h1, l1;
    split1(v0, h0, l0);
    split1(v1, h1, l1);
    __nv_bfloat162 th; th.x = h0; th.y = h1;
    __nv_bfloat162 tl; tl.x = l0; tl.y = l1;
    *(__nv_bfloat162*)(H  + off) = th;
    *(__nv_bfloat162*)(Lo + off) = tl;
}

// pack two fp32 into (hi bf16x2, lo bf16x2) registers
__device__ __forceinline__ void splitpack2(float a, float b, uint32_t& h, uint32_t& l) {
    bf16 ha, la, hb, lb;
    split1(a, ha, la);
    split1(b, hb, lb);
    h = ((uint32_t)__bfloat16_as_ushort(hb) << 16) | __bfloat16_as_ushort(ha);
    l = ((uint32_t)__bfloat16_as_ushort(lb) << 16) | __bfloat16_as_ushort(la);
}

__global__ void split_kernel(const float* __restrict__ x, bf16* __restrict__ h,
                             bf16* __restrict__ l, int n4) {
    int i = blockIdx.x * blockDim.x + threadIdx.x;
    if (i >= n4) return;
    float4 v = ((const float4*)x)[i];
    bf16 h0,l0,h1,l1,h2,l2,h3,l3;
    split1(v.x, h0, l0); split1(v.y, h1, l1);
    split1(v.z, h2, l2); split1(v.w, h3, l3);
    ((ushort4*)h)[i] = make_ushort4(__bfloat16_as_ushort(h0), __bfloat16_as_ushort(h1),
                                    __bfloat16_as_ushort(h2), __bfloat16_as_ushort(h3));
    ((ushort4*)l)[i] = make_ushort4(__bfloat16_as_ushort(l0), __bfloat16_as_ushort(l1),
                                    __bfloat16_as_ushort(l2), __bfloat16_as_ushort(l3));
}

__global__ void split_pack_kernel(const float* __restrict__ x, bf16* __restrict__ h,
                                  bf16* __restrict__ l, int row_off) {
    int i = blockIdx.x * blockDim.x + threadIdx.x;
    if (i >= L_*D_*D_/4) return;
    int lay = i / (D_*D_/4);
    int rem = i % (D_*D_/4);
    int r   = rem / (D_/4);
    int c4  = rem % (D_/4);
    float4 v = ((const float4*)x)[i];
    int d4 = lay*(3*D_*D_/4) + (row_off + r)*(D_/4) + c4;
    bf16 h0,l0,h1,l1,h2,l2,h3,l3;
    split1(v.x, h0, l0); split1(v.y, h1, l1);
    split1(v.z, h2, l2); split1(v.w, h3, l3);
    ((ushort4*)h)[d4] = make_ushort4(__bfloat16_as_ushort(h0), __bfloat16_as_ushort(h1),
                                     __bfloat16_as_ushort(h2), __bfloat16_as_ushort(h3));
    ((ushort4*)l)[d4] = make_ushort4(__bfloat16_as_ushort(l0), __bfloat16_as_ushort(l1),
                                     __bfloat16_as_ushort(l2), __bfloat16_as_ushort(l3));
}

__global__ void split_pack_gu_kernel(const float* __restrict__ wg, const float* __restrict__ wu,
                                     bf16* __restrict__ h, bf16* __restrict__ l) {
    int i = blockIdx.x * blockDim.x + threadIdx.x;
    if (i >= L_*DI_*D_/4) return;
    int lay = i / (DI_*D_/4);
    int rem = i % (DI_*D_/4);
    int r   = rem / (D_/4);
    int c4  = rem % (D_/4);
    float4 vg = ((const float4*)wg)[i];
    float4 vu = ((const float4*)wu)[i];
    size_t base = (size_t)lay*(2*DI_*D_/4);
    size_t dg = base + (size_t)(2*r)  *(D_/4) + c4;
    size_t du = base + (size_t)(2*r+1)*(D_/4) + c4;
    bf16 h0,l0,h1,l1,h2,l2,h3,l3;
    split1(vg.x, h0, l0); split1(vg.y, h1, l1);
    split1(vg.z, h2, l2); split1(vg.w, h3, l3);
    ((ushort4*)h)[dg] = make_ushort4(__bfloat16_as_ushort(h0), __bfloat16_as_ushort(h1),
                                     __bfloat16_as_ushort(h2), __bfloat16_as_ushort(h3));
    ((ushort4*)l)[dg] = make_ushort4(__bfloat16_as_ushort(l0), __bfloat16_as_ushort(l1),
                                     __bfloat16_as_ushort(l2), __bfloat16_as_ushort(l3));
    split1(vu.x, h0, l0); split1(vu.y, h1, l1);
    split1(vu.z, h2, l2); split1(vu.w, h3, l3);
    ((ushort4*)h)[du] = make_ushort4(__bfloat16_as_ushort(h0), __bfloat16_as_ushort(h1),
                                     __bfloat16_as_ushort(h2), __bfloat16_as_ushort(h3));
    ((ushort4*)l)[du] = make_ushort4(__bfloat16_as_ushort(l0), __bfloat16_as_ushort(l1),
                                     __bfloat16_as_ushort(l2), __bfloat16_as_ushort(l3));
}

__global__ void pack_bias_kernel(const float* __restrict__ bq, const float* __restrict__ bk,
                                 const float* __restrict__ bv, float* __restrict__ dst) {
    int i = blockIdx.x * blockDim.x + threadIdx.x;
    if (i >= L_*3*D_) return;
    int lay = i / (3*D_);
    int j   = i % (3*D_);
    float v = (j < D_) ? bq[lay*D_ + j]
            : (j < 2*D_) ? bk[lay*D_ + j - D_]
            : bv[lay*D_ + j - 2*D_];
    dst[i] = v;
}

// ---------------- small kernels ----------------
__global__ void embed_kernel(const int* __restrict__ x, const float* __restrict__ emb,
                             float* __restrict__ h) {
    int i = blockIdx.x * blockDim.x + threadIdx.x;
    int t = i / (D_/4);
    int c = i % (D_/4);
    float4 v = *(const float4*)(emb + (size_t)x[t]*D_ + c*4);
    *(float4*)(h + (size_t)t*D_ + c*4) = v;
}

__global__ void rope_cache_kernel() {
    int i = blockIdx.x * blockDim.x + threadIdx.x;
    if (i >= S_*32) return;
    int s = i / 32, j = i % 32;
    double inv = pow(10000.0, -(double)j / 32.0);
    double ph = (double)s * inv;
    g_cos[i] = (float)cos(ph);
    g_sin[i] = (float)sin(ph);
}

__global__ void rope_kernel() {
    int i = blockIdx.x * blockDim.x + threadIdx.x;
    int t = i >> 9;
    int r = i & 511;
    int h = r >> 5, d = r & 31;
    int s = t & (S_-1);
    float c  = g_cos[s*32 + d];
    float sn = g_sin[s*32 + d];
    size_t qkb = (size_t)t*2048 + h*DH_ + d;
    size_t ob  = (size_t)t*D_   + h*DH_ + d;
    float a, b, r0, r1;
    a = g_qk[qkb]; b = g_qk[qkb+32];
    r0 = a*c - b*sn;  r1 = b*c + a*sn;
    split1(r0, s_q_h[ob],    s_q_l[ob]);
    split1(r1, s_q_h[ob+32], s_q_l[ob+32]);
    a = g_qk[qkb+1024]; b = g_qk[qkb+1024+32];
    r0 = a*c - b*sn;  r1 = b*c + a*sn;
    split1(r0, s_k_h[ob],    s_k_l[ob]);
    split1(r1, s_k_h[ob+32], s_k_l[ob+32]);
}

__global__ void rmsnorm_kernel(const float* __restrict__ x, const float* __restrict__ w,
                               bf16* __restrict__ oh, bf16* __restrict__ ol) {
    int t = blockIdx.x;
    int tid = threadIdx.x;
    const float* xp = x + (size_t)t*D_;
    float v[4];
    float s = 0.f;
    #pragma unroll
    for (int i = 0; i < 4; i++) { v[i] = xp[tid + i*256]; s += v[i]*v[i]; }
    #pragma unroll
    for (int off = 16; off; off >>= 1) s += __shfl_xor_sync(0xffffffffu, s, off);
    __shared__ float red[8];
    if ((tid & 31) == 0) red[tid >> 5] = s;
    __syncthreads();
    if (tid < 32) {
        float s2 = (tid < 8) ? red[tid] : 0.f;
        #pragma unroll
        for (int off = 4; off; off >>= 1) s2 += __shfl_xor_sync(0xffffffffu, s2, off);
        if (tid == 0) red[0] = s2;
    }
    __syncthreads();
    float r = rsqrtf(red[0] * (1.f/(float)D_) + 1e-6f);
    size_t base = (size_t)t*D_;
    #pragma unroll
    for (int i = 0; i < 4; i++) {
        int idx = tid + i*256;
        split1(w[idx] * v[i] * r, oh[base+idx], ol[base+idx]);
    }
}

// ---------------- bf16x3 GEMM on pre-split operands ----------------
enum { EPI_NONE = 0, EPI_BIAS_RES = 2, EPI_RES = 3,
       EPI_QKV = 8, EPI_SWIGLU = 9 };

__device__ __forceinline__ void mma_bf16(float* d, const uint32_t* a, const uint32_t* b) {
    asm volatile(
        "mma.sync.aligned.m16n8k16.row.col.f32.bf16.bf16.f32 "
        "{%0,%1,%2,%3}, {%4,%5,%6,%7}, {%8,%9}, {%0,%1,%2,%3};\n"
        : "+f"(d[0]), "+f"(d[1]), "+f"(d[2]), "+f"(d[3])
        : "r"(a[0]), "r"(a[1]), "r"(a[2]), "r"(a[3]),
          "r"(b[0]), "r"(b[1]));
}

#define CP_ASYNC16(dst, src) \
    asm volatile("cp.async.cg.shared.global [%0], [%1], 16;" :: "r"(dst), "l"(src))
#define CP_COMMIT() asm volatile("cp.async.commit_group;" ::: "memory")
#define CP_WAIT0()  asm volatile("cp.async.wait_group 0;"  ::: "memory")

template<int BM, int BN, int BK, int WM, int WN, int EPI, int MINB>
__global__ __launch_bounds__((BM/WM)*(BN/WN)*32, MINB)
void gemm_tc(const bf16* __restrict__ Agh, const bf16* __restrict__ Agl,
             const bf16* __restrict__ Bgh, const bf16* __restrict__ Bgl,
             float* __restrict__ C, bf16* __restrict__ Oh, bf16* __restrict__ Ol,
             const float* __restrict__ bias,
             int M, int N, int K, int lda, int ldb, int ldc)
{
    constexpr int WARPS_N = BN/WN;
    constexpr int THREADS = (BM/WM)*(BN/WN)*32;
    constexpr int MT = WM/16;
    constexpr int NT = WN/8;
    constexpr int SP = BK/2 + 4;
    constexpr int SZA = BM*SP;
    constexpr int SZB = BN*SP;
    constexpr int STAGE = 2*SZA + 2*SZB;
    constexpr int NCA = (BM*BK/8)/THREADS;
    constexpr int NCB = (BN*BK/8)/THREADS;

    extern __shared__ uint32_t smem_u[];

    const int tid = threadIdx.x;
    const int m0 = blockIdx.y * BM;
    const int n0 = blockIdx.x * BN;

    const int warp = tid >> 5;
    const int lane = tid & 31;
    const int g = lane >> 2;
    const int c = lane & 3;
    const int wn = warp % WARPS_N;
    const int wm = warp / WARPS_N;

    float acc[MT][NT][4];
    #pragma unroll
    for (int i = 0; i < MT; i++)
        #pragma unroll
        for (int j = 0; j < NT; j++)
            #pragma unroll
            for (int r = 0; r < 4; r++) acc[i][j][r] = 0.f;

    const int nk = K / BK;

    const uint32_t smb = (uint32_t)__cvta_generic_to_shared(smem_u);
    auto cp_tile = [&](int kt, int s) {
        const uint32_t Ah = smb + s*STAGE*4;
        const uint32_t Al = Ah + SZA*4;
        const uint32_t Bh = Al + SZA*4;
        const uint32_t Bl = Bh + SZB*4;
        #pragma unroll
        for (int i = 0; i < NCA; i++) {
            int f  = tid + i*THREADS;
            int r  = f / (BK/8);
            int c8 = f % (BK/8);
            size_t   go = (size_t)(m0+r)*lda + kt + c8*8;
            uint32_t so = (uint32_t)(r*SP + c8*4)*4;
            CP_ASYNC16(Ah + so, Agh + go);
            CP_ASYNC16(Al + so, Agl + go);
        }
        #pragma unroll
        for (int i = 0; i < NCB; i++) {
            int f  = tid + i*THREADS;
            int r  = f / (BK/8);
            int c8 = f % (BK/8);
            size_t   go = (size_t)(n0+r)*ldb + kt + c8*8;
            uint32_t so = (uint32_t)(r*SP + c8*4)*4;
            CP_ASYNC16(Bh + so, Bgh + go);
            CP_ASYNC16(Bl + so, Bgl + go);
        }
        CP_COMMIT();
    };

    auto compute_stage = [&](int cur) {
        const uint32_t* Ah = smem_u + cur*STAGE;
        const uint32_t* Al = Ah + SZA;
        const uint32_t* Bh = Al + SZA;
        const uint32_t* Bl = Bh + SZB;
        #pragma unroll
        for (int ks = 0; ks < BK; ks += 16) {
            const int kp = ks >> 1;
            uint32_t ah[MT][4], al[MT][4], bh[NT][2], bl[NT][2];
            #pragma unroll
            for (int i = 0; i < MT; i++) {
                int mr = wm*WM + i*16 + g;
                ah[i][0] = Ah[mr*SP     + kp + c];   al[i][0] = Al[mr*SP     + kp + c];
                ah[i][1] = Ah[(mr+8)*SP + kp + c];   al[i][1] = Al[(mr+8)*SP + kp + c];
                ah[i][2] = Ah[mr*SP     + kp + c+4]; al[i][2] = Al[mr*SP     + kp + c+4];
                ah[i][3] = Ah[(mr+8)*SP + kp + c+4]; al[i][3] = Al[(mr+8)*SP + kp + c+4];
            }
            #pragma unroll
            for (int j = 0; j < NT; j++) {
                int nr = wn*WN + j*8 + g;
                bh[j][0] = Bh[nr*SP + kp + c];   bl[j][0] = Bl[nr*SP + kp + c];
                bh[j][1] = Bh[nr*SP + kp + c+4]; bl[j][1] = Bl[nr*SP + kp + c+4];
            }
            #pragma unroll
            for (int i = 0; i < MT; i++)
                #pragma unroll
                for (int j = 0; j < NT; j++)
                    mma_bf16(acc[i][j], ah[i], bh[j]);
            #pragma unroll
            for (int i = 0; i < MT; i++)
                #pragma unroll
                for (int j = 0; j < NT; j++)
                    mma_bf16(acc[i][j], ah[i], bl[j]);
            #pragma unroll
            for (int i = 0; i < MT; i++)
                #pragma unroll
                for (int j = 0; j < NT; j++)
                    mma_bf16(acc[i][j], al[i], bh[j]);
        }
    };

    cp_tile(0, 0);
    CP_WAIT0();
    __syncthreads();

    for (int t = 0; t < nk; t++) {
        const int cur = t & 1;
        if (t + 1 < nk) cp_tile((t+1)*BK, cur ^ 1);
        compute_stage(cur);
        if (t + 1 < nk) CP_WAIT0();
        __syncthreads();
    }

    #pragma unroll
    for (int i = 0; i < MT; i++) {
        #pragma unroll
        for (int j = 0; j < NT; j++) {
            int n = n0 + wn*WN + j*8 + 2*c;
            #pragma unroll
            for (int rr = 0; rr < 2; rr++) {
                int m = m0 + wm*WM + i*16 + g + rr*8;
                float v0 = acc[i][j][rr*2 + 0];
                float v1 = acc[i][j][rr*2 + 1];
                if (EPI == EPI_QKV) {
                    v0 += bias[n]; v1 += bias[n+1];
                    if (n < 2*D_) {
                        *(float2*)(C + (size_t)m*ldc + n) = make_float2(v0, v1);
                    } else {
                        int dg = n - 2*D_;
                        int hh = dg >> 6, dd = dg & 63;
                        int b  = m >> 10, s = m & 1023;
                        size_t o0 = (((size_t)b*H_ + hh)*DH_ + dd)*S_ + s;
                        split1(v0, Oh[o0],      Ol[o0]);
                        split1(v1, Oh[o0+S_],   Ol[o0+S_]);
                    }
                    continue;
                }
                if (EPI == EPI_SWIGLU) {
                    float sw = v0 / (1.f + expf(-v0)) * v1;
                    size_t oo = (size_t)m*(ldc >> 1) + (n >> 1);
                    split1(sw, Oh[oo], Ol[oo]);
                    continue;
                }
                size_t off = (size_t)m*ldc + n;
                if (EPI == EPI_BIAS_RES) {
                    v0 += bias[n]   + C[off];
                    v1 += bias[n+1] + C[off+1];
                    *(float2*)(C + off) = make_float2(v0, v1);
                } else if (EPI == EPI_RES) {
                    v0 += C[off]; v1 += C[off+1];
                    *(float2*)(C + off) = make_float2(v0, v1);
                } else if (EPI == EPI_NONE) {
                    *(float2*)(C + off) = make_float2(v0, v1);
                }
            }
        }
    }
}

// ================== flash attention (scores+softmax+attV fused) ==================
// block: 128 threads (4 warps), each warp owns 16 query rows x all 64 key cols.
// grid: (S/64 row blocks, B*H). smem: Q tile + double-buffered K/V tiles, SP=36.
#define FA_SP 36
#define FA_TW (64*FA_SP)                 // words per tile (2304)
#define FA_SMEM ((2*FA_TW + 2*4*FA_TW)*4)  // Qh,Ql + 2 stages x (Kh,Kl,Vh,Vl) = 92160B

__global__ __launch_bounds__(128, 2)
void flash_attn_kernel(float scale)
{
    extern __shared__ uint32_t sm[];
    const int tid  = threadIdx.x;
    const int warp = tid >> 5;
    const int lane = tid & 31;
    const int g = lane >> 2;
    const int c = lane & 3;
    const int mb = blockIdx.x;           // query row block (64 rows)
    const int bh = blockIdx.y;
    const int b  = bh >> 4;              // / H_
    const int hh = bh & 15;              // % H_
    const int m0 = mb * 64;

    const uint32_t smb = (uint32_t)__cvta_generic_to_shared(sm);
    uint32_t* sQh = sm;
    uint32_t* sQl = sm + FA_TW;

    const size_t vbase = (size_t)bh * DH_ * S_;

    // Q tile load (part of first cp.async group)
    #pragma unroll
    for (int i = 0; i < 4; i++) {
        int f = tid + i*128;             // 0..511
        int r = f >> 3, c8 = f & 7;
        size_t go = ((size_t)(b*S_ + m0 + r))*D_ + hh*64 + c8*8;
        uint32_t so = (uint32_t)(r*FA_SP + c8*4)*4;
        CP_ASYNC16(smb + so,             s_q_h + go);
        CP_ASYNC16(smb + FA_TW*4 + so,   s_q_l + go);
    }

    auto cp_kv = [&](int kb, int s) {
        uint32_t kvb = smb + (2*FA_TW + s*4*FA_TW)*4;
        #pragma unroll
        for (int i = 0; i < 4; i++) {
            int f = tid + i*128;
            int r = f >> 3, c8 = f & 7;
            uint32_t so = (uint32_t)(r*FA_SP + c8*4)*4;
            size_t gok = ((size_t)(b*S_ + kb*64 + r))*D_ + hh*64 + c8*8;
            CP_ASYNC16(kvb + so,             s_k_h + gok);
            CP_ASYNC16(kvb + FA_TW*4 + so,   s_k_l + gok);
            size_t gov = vbase + (size_t)r*S_ + kb*64 + c8*8;
            CP_ASYNC16(kvb + 2*FA_TW*4 + so, s_vt_h + gov);
            CP_ASYNC16(kvb + 3*FA_TW*4 + so, s_vt_l + gov);
        }
        CP_COMMIT();
    };

    cp_kv(0, 0);
    CP_WAIT0();
    __syncthreads();

    float m_r[2] = {-INFINITY, -INFINITY};
    float l_r[2] = {0.f, 0.f};
    float Oa[8][4];
    #pragma unroll
    for (int j = 0; j < 8; j++)
        #pragma unroll
        for (int r = 0; r < 4; r++) Oa[j][r] = 0.f;

    const int mr = warp*16 + g;          // local row (rr=0); +8 for rr=1

    for (int kb = 0; kb <= mb; kb++) {
        const int cur = kb & 1;
        if (kb < mb) cp_kv(kb+1, cur ^ 1);

        // ---- S = Q K^T (bf16x3) ----
        float Sa[8][4];
        #pragma unroll
        for (int j = 0; j < 8; j++)
            #pragma unroll
            for (int r = 0; r < 4; r++) Sa[j][r] = 0.f;

        {
            const uint32_t* Bh = sm + 2*FA_TW + cur*4*FA_TW;
            const uint32_t* Bl = Bh + FA_TW;
            #pragma unroll
            for (int ks = 0; ks < 64; ks += 16) {
                const int kp = ks >> 1;
                uint32_t ah[4], al[4], bh[8][2], bl[8][2];
                ah[0] = sQh[mr*FA_SP     + kp + c];   al[0] = sQl[mr*FA_SP     + kp + c];
                ah[1] = sQh[(mr+8)*FA_SP + kp + c];   al[1] = sQl[(mr+8)*FA_SP + kp + c];
                ah[2] = sQh[mr*FA_SP     + kp + c+4]; al[2] = sQl[mr*FA_SP     + kp + c+4];
                ah[3] = sQh[(mr+8)*FA_SP + kp + c+4]; al[3] = sQl[(mr+8)*FA_SP + kp + c+4];
                #pragma unroll
                for (int j = 0; j < 8; j++) {
                    int nr = j*8 + g;
                    bh[j][0] = Bh[nr*FA_SP + kp + c];   bl[j][0] = Bl[nr*FA_SP + kp + c];
                    bh[j][1] = Bh[nr*FA_SP + kp + c+4]; bl[j][1] = Bl[nr*FA_SP + kp + c+4];
                }
                #pragma unroll
                for (int j = 0; j < 8; j++) mma_bf16(Sa[j], ah, bh[j]);
                #pragma unroll
                for (int j = 0; j < 8; j++) mma_bf16(Sa[j], ah, bl[j]);
                #pragma unroll
                for (int j = 0; j < 8; j++) mma_bf16(Sa[j], al, bh[j]);
            }
        }

        // ---- scale + causal mask (diag block only) ----
        #pragma unroll
        for (int j = 0; j < 8; j++)
            #pragma unroll
            for (int r = 0; r < 4; r++) Sa[j][r] *= scale;
        if (kb == mb) {
            #pragma unroll
            for (int j = 0; j < 8; j++) {
                int col = kb*64 + j*8 + 2*c;
                #pragma unroll
                for (int rr = 0; rr < 2; rr++) {
                    int row = m0 + mr + rr*8;
                    if (col     > row) Sa[j][rr*2]   = -INFINITY;
                    if (col + 1 > row) Sa[j][rr*2+1] = -INFINITY;
                }
            }
        }

        // ---- online softmax (per row rr) ----
        #pragma unroll
        for (int rr = 0; rr < 2; rr++) {
            float mx = -INFINITY;
            #pragma unroll
            for (int j = 0; j < 8; j++)
                mx = fmaxf(mx, fmaxf(Sa[j][rr*2], Sa[j][rr*2+1]));
            mx = fmaxf(mx, __shfl_xor_sync(0xffffffffu, mx, 1));
            mx = fmaxf(mx, __shfl_xor_sync(0xffffffffu, mx, 2));
            float mnew  = fmaxf(m_r[rr], mx);
            float alpha = expf(m_r[rr] - mnew);
            float sum = 0.f;
            #pragma unroll
            for (int j = 0; j < 8; j++) {
                float p0 = expf(Sa[j][rr*2]   - mnew);
                float p1 = expf(Sa[j][rr*2+1] - mnew);
                Sa[j][rr*2] = p0; Sa[j][rr*2+1] = p1;
                sum += p0 + p1;
            }
            sum += __shfl_xor_sync(0xffffffffu, sum, 1);
            sum += __shfl_xor_sync(0xffffffffu, sum, 2);
            l_r[rr] = l_r[rr]*alpha + sum;
            m_r[rr] = mnew;
            #pragma unroll
            for (int j = 0; j < 8; j++) {
                Oa[j][rr*2]   *= alpha;
                Oa[j][rr*2+1] *= alpha;
            }
        }

        // ---- O += P V  (P from registers, bf16x3) ----
        {
            const uint32_t* Vh = sm + 2*FA_TW + cur*4*FA_TW + 2*FA_TW;
            const uint32_t* Vl = Vh + FA_TW;
            #pragma unroll
            for (int ks = 0; ks < 64; ks += 16) {
                const int j0 = ks >> 3;          // S col tiles j0, j0+1
                const int kp = ks >> 1;
                uint32_t ph[4], pl[4];
                splitpack2(Sa[j0][0],   Sa[j0][1],   ph[0], pl[0]);
                splitpack2(Sa[j0][2],   Sa[j0][3],   ph[1], pl[1]);
                splitpack2(Sa[j0+1][0], Sa[j0+1][1], ph[2], pl[2]);
                splitpack2(Sa[j0+1][2], Sa[j0+1][3], ph[3], pl[3]);
                uint32_t bh[8][2], bl[8][2];
                #pragma unroll
                for (int j = 0; j < 8; j++) {
                    int nr = j*8 + g;
                    bh[j][0] = Vh[nr*FA_SP + kp + c];   bl[j][0] = Vl[nr*FA_SP + kp + c];
                    bh[j][1] = Vh[nr*FA_SP + kp + c+4]; bl[j][1] = Vl[nr*FA_SP + kp + c+4];
                }
                #pragma unroll
                for (int j = 0; j < 8; j++) mma_bf16(Oa[j], ph, bh[j]);
                #pragma unroll
                for (int j = 0; j < 8; j++) mma_bf16(Oa[j], ph, bl[j]);
                #pragma unroll
                for (int j = 0; j < 8; j++) mma_bf16(Oa[j], pl, bh[j]);
            }
        }

        if (kb < mb) CP_WAIT0();
        __syncthreads();
    }

    // ---- normalize and write y (split bf16, [t][h*64+d]) ----
    float inv0 = 1.f / l_r[0];
    float inv1 = 1.f / l_r[1];
    #pragma unroll
    for (int j = 0; j < 8; j++) {
        int d = j*8 + 2*c;
        size_t t0 = (size_t)(b*S_ + m0 + mr)*D_ + hh*64 + d;
        split_store2(s_y_h, s_y_l, t0,          Oa[j][0]*inv0, Oa[j][1]*inv0);
        split_store2(s_y_h, s_y_l, t0 + 8*D_,   Oa[j][2]*inv1, Oa[j][3]*inv1);
    }
}

// ---------------- host ----------------
template<int BM, int BN, int BK>
constexpr int smem_bytes() {
    return 2 * (2*BM*(BK/2+4) + 2*BN*(BK/2+4)) * 4;
}

extern "C" void kernel_launch(void* const* d_in, const int* in_sizes, int n_in,
                              void* d_out, int out_size) {
    const int*   x      = (const int*)  d_in[0];
    const float* emb    = (const float*)d_in[1];
    const float* wq     = (const float*)d_in[2];
    const float* bq     = (const float*)d_in[3];
    const float* wk     = (const float*)d_in[4];
    const float* bk     = (const float*)d_in[5];
    const float* wv     = (const float*)d_in[6];
    const float* bv     = (const float*)d_in[7];
    const float* wo     = (const float*)d_in[8];
    const float* bo     = (const float*)d_in[9];
    const float* w_gate = (const float*)d_in[10];
    const float* w_up   = (const float*)d_in[11];
    const float* w_down = (const float*)d_in[12];
    const float* ln1    = (const float*)d_in[13];
    const float* ln2    = (const float*)d_in[14];
    const float* norm_w = (const float*)d_in[15];
    float* out = (float*)d_out;

    float *h, *qk, *bqkv;
    cudaGetSymbolAddress((void**)&h,    g_h);
    cudaGetSymbolAddress((void**)&qk,   g_qk);
    cudaGetSymbolAddress((void**)&bqkv, g_bqkv);

    bf16 *wqkvh,*wqkvl,*woh,*wol,*wguh,*wgul,*wdh,*wdl,*embh,*embl;
    bf16 *hnh,*hnl,*vth,*vtl,*yh,*yl,*gah,*gal;
    cudaGetSymbolAddress((void**)&wqkvh, s_wqkv_h); cudaGetSymbolAddress((void**)&wqkvl, s_wqkv_l);
    cudaGetSymbolAddress((void**)&woh, s_wo_h);  cudaGetSymbolAddress((void**)&wol, s_wo_l);
    cudaGetSymbolAddress((void**)&wguh, s_wgu_h); cudaGetSymbolAddress((void**)&wgul, s_wgu_l);
    cudaGetSymbolAddress((void**)&wdh, s_wd_h);  cudaGetSymbolAddress((void**)&wdl, s_wd_l);
    cudaGetSymbolAddress((void**)&embh, s_emb_h); cudaGetSymbolAddress((void**)&embl, s_emb_l);
    cudaGetSymbolAddress((void**)&hnh, s_hn_h);  cudaGetSymbolAddress((void**)&hnl, s_hn_l);
    cudaGetSymbolAddress((void**)&vth, s_vt_h);  cudaGetSymbolAddress((void**)&vtl, s_vt_l);
    cudaGetSymbolAddress((void**)&yh,  s_y_h);   cudaGetSymbolAddress((void**)&yl,  s_y_l);
    cudaGetSymbolAddress((void**)&gah, s_ga_h);  cudaGetSymbolAddress((void**)&gal, s_ga_l);

    constexpr int SM_S = smem_bytes<128,128,32>();   // 81920
    constexpr int SM_P = smem_bytes<128,64,32>();    // 61440

    cudaFuncSetAttribute(gemm_tc<128,64,32,64,32,EPI_QKV,3>,      cudaFuncAttributeMaxDynamicSharedMemorySize, SM_P);
    cudaFuncSetAttribute(gemm_tc<128,64,32,64,32,EPI_BIAS_RES,3>, cudaFuncAttributeMaxDynamicSharedMemorySize, SM_P);
    cudaFuncSetAttribute(gemm_tc<128,128,32,64,32,EPI_SWIGLU,2>,  cudaFuncAttributeMaxDynamicSharedMemorySize, SM_S);
    cudaFuncSetAttribute(gemm_tc<128,64,32,64,32,EPI_RES,3>,      cudaFuncAttributeMaxDynamicSharedMemorySize, SM_P);
    cudaFuncSetAttribute(gemm_tc<128,128,32,64,32,EPI_NONE,2>,    cudaFuncAttributeMaxDynamicSharedMemorySize, SM_S);
    cudaFuncSetAttribute(flash_attn_kernel,                       cudaFuncAttributeMaxDynamicSharedMemorySize, FA_SMEM);

    // ---- prep ----
    auto split_launch = [](const float* src, bf16* dh, bf16* dl, size_t n) {
        int n4 = (int)(n / 4);
        split_kernel<<<(n4 + 255)/256, 256>>>(src, dh, dl, n4);
    };
    int nw4 = L_*D_*D_/4;
    split_pack_kernel<<<(nw4+255)/256, 256>>>(wq, wqkvh, wqkvl, 0);
    split_pack_kernel<<<(nw4+255)/256, 256>>>(wk, wqkvh, wqkvl, D_);
    split_pack_kernel<<<(nw4+255)/256, 256>>>(wv, wqkvh, wqkvl, 2*D_);
    pack_bias_kernel<<<(L_*3*D_+255)/256, 256>>>(bq, bk, bv, bqkv);
    split_launch(wo, woh, wol, (size_t)L_*D_*D_);
    int ngu4 = L_*DI_*D_/4;
    split_pack_gu_kernel<<<(ngu4+255)/256, 256>>>(w_gate, w_up, wguh, wgul);
    split_launch(w_down, wdh, wdl, (size_t)L_*D_*DI_);
    split_launch(emb, embh, embl, (size_t)V_*D_);

    embed_kernel<<<T_*D_/4/256, 256>>>(x, emb, h);
    rope_cache_kernel<<<(S_*32 + 255)/256, 256>>>();

    const dim3 gqkv(3*D_/64, T_/128, 1);
    const dim3 gp(D_/64,   T_/128, 1);
    const dim3 ggu(2*DI_/128, T_/128, 1);
    const dim3 gfa(S_/64, B_*H_, 1);       // 16 x 32 flash blocks

    for (int l = 0; l < L_; l++) {
        rmsnorm_kernel<<<T_, 256>>>(h, ln1 + (size_t)l*D_, hnh, hnl);

        gemm_tc<128,64,32,64,32,EPI_QKV,3><<<gqkv,128,SM_P>>>(
            hnh, hnl, wqkvh + (size_t)l*3*D_*D_, wqkvl + (size_t)l*3*D_*D_,
            qk, vth, vtl, bqkv + (size_t)l*3*D_,
            T_, 3*D_, D_, D_, D_, 2*D_);

        rope_kernel<<<T_*H_*32/256, 256>>>();

        flash_attn_kernel<<<gfa, 128, FA_SMEM>>>(0.125f);

        gemm_tc<128,64,32,64,32,EPI_BIAS_RES,3><<<gp,128,SM_P>>>(
            yh, yl, woh + (size_t)l*D_*D_, wol + (size_t)l*D_*D_,
            h, nullptr, nullptr, bo + (size_t)l*D_,
            T_, D_, D_, D_, D_, D_);

        rmsnorm_kernel<<<T_, 256>>>(h, ln2 + (size_t)l*D_, hnh, hnl);

        gemm_tc<128,128,32,64,32,EPI_SWIGLU,2><<<ggu,256,SM_S>>>(
            hnh, hnl, wguh + (size_t)l*2*DI_*D_, wgul + (size_t)l*2*DI_*D_,
            nullptr, gah, gal, nullptr,
            T_, 2*DI_, D_, D_, D_, 2*DI_);

        gemm_tc<128,64,32,64,32,EPI_RES,3><<<gp,128,SM_P>>>(
            gah, gal, wdh + (size_t)l*D_*DI_, wdl + (size_t)l*D_*DI_,
            h, nullptr, nullptr, nullptr,
            T_, D_, DI_, DI_, DI_, D_);
    }

    rmsnorm_kernel<<<T_, 256>>>(h, norm_w, hnh, hnl);

    const dim3 gl(V_/128, T_/128, 1);
    gemm_tc<128,128,32,64,32,EPI_NONE,2><<<gl,256,SM_S>>>(
        hnh, hnl, embh, embl, out, nullptr, nullptr, nullptr,
        T_, V_, D_, D_, D_, V_);
}

// round 14
// speedup vs baseline: 1.4930x; 1.0331x over previous
#include <cuda_runtime.h>
#include <cuda_bf16.h>
#include <cstdint>
#include <math.h>

#define L_  8
#define D_  1024
#define H_  16
#define DH_ 64
#define DI_ 4096
#define V_  32000
#define B_  2
#define S_  1024
#define T_  (B_*S_)

typedef __nv_bfloat16 bf16;

// ---------------- fp32 scratch ----------------
__device__ float g_h   [T_*D_];
__device__ float g_cos [S_*32];
__device__ float g_sin [S_*32];
__device__ float g_bqkv[L_*3*D_];

// ---------------- split bf16 scratch (hi/lo) ----------------
__device__ bf16 s_wqkv_h[L_*3*D_*D_], s_wqkv_l[L_*3*D_*D_];
__device__ bf16 s_wo_h[L_*D_*D_],   s_wo_l[L_*D_*D_];
__device__ bf16 s_wgu_h[(size_t)L_*2*DI_*D_], s_wgu_l[(size_t)L_*2*DI_*D_];
__device__ bf16 s_wd_h[L_*D_*DI_],  s_wd_l[L_*D_*DI_];
__device__ bf16 s_emb_h[V_*D_],     s_emb_l[V_*D_];
__device__ bf16 s_hn_h[T_*D_],      s_hn_l[T_*D_];
__device__ bf16 s_q_h [T_*D_],      s_q_l [T_*D_];
__device__ bf16 s_k_h [T_*D_],      s_k_l [T_*D_];
__device__ bf16 s_vt_h[T_*D_],      s_vt_l[T_*D_];     // [b][h][d][s]
__device__ bf16 s_y_h [T_*D_],      s_y_l [T_*D_];
__device__ bf16 s_ga_h[T_*DI_],     s_ga_l[T_*DI_];

// ---------------- helpers ----------------
__device__ __forceinline__ void split1(float v, bf16& h, bf16& l) {
    h = __float2bfloat16(v);
    l = __float2bfloat16(v - __bfloat162float(h));
}

__device__ __forceinline__ void split_store2(bf16* H, bf16* Lo, size_t off, float v0, float v1) {
    bf16 h0, l0, h1, l1;
    split1(v0, h0, l0);
    split1(v1, h1, l1);
    __nv_bfloat162 th; th.x = h0; th.y = h1;
    __nv_bfloat162 tl; tl.x = l0; tl.y = l1;
    *(__nv_bfloat162*)(H  + off) = th;
    *(__nv_bfloat162*)(Lo + off) = tl;
}

__device__ __forceinline__ void splitpack2(float a, float b, uint32_t& h, uint32_t& l) {
    bf16 ha, la, hb, lb;
    split1(a, ha, la);
    split1(b, hb, lb);
    h = ((uint32_t)__bfloat16_as_ushort(hb) << 16) | __bfloat16_as_ushort(ha);
    l = ((uint32_t)__bfloat16_as_ushort(lb) << 16) | __bfloat16_as_ushort(la);
}

__global__ void split_kernel(const float* __restrict__ x, bf16* __restrict__ h,
                             bf16* __restrict__ l, int n4) {
    int i = blockIdx.x * blockDim.x + threadIdx.x;
    if (i >= n4) return;
    float4 v = ((const float4*)x)[i];
    bf16 h0,l0,h1,l1,h2,l2,h3,l3;
    split1(v.x, h0, l0); split1(v.y, h1, l1);
    split1(v.z, h2, l2); split1(v.w, h3, l3);
    ((ushort4*)h)[i] = make_ushort4(__bfloat16_as_ushort(h0), __bfloat16_as_ushort(h1),
                                    __bfloat16_as_ushort(h2), __bfloat16_as_ushort(h3));
    ((ushort4*)l)[i] = make_ushort4(__bfloat16_as_ushort(l0), __bfloat16_as_ushort(l1),
                                    __bfloat16_as_ushort(l2), __bfloat16_as_ushort(l3));
}

__global__ void split_pack_kernel(const float* __restrict__ x, bf16* __restrict__ h,
                                  bf16* __restrict__ l, int row_off) {
    int i = blockIdx.x * blockDim.x + threadIdx.x;
    if (i >= L_*D_*D_/4) return;
    int lay = i / (D_*D_/4);
    int rem = i % (D_*D_/4);
    int r   = rem / (D_/4);
    int c4  = rem % (D_/4);
    float4 v = ((const float4*)x)[i];
    int d4 = lay*(3*D_*D_/4) + (row_off + r)*(D_/4) + c4;
    bf16 h0,l0,h1,l1,h2,l2,h3,l3;
    split1(v.x, h0, l0); split1(v.y, h1, l1);
    split1(v.z, h2, l2); split1(v.w, h3, l3);
    ((ushort4*)h)[d4] = make_ushort4(__bfloat16_as_ushort(h0), __bfloat16_as_ushort(h1),
                                     __bfloat16_as_ushort(h2), __bfloat16_as_ushort(h3));
    ((ushort4*)l)[d4] = make_ushort4(__bfloat16_as_ushort(l0), __bfloat16_as_ushort(l1),
                                     __bfloat16_as_ushort(l2), __bfloat16_as_ushort(l3));
}

__global__ void split_pack_gu_kernel(const float* __restrict__ wg, const float* __restrict__ wu,
                                     bf16* __restrict__ h, bf16* __restrict__ l) {
    int i = blockIdx.x * blockDim.x + threadIdx.x;
    if (i >= L_*DI_*D_/4) return;
    int lay = i / (DI_*D_/4);
    int rem = i % (DI_*D_/4);
    int r   = rem / (D_/4);
    int c4  = rem % (D_/4);
    float4 vg = ((const float4*)wg)[i];
    float4 vu = ((const float4*)wu)[i];
    size_t base = (size_t)lay*(2*DI_*D_/4);
    size_t dg = base + (size_t)(2*r)  *(D_/4) + c4;
    size_t du = base + (size_t)(2*r+1)*(D_/4) + c4;
    bf16 h0,l0,h1,l1,h2,l2,h3,l3;
    split1(vg.x, h0, l0); split1(vg.y, h1, l1);
    split1(vg.z, h2, l2); split1(vg.w, h3, l3);
    ((ushort4*)h)[dg] = make_ushort4(__bfloat16_as_ushort(h0), __bfloat16_as_ushort(h1),
                                     __bfloat16_as_ushort(h2), __bfloat16_as_ushort(h3));
    ((ushort4*)l)[dg] = make_ushort4(__bfloat16_as_ushort(l0), __bfloat16_as_ushort(l1),
                                     __bfloat16_as_ushort(l2), __bfloat16_as_ushort(l3));
    split1(vu.x, h0, l0); split1(vu.y, h1, l1);
    split1(vu.z, h2, l2); split1(vu.w, h3, l3);
    ((ushort4*)h)[du] = make_ushort4(__bfloat16_as_ushort(h0), __bfloat16_as_ushort(h1),
                                     __bfloat16_as_ushort(h2), __bfloat16_as_ushort(h3));
    ((ushort4*)l)[du] = make_ushort4(__bfloat16_as_ushort(l0), __bfloat16_as_ushort(l1),
                                     __bfloat16_as_ushort(l2), __bfloat16_as_ushort(l3));
}

__global__ void pack_bias_kernel(const float* __restrict__ bq, const float* __restrict__ bk,
                                 const float* __restrict__ bv, float* __restrict__ dst) {
    int i = blockIdx.x * blockDim.x + threadIdx.x;
    if (i >= L_*3*D_) return;
    int lay = i / (3*D_);
    int j   = i % (3*D_);
    float v = (j < D_) ? bq[lay*D_ + j]
            : (j < 2*D_) ? bk[lay*D_ + j - D_]
            : bv[lay*D_ + j - 2*D_];
    dst[i] = v;
}

// ---------------- small kernels ----------------
__global__ void embed_kernel(const int* __restrict__ x, const float* __restrict__ emb,
                             float* __restrict__ h) {
    int i = blockIdx.x * blockDim.x + threadIdx.x;
    int t = i / (D_/4);
    int c = i % (D_/4);
    float4 v = *(const float4*)(emb + (size_t)x[t]*D_ + c*4);
    *(float4*)(h + (size_t)t*D_ + c*4) = v;
}

__global__ void rope_cache_kernel() {
    int i = blockIdx.x * blockDim.x + threadIdx.x;
    if (i >= S_*32) return;
    int s = i / 32, j = i % 32;
    double inv = pow(10000.0, -(double)j / 32.0);
    double ph = (double)s * inv;
    g_cos[i] = (float)cos(ph);
    g_sin[i] = (float)sin(ph);
}

__global__ void rmsnorm_kernel(const float* __restrict__ x, const float* __restrict__ w,
                               bf16* __restrict__ oh, bf16* __restrict__ ol) {
    int t = blockIdx.x;
    int tid = threadIdx.x;
    const float* xp = x + (size_t)t*D_;
    float v[4];
    float s = 0.f;
    #pragma unroll
    for (int i = 0; i < 4; i++) { v[i] = xp[tid + i*256]; s += v[i]*v[i]; }
    #pragma unroll
    for (int off = 16; off; off >>= 1) s += __shfl_xor_sync(0xffffffffu, s, off);
    __shared__ float red[8];
    if ((tid & 31) == 0) red[tid >> 5] = s;
    __syncthreads();
    if (tid < 32) {
        float s2 = (tid < 8) ? red[tid] : 0.f;
        #pragma unroll
        for (int off = 4; off; off >>= 1) s2 += __shfl_xor_sync(0xffffffffu, s2, off);
        if (tid == 0) red[0] = s2;
    }
    __syncthreads();
    float r = rsqrtf(red[0] * (1.f/(float)D_) + 1e-6f);
    size_t base = (size_t)t*D_;
    #pragma unroll
    for (int i = 0; i < 4; i++) {
        int idx = tid + i*256;
        split1(w[idx] * v[i] * r, oh[base+idx], ol[base+idx]);
    }
}

// ---------------- bf16x3 GEMM on pre-split operands ----------------
enum { EPI_NONE = 0, EPI_BIAS_RES = 2, EPI_RES = 3,
       EPI_QKV = 8, EPI_SWIGLU = 9 };

__device__ __forceinline__ void mma_bf16(float* d, const uint32_t* a, const uint32_t* b) {
    asm volatile(
        "mma.sync.aligned.m16n8k16.row.col.f32.bf16.bf16.f32 "
        "{%0,%1,%2,%3}, {%4,%5,%6,%7}, {%8,%9}, {%0,%1,%2,%3};\n"
        : "+f"(d[0]), "+f"(d[1]), "+f"(d[2]), "+f"(d[3])
        : "r"(a[0]), "r"(a[1]), "r"(a[2]), "r"(a[3]),
          "r"(b[0]), "r"(b[1]));
}

#define CP_ASYNC16(dst, src) \
    asm volatile("cp.async.cg.shared.global [%0], [%1], 16;" :: "r"(dst), "l"(src))
#define CP_COMMIT() asm volatile("cp.async.commit_group;" ::: "memory")
#define CP_WAIT0()  asm volatile("cp.async.wait_group 0;"  ::: "memory")

template<int BM, int BN, int BK, int WM, int WN, int EPI, int MINB>
__global__ __launch_bounds__((BM/WM)*(BN/WN)*32, MINB)
void gemm_tc(const bf16* __restrict__ Agh, const bf16* __restrict__ Agl,
             const bf16* __restrict__ Bgh, const bf16* __restrict__ Bgl,
             float* __restrict__ C, bf16* __restrict__ Oh, bf16* __restrict__ Ol,
             const float* __restrict__ bias,
             int M, int N, int K, int lda, int ldb, int ldc)
{
    constexpr int WARPS_N = BN/WN;
    constexpr int THREADS = (BM/WM)*(BN/WN)*32;
    constexpr int MT = WM/16;
    constexpr int NT = WN/8;
    constexpr int SP = BK/2 + 4;
    constexpr int SZA = BM*SP;
    constexpr int SZB = BN*SP;
    constexpr int STAGE = 2*SZA + 2*SZB;
    constexpr int NCA = (BM*BK/8)/THREADS;
    constexpr int NCB = (BN*BK/8)/THREADS;

    extern __shared__ uint32_t smem_u[];

    const int tid = threadIdx.x;
    const int m0 = blockIdx.y * BM;
    const int n0 = blockIdx.x * BN;

    const int warp = tid >> 5;
    const int lane = tid & 31;
    const int g = lane >> 2;
    const int c = lane & 3;
    const int wn = warp % WARPS_N;
    const int wm = warp / WARPS_N;

    float acc[MT][NT][4];
    #pragma unroll
    for (int i = 0; i < MT; i++)
        #pragma unroll
        for (int j = 0; j < NT; j++)
            #pragma unroll
            for (int r = 0; r < 4; r++) acc[i][j][r] = 0.f;

    const int nk = K / BK;

    const uint32_t smb = (uint32_t)__cvta_generic_to_shared(smem_u);
    auto cp_tile = [&](int kt, int s) {
        const uint32_t Ah = smb + s*STAGE*4;
        const uint32_t Al = Ah + SZA*4;
        const uint32_t Bh = Al + SZA*4;
        const uint32_t Bl = Bh + SZB*4;
        #pragma unroll
        for (int i = 0; i < NCA; i++) {
            int f  = tid + i*THREADS;
            int r  = f / (BK/8);
            int c8 = f % (BK/8);
            size_t   go = (size_t)(m0+r)*lda + kt + c8*8;
            uint32_t so = (uint32_t)(r*SP + c8*4)*4;
            CP_ASYNC16(Ah + so, Agh + go);
            CP_ASYNC16(Al + so, Agl + go);
        }
        #pragma unroll
        for (int i = 0; i < NCB; i++) {
            int f  = tid + i*THREADS;
            int r  = f / (BK/8);
            int c8 = f % (BK/8);
            size_t   go = (size_t)(n0+r)*ldb + kt + c8*8;
            uint32_t so = (uint32_t)(r*SP + c8*4)*4;
            CP_ASYNC16(Bh + so, Bgh + go);
            CP_ASYNC16(Bl + so, Bgl + go);
        }
        CP_COMMIT();
    };

    auto compute_stage = [&](int cur) {
        const uint32_t* Ah = smem_u + cur*STAGE;
        const uint32_t* Al = Ah + SZA;
        const uint32_t* Bh = Al + SZA;
        const uint32_t* Bl = Bh + SZB;
        #pragma unroll
        for (int ks = 0; ks < BK; ks += 16) {
            const int kp = ks >> 1;
            uint32_t ah[MT][4], al[MT][4], bh[NT][2], bl[NT][2];
            #pragma unroll
            for (int i = 0; i < MT; i++) {
                int mr = wm*WM + i*16 + g;
                ah[i][0] = Ah[mr*SP     + kp + c];   al[i][0] = Al[mr*SP     + kp + c];
                ah[i][1] = Ah[(mr+8)*SP + kp + c];   al[i][1] = Al[(mr+8)*SP + kp + c];
                ah[i][2] = Ah[mr*SP     + kp + c+4]; al[i][2] = Al[mr*SP     + kp + c+4];
                ah[i][3] = Ah[(mr+8)*SP + kp + c+4]; al[i][3] = Al[(mr+8)*SP + kp + c+4];
            }
            #pragma unroll
            for (int j = 0; j < NT; j++) {
                int nr = wn*WN + j*8 + g;
                bh[j][0] = Bh[nr*SP + kp + c];   bl[j][0] = Bl[nr*SP + kp + c];
                bh[j][1] = Bh[nr*SP + kp + c+4]; bl[j][1] = Bl[nr*SP + kp + c+4];
            }
            #pragma unroll
            for (int i = 0; i < MT; i++)
                #pragma unroll
                for (int j = 0; j < NT; j++)
                    mma_bf16(acc[i][j], ah[i], bh[j]);
            #pragma unroll
            for (int i = 0; i < MT; i++)
                #pragma unroll
                for (int j = 0; j < NT; j++)
                    mma_bf16(acc[i][j], ah[i], bl[j]);
            #pragma unroll
            for (int i = 0; i < MT; i++)
                #pragma unroll
                for (int j = 0; j < NT; j++)
                    mma_bf16(acc[i][j], al[i], bh[j]);
        }
    };

    cp_tile(0, 0);
    CP_WAIT0();
    __syncthreads();

    for (int t = 0; t < nk; t++) {
        const int cur = t & 1;
        if (t + 1 < nk) cp_tile((t+1)*BK, cur ^ 1);
        compute_stage(cur);
        if (t + 1 < nk) CP_WAIT0();
        __syncthreads();
    }

    // ---------------- epilogues ----------------
    if (EPI == EPI_QKV) {
        // WN must be 64 (head-aligned). q/k blocks: rope in registers; V: transposed split store.
        if (n0 < 2*D_) {
            const bool isq = (n0 < D_);
            #pragma unroll
            for (int i = 0; i < MT; i++) {
                #pragma unroll
                for (int jj = 0; jj < NT/2; jj++) {
                    #pragma unroll
                    for (int rr = 0; rr < 2; rr++) {
                        int m = m0 + wm*WM + i*16 + g + rr*8;
                        int s = m & (S_-1);
                        #pragma unroll
                        for (int t2 = 0; t2 < 2; t2++) {
                            int n = n0 + jj*8 + 2*c + t2;
                            float a  = acc[i][jj]  [rr*2+t2] + bias[n];
                            float bb = acc[i][jj+4][rr*2+t2] + bias[n+32];
                            int d = n & 63;                 // < 32
                            float co = g_cos[s*32 + d];
                            float si = g_sin[s*32 + d];
                            float r0 = a*co - bb*si;
                            float r1 = bb*co + a*si;
                            int col = isq ? (n & (D_-1)) : (n - D_);
                            size_t o = (size_t)m*D_ + col;
                            if (isq) {
                                split1(r0, s_q_h[o],    s_q_l[o]);
                                split1(r1, s_q_h[o+32], s_q_l[o+32]);
                            } else {
                                split1(r0, s_k_h[o],    s_k_l[o]);
                                split1(r1, s_k_h[o+32], s_k_l[o+32]);
                            }
                        }
                    }
                }
            }
        } else {
            #pragma unroll
            for (int i = 0; i < MT; i++) {
                #pragma unroll
                for (int j = 0; j < NT; j++) {
                    int n = n0 + wn*WN + j*8 + 2*c;
                    #pragma unroll
                    for (int rr = 0; rr < 2; rr++) {
                        int m = m0 + wm*WM + i*16 + g + rr*8;
                        float v0 = acc[i][j][rr*2]   + bias[n];
                        float v1 = acc[i][j][rr*2+1] + bias[n+1];
                        int dg = n - 2*D_;
                        int hh = dg >> 6, dd = dg & 63;
                        int b  = m >> 10, s = m & 1023;
                        size_t o0 = (((size_t)b*H_ + hh)*DH_ + dd)*S_ + s;
                        split1(v0, Oh[o0],    Ol[o0]);
                        split1(v1, Oh[o0+S_], Ol[o0+S_]);
                    }
                }
            }
        }
        return;
    }

    #pragma unroll
    for (int i = 0; i < MT; i++) {
        #pragma unroll
        for (int j = 0; j < NT; j++) {
            int n = n0 + wn*WN + j*8 + 2*c;
            #pragma unroll
            for (int rr = 0; rr < 2; rr++) {
                int m = m0 + wm*WM + i*16 + g + rr*8;
                float v0 = acc[i][j][rr*2 + 0];
                float v1 = acc[i][j][rr*2 + 1];
                if (EPI == EPI_SWIGLU) {
                    float sw = v0 / (1.f + expf(-v0)) * v1;
                    size_t oo = (size_t)m*(ldc >> 1) + (n >> 1);
                    split1(sw, Oh[oo], Ol[oo]);
                    continue;
                }
                size_t off = (size_t)m*ldc + n;
                if (EPI == EPI_BIAS_RES) {
                    v0 += bias[n]   + C[off];
                    v1 += bias[n+1] + C[off+1];
                    *(float2*)(C + off) = make_float2(v0, v1);
                } else if (EPI == EPI_RES) {
                    v0 += C[off]; v1 += C[off+1];
                    *(float2*)(C + off) = make_float2(v0, v1);
                } else if (EPI == EPI_NONE) {
                    *(float2*)(C + off) = make_float2(v0, v1);
                }
            }
        }
    }
}

// ================== flash attention (scores+softmax+attV fused) ==================
#define FA_SP 36
#define FA_TW (64*FA_SP)
#define FA_SMEM ((2*FA_TW + 2*4*FA_TW)*4)

__global__ __launch_bounds__(128, 2)
void flash_attn_kernel(float scale)
{
    extern __shared__ uint32_t sm[];
    const int tid  = threadIdx.x;
    const int warp = tid >> 5;
    const int lane = tid & 31;
    const int g = lane >> 2;
    const int c = lane & 3;
    const int mb = blockIdx.x;
    const int bh = blockIdx.y;
    const int b  = bh >> 4;
    const int hh = bh & 15;
    const int m0 = mb * 64;

    const uint32_t smb = (uint32_t)__cvta_generic_to_shared(sm);
    uint32_t* sQh = sm;
    uint32_t* sQl = sm + FA_TW;

    const size_t vbase = (size_t)bh * DH_ * S_;

    #pragma unroll
    for (int i = 0; i < 4; i++) {
        int f = tid + i*128;
        int r = f >> 3, c8 = f & 7;
        size_t go = ((size_t)(b*S_ + m0 + r))*D_ + hh*64 + c8*8;
        uint32_t so = (uint32_t)(r*FA_SP + c8*4)*4;
        CP_ASYNC16(smb + so,             s_q_h + go);
        CP_ASYNC16(smb + FA_TW*4 + so,   s_q_l + go);
    }

    auto cp_kv = [&](int kb, int s) {
        uint32_t kvb = smb + (2*FA_TW + s*4*FA_TW)*4;
        #pragma unroll
        for (int i = 0; i < 4; i++) {
            int f = tid + i*128;
            int r = f >> 3, c8 = f & 7;
            uint32_t so = (uint32_t)(r*FA_SP + c8*4)*4;
            size_t gok = ((size_t)(b*S_ + kb*64 + r))*D_ + hh*64 + c8*8;
            CP_ASYNC16(kvb + so,             s_k_h + gok);
            CP_ASYNC16(kvb + FA_TW*4 + so,   s_k_l + gok);
            size_t gov = vbase + (size_t)r*S_ + kb*64 + c8*8;
            CP_ASYNC16(kvb + 2*FA_TW*4 + so, s_vt_h + gov);
            CP_ASYNC16(kvb + 3*FA_TW*4 + so, s_vt_l + gov);
        }
        CP_COMMIT();
    };

    cp_kv(0, 0);
    CP_WAIT0();
    __syncthreads();

    float m_r[2] = {-INFINITY, -INFINITY};
    float l_r[2] = {0.f, 0.f};
    float Oa[8][4];
    #pragma unroll
    for (int j = 0; j < 8; j++)
        #pragma unroll
        for (int r = 0; r < 4; r++) Oa[j][r] = 0.f;

    const int mr = warp*16 + g;

    for (int kb = 0; kb <= mb; kb++) {
        const int cur = kb & 1;
        if (kb < mb) cp_kv(kb+1, cur ^ 1);

        float Sa[8][4];
        #pragma unroll
        for (int j = 0; j < 8; j++)
            #pragma unroll
            for (int r = 0; r < 4; r++) Sa[j][r] = 0.f;

        {
            const uint32_t* Bh = sm + 2*FA_TW + cur*4*FA_TW;
            const uint32_t* Bl = Bh + FA_TW;
            #pragma unroll
            for (int ks = 0; ks < 64; ks += 16) {
                const int kp = ks >> 1;
                uint32_t ah[4], al[4], bh[8][2], bl[8][2];
                ah[0] = sQh[mr*FA_SP     + kp + c];   al[0] = sQl[mr*FA_SP     + kp + c];
                ah[1] = sQh[(mr+8)*FA_SP + kp + c];   al[1] = sQl[(mr+8)*FA_SP + kp + c];
                ah[2] = sQh[mr*FA_SP     + kp + c+4]; al[2] = sQl[mr*FA_SP     + kp + c+4];
                ah[3] = sQh[(mr+8)*FA_SP + kp + c+4]; al[3] = sQl[(mr+8)*FA_SP + kp + c+4];
                #pragma unroll
                for (int j = 0; j < 8; j++) {
                    int nr = j*8 + g;
                    bh[j][0] = Bh[nr*FA_SP + kp + c];   bl[j][0] = Bl[nr*FA_SP + kp + c];
                    bh[j][1] = Bh[nr*FA_SP + kp + c+4]; bl[j][1] = Bl[nr*FA_SP + kp + c+4];
                }
                #pragma unroll
                for (int j = 0; j < 8; j++) mma_bf16(Sa[j], ah, bh[j]);
                #pragma unroll
                for (int j = 0; j < 8; j++) mma_bf16(Sa[j], ah, bl[j]);
                #pragma unroll
                for (int j = 0; j < 8; j++) mma_bf16(Sa[j], al, bh[j]);
            }
        }

        #pragma unroll
        for (int j = 0; j < 8; j++)
            #pragma unroll
            for (int r = 0; r < 4; r++) Sa[j][r] *= scale;
        if (kb == mb) {
            #pragma unroll
            for (int j = 0; j < 8; j++) {
                int col = kb*64 + j*8 + 2*c;
                #pragma unroll
                for (int rr = 0; rr < 2; rr++) {
                    int row = m0 + mr + rr*8;
                    if (col     > row) Sa[j][rr*2]   = -INFINITY;
                    if (col + 1 > row) Sa[j][rr*2+1] = -INFINITY;
                }
            }
        }

        #pragma unroll
        for (int rr = 0; rr < 2; rr++) {
            float mx = -INFINITY;
            #pragma unroll
            for (int j = 0; j < 8; j++)
                mx = fmaxf(mx, fmaxf(Sa[j][rr*2], Sa[j][rr*2+1]));
            mx = fmaxf(mx, __shfl_xor_sync(0xffffffffu, mx, 1));
            mx = fmaxf(mx, __shfl_xor_sync(0xffffffffu, mx, 2));
            float mnew  = fmaxf(m_r[rr], mx);
            float alpha = expf(m_r[rr] - mnew);
            float sum = 0.f;
            #pragma unroll
            for (int j = 0; j < 8; j++) {
                float p0 = expf(Sa[j][rr*2]   - mnew);
                float p1 = expf(Sa[j][rr*2+1] - mnew);
                Sa[j][rr*2] = p0; Sa[j][rr*2+1] = p1;
                sum += p0 + p1;
            }
            sum += __shfl_xor_sync(0xffffffffu, sum, 1);
            sum += __shfl_xor_sync(0xffffffffu, sum, 2);
            l_r[rr] = l_r[rr]*alpha + sum;
            m_r[rr] = mnew;
            #pragma unroll
            for (int j = 0; j < 8; j++) {
                Oa[j][rr*2]   *= alpha;
                Oa[j][rr*2+1] *= alpha;
            }
        }

        {
            const uint32_t* Vh = sm + 2*FA_TW + cur*4*FA_TW + 2*FA_TW;
            const uint32_t* Vl = Vh + FA_TW;
            #pragma unroll
            for (int ks = 0; ks < 64; ks += 16) {
                const int j0 = ks >> 3;
                const int kp = ks >> 1;
                uint32_t ph[4], pl[4];
                splitpack2(Sa[j0][0],   Sa[j0][1],   ph[0], pl[0]);
                splitpack2(Sa[j0][2],   Sa[j0][3],   ph[1], pl[1]);
                splitpack2(Sa[j0+1][0], Sa[j0+1][1], ph[2], pl[2]);
                splitpack2(Sa[j0+1][2], Sa[j0+1][3], ph[3], pl[3]);
                uint32_t bh[8][2], bl[8][2];
                #pragma unroll
                for (int j = 0; j < 8; j++) {
                    int nr = j*8 + g;
                    bh[j][0] = Vh[nr*FA_SP + kp + c];   bl[j][0] = Vl[nr*FA_SP + kp + c];
                    bh[j][1] = Vh[nr*FA_SP + kp + c+4]; bl[j][1] = Vl[nr*FA_SP + kp + c+4];
                }
                #pragma unroll
                for (int j = 0; j < 8; j++) mma_bf16(Oa[j], ph, bh[j]);
                #pragma unroll
                for (int j = 0; j < 8; j++) mma_bf16(Oa[j], ph, bl[j]);
                #pragma unroll
                for (int j = 0; j < 8; j++) mma_bf16(Oa[j], pl, bh[j]);
            }
        }

        if (kb < mb) CP_WAIT0();
        __syncthreads();
    }

    float inv0 = 1.f / l_r[0];
    float inv1 = 1.f / l_r[1];
    #pragma unroll
    for (int j = 0; j < 8; j++) {
        int d = j*8 + 2*c;
        size_t t0 = (size_t)(b*S_ + m0 + mr)*D_ + hh*64 + d;
        split_store2(s_y_h, s_y_l, t0,          Oa[j][0]*inv0, Oa[j][1]*inv0);
        split_store2(s_y_h, s_y_l, t0 + 8*D_,   Oa[j][2]*inv1, Oa[j][3]*inv1);
    }
}

// ---------------- host ----------------
template<int BM, int BN, int BK>
constexpr int smem_bytes() {
    return 2 * (2*BM*(BK/2+4) + 2*BN*(BK/2+4)) * 4;
}

extern "C" void kernel_launch(void* const* d_in, const int* in_sizes, int n_in,
                              void* d_out, int out_size) {
    const int*   x      = (const int*)  d_in[0];
    const float* emb    = (const float*)d_in[1];
    const float* wq     = (const float*)d_in[2];
    const float* bq     = (const float*)d_in[3];
    const float* wk     = (const float*)d_in[4];
    const float* bk     = (const float*)d_in[5];
    const float* wv     = (const float*)d_in[6];
    const float* bv     = (const float*)d_in[7];
    const float* wo     = (const float*)d_in[8];
    const float* bo     = (const float*)d_in[9];
    const float* w_gate = (const float*)d_in[10];
    const float* w_up   = (const float*)d_in[11];
    const float* w_down = (const float*)d_in[12];
    const float* ln1    = (const float*)d_in[13];
    const float* ln2    = (const float*)d_in[14];
    const float* norm_w = (const float*)d_in[15];
    float* out = (float*)d_out;

    float *h, *bqkv;
    cudaGetSymbolAddress((void**)&h,    g_h);
    cudaGetSymbolAddress((void**)&bqkv, g_bqkv);

    bf16 *wqkvh,*wqkvl,*woh,*wol,*wguh,*wgul,*wdh,*wdl,*embh,*embl;
    bf16 *hnh,*hnl,*vth,*vtl,*yh,*yl,*gah,*gal;
    cudaGetSymbolAddress((void**)&wqkvh, s_wqkv_h); cudaGetSymbolAddress((void**)&wqkvl, s_wqkv_l);
    cudaGetSymbolAddress((void**)&woh, s_wo_h);  cudaGetSymbolAddress((void**)&wol, s_wo_l);
    cudaGetSymbolAddress((void**)&wguh, s_wgu_h); cudaGetSymbolAddress((void**)&wgul, s_wgu_l);
    cudaGetSymbolAddress((void**)&wdh, s_wd_h);  cudaGetSymbolAddress((void**)&wdl, s_wd_l);
    cudaGetSymbolAddress((void**)&embh, s_emb_h); cudaGetSymbolAddress((void**)&embl, s_emb_l);
    cudaGetSymbolAddress((void**)&hnh, s_hn_h);  cudaGetSymbolAddress((void**)&hnl, s_hn_l);
    cudaGetSymbolAddress((void**)&vth, s_vt_h);  cudaGetSymbolAddress((void**)&vtl, s_vt_l);
    cudaGetSymbolAddress((void**)&yh,  s_y_h);   cudaGetSymbolAddress((void**)&yl,  s_y_l);
    cudaGetSymbolAddress((void**)&gah, s_ga_h);  cudaGetSymbolAddress((void**)&gal, s_ga_l);

    constexpr int SM_S = smem_bytes<128,128,32>();   // 81920
    constexpr int SM_P = smem_bytes<128,64,32>();    // 61440

    cudaFuncSetAttribute(gemm_tc<128,64,32,32,64,EPI_QKV,3>,      cudaFuncAttributeMaxDynamicSharedMemorySize, SM_P);
    cudaFuncSetAttribute(gemm_tc<128,64,32,64,32,EPI_BIAS_RES,3>, cudaFuncAttributeMaxDynamicSharedMemorySize, SM_P);
    cudaFuncSetAttribute(gemm_tc<128,128,32,64,64,EPI_SWIGLU,2>,  cudaFuncAttributeMaxDynamicSharedMemorySize, SM_S);
    cudaFuncSetAttribute(gemm_tc<128,64,32,64,32,EPI_RES,3>,      cudaFuncAttributeMaxDynamicSharedMemorySize, SM_P);
    cudaFuncSetAttribute(gemm_tc<128,128,32,64,64,EPI_NONE,2>,    cudaFuncAttributeMaxDynamicSharedMemorySize, SM_S);
    cudaFuncSetAttribute(flash_attn_kernel,                       cudaFuncAttributeMaxDynamicSharedMemorySize, FA_SMEM);

    // ---- prep ----
    auto split_launch = [](const float* src, bf16* dh, bf16* dl, size_t n) {
        int n4 = (int)(n / 4);
        split_kernel<<<(n4 + 255)/256, 256>>>(src, dh, dl, n4);
    };
    int nw4 = L_*D_*D_/4;
    split_pack_kernel<<<(nw4+255)/256, 256>>>(wq, wqkvh, wqkvl, 0);
    split_pack_kernel<<<(nw4+255)/256, 256>>>(wk, wqkvh, wqkvl, D_);
    split_pack_kernel<<<(nw4+255)/256, 256>>>(wv, wqkvh, wqkvl, 2*D_);
    pack_bias_kernel<<<(L_*3*D_+255)/256, 256>>>(bq, bk, bv, bqkv);
    split_launch(wo, woh, wol, (size_t)L_*D_*D_);
    int ngu4 = L_*DI_*D_/4;
    split_pack_gu_kernel<<<(ngu4+255)/256, 256>>>(w_gate, w_up, wguh, wgul);
    split_launch(w_down, wdh, wdl, (size_t)L_*D_*DI_);
    split_launch(emb, embh, embl, (size_t)V_*D_);

    embed_kernel<<<T_*D_/4/256, 256>>>(x, emb, h);
    rope_cache_kernel<<<(S_*32 + 255)/256, 256>>>();

    const dim3 gqkv(3*D_/64, T_/128, 1);    // 48 x 16, 128 thr
    const dim3 gp(D_/64,   T_/128, 1);      // 16 x 16, 128 thr
    const dim3 ggu(2*DI_/128, T_/128, 1);   // 64 x 16, 128 thr
    const dim3 gfa(S_/64, B_*H_, 1);

    for (int l = 0; l < L_; l++) {
        rmsnorm_kernel<<<T_, 256>>>(h, ln1 + (size_t)l*D_, hnh, hnl);

        // fused QKV + bias + RoPE (q,k) + transposed split V
        gemm_tc<128,64,32,32,64,EPI_QKV,3><<<gqkv,128,SM_P>>>(
            hnh, hnl, wqkvh + (size_t)l*3*D_*D_, wqkvl + (size_t)l*3*D_*D_,
            nullptr, vth, vtl, bqkv + (size_t)l*3*D_,
            T_, 3*D_, D_, D_, D_, 0);

        flash_attn_kernel<<<gfa, 128, FA_SMEM>>>(0.125f);

        gemm_tc<128,64,32,64,32,EPI_BIAS_RES,3><<<gp,128,SM_P>>>(
            yh, yl, woh + (size_t)l*D_*D_, wol + (size_t)l*D_*D_,
            h, nullptr, nullptr, bo + (size_t)l*D_,
            T_, D_, D_, D_, D_, D_);

        rmsnorm_kernel<<<T_, 256>>>(h, ln2 + (size_t)l*D_, hnh, hnl);

        gemm_tc<128,128,32,64,64,EPI_SWIGLU,2><<<ggu,128,SM_S>>>(
            hnh, hnl, wguh + (size_t)l*2*DI_*D_, wgul + (size_t)l*2*DI_*D_,
            nullptr, gah, gal, nullptr,
            T_, 2*DI_, D_, D_, D_, 2*DI_);

        gemm_tc<128,64,32,64,32,EPI_RES,3><<<gp,128,SM_P>>>(
            gah, gal, wdh + (size_t)l*D_*DI_, wdl + (size_t)l*D_*DI_,
            h, nullptr, nullptr, nullptr,
            T_, D_, DI_, DI_, DI_, D_);
    }

    rmsnorm_kernel<<<T_, 256>>>(h, norm_w, hnh, hnl);

    const dim3 gl(V_/128, T_/128, 1);
    gemm_tc<128,128,32,64,64,EPI_NONE,2><<<gl,128,SM_S>>>(
        hnh, hnl, embh, embl, out, nullptr, nullptr, nullptr,
        T_, V_, D_, D_, D_, V_);
}

// round 15
// speedup vs baseline: 1.5418x; 1.0327x over previous
#include <cuda_runtime.h>
#include <cuda_bf16.h>
#include <cstdint>
#include <math.h>

#define L_  8
#define D_  1024
#define H_  16
#define DH_ 64
#define DI_ 4096
#define V_  32000
#define B_  2
#define S_  1024
#define T_  (B_*S_)

typedef __nv_bfloat16 bf16;

// ---------------- fp32 scratch ----------------
__device__ float g_h   [T_*D_];
__device__ float g_cos [S_*32];
__device__ float g_sin [S_*32];
__device__ float g_bqkv[L_*3*D_];

// ---------------- split bf16 scratch (hi/lo) ----------------
__device__ bf16 s_wqkv_h[L_*3*D_*D_], s_wqkv_l[L_*3*D_*D_];
__device__ bf16 s_wo_h[L_*D_*D_],   s_wo_l[L_*D_*D_];
__device__ bf16 s_wgu_h[(size_t)L_*2*DI_*D_], s_wgu_l[(size_t)L_*2*DI_*D_];
__device__ bf16 s_wd_h[L_*D_*DI_],  s_wd_l[L_*D_*DI_];
__device__ bf16 s_emb_h[V_*D_],     s_emb_l[V_*D_];
__device__ bf16 s_hn_h[T_*D_],      s_hn_l[T_*D_];
__device__ bf16 s_q_h [T_*D_],      s_q_l [T_*D_];
__device__ bf16 s_k_h [T_*D_],      s_k_l [T_*D_];
__device__ bf16 s_vt_h[T_*D_],      s_vt_l[T_*D_];
__device__ bf16 s_y_h [T_*D_],      s_y_l [T_*D_];
__device__ bf16 s_ga_h[T_*DI_],     s_ga_l[T_*DI_];

// ---------------- helpers ----------------
__device__ __forceinline__ void split1(float v, bf16& h, bf16& l) {
    h = __float2bfloat16(v);
    l = __float2bfloat16(v - __bfloat162float(h));
}

__device__ __forceinline__ void split_store2(bf16* H, bf16* Lo, size_t off, float v0, float v1) {
    bf16 h0, l0, h1, l1;
    split1(v0, h0, l0);
    split1(v1, h1, l1);
    __nv_bfloat162 th; th.x = h0; th.y = h1;
    __nv_bfloat162 tl; tl.x = l0; tl.y = l1;
    *(__nv_bfloat162*)(H  + off) = th;
    *(__nv_bfloat162*)(Lo + off) = tl;
}

__device__ __forceinline__ void splitpack2(float a, float b, uint32_t& h, uint32_t& l) {
    bf16 ha, la, hb, lb;
    split1(a, ha, la);
    split1(b, hb, lb);
    h = ((uint32_t)__bfloat16_as_ushort(hb) << 16) | __bfloat16_as_ushort(ha);
    l = ((uint32_t)__bfloat16_as_ushort(lb) << 16) | __bfloat16_as_ushort(la);
}

__global__ void split_kernel(const float* __restrict__ x, bf16* __restrict__ h,
                             bf16* __restrict__ l, int n4) {
    int i = blockIdx.x * blockDim.x + threadIdx.x;
    if (i >= n4) return;
    float4 v = ((const float4*)x)[i];
    bf16 h0,l0,h1,l1,h2,l2,h3,l3;
    split1(v.x, h0, l0); split1(v.y, h1, l1);
    split1(v.z, h2, l2); split1(v.w, h3, l3);
    ((ushort4*)h)[i] = make_ushort4(__bfloat16_as_ushort(h0), __bfloat16_as_ushort(h1),
                                    __bfloat16_as_ushort(h2), __bfloat16_as_ushort(h3));
    ((ushort4*)l)[i] = make_ushort4(__bfloat16_as_ushort(l0), __bfloat16_as_ushort(l1),
                                    __bfloat16_as_ushort(l2), __bfloat16_as_ushort(l3));
}

__global__ void split_pack_kernel(const float* __restrict__ x, bf16* __restrict__ h,
                                  bf16* __restrict__ l, int row_off) {
    int i = blockIdx.x * blockDim.x + threadIdx.x;
    if (i >= L_*D_*D_/4) return;
    int lay = i / (D_*D_/4);
    int rem = i % (D_*D_/4);
    int r   = rem / (D_/4);
    int c4  = rem % (D_/4);
    float4 v = ((const float4*)x)[i];
    int d4 = lay*(3*D_*D_/4) + (row_off + r)*(D_/4) + c4;
    bf16 h0,l0,h1,l1,h2,l2,h3,l3;
    split1(v.x, h0, l0); split1(v.y, h1, l1);
    split1(v.z, h2, l2); split1(v.w, h3, l3);
    ((ushort4*)h)[d4] = make_ushort4(__bfloat16_as_ushort(h0), __bfloat16_as_ushort(h1),
                                     __bfloat16_as_ushort(h2), __bfloat16_as_ushort(h3));
    ((ushort4*)l)[d4] = make_ushort4(__bfloat16_as_ushort(l0), __bfloat16_as_ushort(l1),
                                     __bfloat16_as_ushort(l2), __bfloat16_as_ushort(l3));
}

__global__ void split_pack_gu_kernel(const float* __restrict__ wg, const float* __restrict__ wu,
                                     bf16* __restrict__ h, bf16* __restrict__ l) {
    int i = blockIdx.x * blockDim.x + threadIdx.x;
    if (i >= L_*DI_*D_/4) return;
    int lay = i / (DI_*D_/4);
    int rem = i % (DI_*D_/4);
    int r   = rem / (D_/4);
    int c4  = rem % (D_/4);
    float4 vg = ((const float4*)wg)[i];
    float4 vu = ((const float4*)wu)[i];
    size_t base = (size_t)lay*(2*DI_*D_/4);
    size_t dg = base + (size_t)(2*r)  *(D_/4) + c4;
    size_t du = base + (size_t)(2*r+1)*(D_/4) + c4;
    bf16 h0,l0,h1,l1,h2,l2,h3,l3;
    split1(vg.x, h0, l0); split1(vg.y, h1, l1);
    split1(vg.z, h2, l2); split1(vg.w, h3, l3);
    ((ushort4*)h)[dg] = make_ushort4(__bfloat16_as_ushort(h0), __bfloat16_as_ushort(h1),
                                     __bfloat16_as_ushort(h2), __bfloat16_as_ushort(h3));
    ((ushort4*)l)[dg] = make_ushort4(__bfloat16_as_ushort(l0), __bfloat16_as_ushort(l1),
                                     __bfloat16_as_ushort(l2), __bfloat16_as_ushort(l3));
    split1(vu.x, h0, l0); split1(vu.y, h1, l1);
    split1(vu.z, h2, l2); split1(vu.w, h3, l3);
    ((ushort4*)h)[du] = make_ushort4(__bfloat16_as_ushort(h0), __bfloat16_as_ushort(h1),
                                     __bfloat16_as_ushort(h2), __bfloat16_as_ushort(h3));
    ((ushort4*)l)[du] = make_ushort4(__bfloat16_as_ushort(l0), __bfloat16_as_ushort(l1),
                                     __bfloat16_as_ushort(l2), __bfloat16_as_ushort(l3));
}

__global__ void pack_bias_kernel(const float* __restrict__ bq, const float* __restrict__ bk,
                                 const float* __restrict__ bv, float* __restrict__ dst) {
    int i = blockIdx.x * blockDim.x + threadIdx.x;
    if (i >= L_*3*D_) return;
    int lay = i / (3*D_);
    int j   = i % (3*D_);
    float v = (j < D_) ? bq[lay*D_ + j]
            : (j < 2*D_) ? bk[lay*D_ + j - D_]
            : bv[lay*D_ + j - 2*D_];
    dst[i] = v;
}

// ---------------- small kernels ----------------
__global__ void embed_kernel(const int* __restrict__ x, const float* __restrict__ emb,
                             float* __restrict__ h) {
    int i = blockIdx.x * blockDim.x + threadIdx.x;
    int t = i / (D_/4);
    int c = i % (D_/4);
    float4 v = *(const float4*)(emb + (size_t)x[t]*D_ + c*4);
    *(float4*)(h + (size_t)t*D_ + c*4) = v;
}

__global__ void rope_cache_kernel() {
    int i = blockIdx.x * blockDim.x + threadIdx.x;
    if (i >= S_*32) return;
    int s = i / 32, j = i % 32;
    double inv = pow(10000.0, -(double)j / 32.0);
    double ph = (double)s * inv;
    g_cos[i] = (float)cos(ph);
    g_sin[i] = (float)sin(ph);
}

__global__ void rmsnorm_kernel(const float* __restrict__ x, const float* __restrict__ w,
                               bf16* __restrict__ oh, bf16* __restrict__ ol) {
    int t = blockIdx.x;
    int tid = threadIdx.x;
    const float* xp = x + (size_t)t*D_;
    float v[4];
    float s = 0.f;
    #pragma unroll
    for (int i = 0; i < 4; i++) { v[i] = xp[tid + i*256]; s += v[i]*v[i]; }
    #pragma unroll
    for (int off = 16; off; off >>= 1) s += __shfl_xor_sync(0xffffffffu, s, off);
    __shared__ float red[8];
    if ((tid & 31) == 0) red[tid >> 5] = s;
    __syncthreads();
    if (tid < 32) {
        float s2 = (tid < 8) ? red[tid] : 0.f;
        #pragma unroll
        for (int off = 4; off; off >>= 1) s2 += __shfl_xor_sync(0xffffffffu, s2, off);
        if (tid == 0) red[0] = s2;
    }
    __syncthreads();
    float r = rsqrtf(red[0] * (1.f/(float)D_) + 1e-6f);
    size_t base = (size_t)t*D_;
    #pragma unroll
    for (int i = 0; i < 4; i++) {
        int idx = tid + i*256;
        split1(w[idx] * v[i] * r, oh[base+idx], ol[base+idx]);
    }
}

// ---------------- bf16x3 GEMM on pre-split operands ----------------
enum { EPI_NONE = 0, EPI_BIAS_RES_AT = 2, EPI_RES_AT = 3,
       EPI_QKV = 8, EPI_SWIGLU = 9 };

__device__ __forceinline__ void mma_bf16(float* d, const uint32_t* a, const uint32_t* b) {
    asm volatile(
        "mma.sync.aligned.m16n8k16.row.col.f32.bf16.bf16.f32 "
        "{%0,%1,%2,%3}, {%4,%5,%6,%7}, {%8,%9}, {%0,%1,%2,%3};\n"
        : "+f"(d[0]), "+f"(d[1]), "+f"(d[2]), "+f"(d[3])
        : "r"(a[0]), "r"(a[1]), "r"(a[2]), "r"(a[3]),
          "r"(b[0]), "r"(b[1]));
}

#define CP_ASYNC16(dst, src) \
    asm volatile("cp.async.cg.shared.global [%0], [%1], 16;" :: "r"(dst), "l"(src))
#define CP_COMMIT() asm volatile("cp.async.commit_group;" ::: "memory")
#define CP_WAIT0()  asm volatile("cp.async.wait_group 0;"  ::: "memory")

// SPLITK: blockIdx.z indexes a K-range of size K/SPLITK; atomic epilogues accumulate.
template<int BM, int BN, int BK, int WM, int WN, int EPI, int MINB, int SPLITK>
__global__ __launch_bounds__((BM/WM)*(BN/WN)*32, MINB)
void gemm_tc(const bf16* __restrict__ Agh, const bf16* __restrict__ Agl,
             const bf16* __restrict__ Bgh, const bf16* __restrict__ Bgl,
             float* __restrict__ C, bf16* __restrict__ Oh, bf16* __restrict__ Ol,
             const float* __restrict__ bias,
             int M, int N, int K, int lda, int ldb, int ldc)
{
    constexpr int WARPS_N = BN/WN;
    constexpr int THREADS = (BM/WM)*(BN/WN)*32;
    constexpr int MT = WM/16;
    constexpr int NT = WN/8;
    constexpr int SP = BK/2 + 4;
    constexpr int SZA = BM*SP;
    constexpr int SZB = BN*SP;
    constexpr int STAGE = 2*SZA + 2*SZB;
    constexpr int NCA = (BM*BK/8)/THREADS;
    constexpr int NCB = (BN*BK/8)/THREADS;

    extern __shared__ uint32_t smem_u[];

    const int tid = threadIdx.x;
    const int m0 = blockIdx.y * BM;
    const int n0 = blockIdx.x * BN;
    const int KS   = K / SPLITK;
    const int Kofs = blockIdx.z * KS;

    const int warp = tid >> 5;
    const int lane = tid & 31;
    const int g = lane >> 2;
    const int c = lane & 3;
    const int wn = warp % WARPS_N;
    const int wm = warp / WARPS_N;

    float acc[MT][NT][4];
    #pragma unroll
    for (int i = 0; i < MT; i++)
        #pragma unroll
        for (int j = 0; j < NT; j++)
            #pragma unroll
            for (int r = 0; r < 4; r++) acc[i][j][r] = 0.f;

    const int nk = KS / BK;

    const uint32_t smb = (uint32_t)__cvta_generic_to_shared(smem_u);
    auto cp_tile = [&](int kt, int s) {
        const uint32_t Ah = smb + s*STAGE*4;
        const uint32_t Al = Ah + SZA*4;
        const uint32_t Bh = Al + SZA*4;
        const uint32_t Bl = Bh + SZB*4;
        #pragma unroll
        for (int i = 0; i < NCA; i++) {
            int f  = tid + i*THREADS;
            int r  = f / (BK/8);
            int c8 = f % (BK/8);
            size_t   go = (size_t)(m0+r)*lda + Kofs + kt + c8*8;
            uint32_t so = (uint32_t)(r*SP + c8*4)*4;
            CP_ASYNC16(Ah + so, Agh + go);
            CP_ASYNC16(Al + so, Agl + go);
        }
        #pragma unroll
        for (int i = 0; i < NCB; i++) {
            int f  = tid + i*THREADS;
            int r  = f / (BK/8);
            int c8 = f % (BK/8);
            size_t   go = (size_t)(n0+r)*ldb + Kofs + kt + c8*8;
            uint32_t so = (uint32_t)(r*SP + c8*4)*4;
            CP_ASYNC16(Bh + so, Bgh + go);
            CP_ASYNC16(Bl + so, Bgl + go);
        }
        CP_COMMIT();
    };

    auto compute_stage = [&](int cur) {
        const uint32_t* Ah = smem_u + cur*STAGE;
        const uint32_t* Al = Ah + SZA;
        const uint32_t* Bh = Al + SZA;
        const uint32_t* Bl = Bh + SZB;
        #pragma unroll
        for (int ks = 0; ks < BK; ks += 16) {
            const int kp = ks >> 1;
            uint32_t ah[MT][4], al[MT][4], bh[NT][2], bl[NT][2];
            #pragma unroll
            for (int i = 0; i < MT; i++) {
                int mr = wm*WM + i*16 + g;
                ah[i][0] = Ah[mr*SP     + kp + c];   al[i][0] = Al[mr*SP     + kp + c];
                ah[i][1] = Ah[(mr+8)*SP + kp + c];   al[i][1] = Al[(mr+8)*SP + kp + c];
                ah[i][2] = Ah[mr*SP     + kp + c+4]; al[i][2] = Al[mr*SP     + kp + c+4];
                ah[i][3] = Ah[(mr+8)*SP + kp + c+4]; al[i][3] = Al[(mr+8)*SP + kp + c+4];
            }
            #pragma unroll
            for (int j = 0; j < NT; j++) {
                int nr = wn*WN + j*8 + g;
                bh[j][0] = Bh[nr*SP + kp + c];   bl[j][0] = Bl[nr*SP + kp + c];
                bh[j][1] = Bh[nr*SP + kp + c+4]; bl[j][1] = Bl[nr*SP + kp + c+4];
            }
            #pragma unroll
            for (int i = 0; i < MT; i++)
                #pragma unroll
                for (int j = 0; j < NT; j++)
                    mma_bf16(acc[i][j], ah[i], bh[j]);
            #pragma unroll
            for (int i = 0; i < MT; i++)
                #pragma unroll
                for (int j = 0; j < NT; j++)
                    mma_bf16(acc[i][j], ah[i], bl[j]);
            #pragma unroll
            for (int i = 0; i < MT; i++)
                #pragma unroll
                for (int j = 0; j < NT; j++)
                    mma_bf16(acc[i][j], al[i], bh[j]);
        }
    };

    cp_tile(0, 0);
    CP_WAIT0();
    __syncthreads();

    for (int t = 0; t < nk; t++) {
        const int cur = t & 1;
        if (t + 1 < nk) cp_tile((t+1)*BK, cur ^ 1);
        compute_stage(cur);
        if (t + 1 < nk) CP_WAIT0();
        __syncthreads();
    }

    // ---------------- epilogues ----------------
    if (EPI == EPI_QKV) {
        if (n0 < 2*D_) {
            const bool isq = (n0 < D_);
            #pragma unroll
            for (int i = 0; i < MT; i++) {
                #pragma unroll
                for (int jj = 0; jj < NT/2; jj++) {
                    #pragma unroll
                    for (int rr = 0; rr < 2; rr++) {
                        int m = m0 + wm*WM + i*16 + g + rr*8;
                        int s = m & (S_-1);
                        #pragma unroll
                        for (int t2 = 0; t2 < 2; t2++) {
                            int n = n0 + jj*8 + 2*c + t2;
                            float a  = acc[i][jj]  [rr*2+t2] + bias[n];
                            float bb = acc[i][jj+4][rr*2+t2] + bias[n+32];
                            int d = n & 63;
                            float co = g_cos[s*32 + d];
                            float si = g_sin[s*32 + d];
                            float r0 = a*co - bb*si;
                            float r1 = bb*co + a*si;
                            int col = isq ? (n & (D_-1)) : (n - D_);
                            size_t o = (size_t)m*D_ + col;
                            if (isq) {
                                split1(r0, s_q_h[o],    s_q_l[o]);
                                split1(r1, s_q_h[o+32], s_q_l[o+32]);
                            } else {
                                split1(r0, s_k_h[o],    s_k_l[o]);
                                split1(r1, s_k_h[o+32], s_k_l[o+32]);
                            }
                        }
                    }
                }
            }
        } else {
            #pragma unroll
            for (int i = 0; i < MT; i++) {
                #pragma unroll
                for (int j = 0; j < NT; j++) {
                    int n = n0 + wn*WN + j*8 + 2*c;
                    #pragma unroll
                    for (int rr = 0; rr < 2; rr++) {
                        int m = m0 + wm*WM + i*16 + g + rr*8;
                        float v0 = acc[i][j][rr*2]   + bias[n];
                        float v1 = acc[i][j][rr*2+1] + bias[n+1];
                        int dg = n - 2*D_;
                        int hh = dg >> 6, dd = dg & 63;
                        int b  = m >> 10, s = m & 1023;
                        size_t o0 = (((size_t)b*H_ + hh)*DH_ + dd)*S_ + s;
                        split1(v0, Oh[o0],    Ol[o0]);
                        split1(v1, Oh[o0+S_], Ol[o0+S_]);
                    }
                }
            }
        }
        return;
    }

    #pragma unroll
    for (int i = 0; i < MT; i++) {
        #pragma unroll
        for (int j = 0; j < NT; j++) {
            int n = n0 + wn*WN + j*8 + 2*c;
            #pragma unroll
            for (int rr = 0; rr < 2; rr++) {
                int m = m0 + wm*WM + i*16 + g + rr*8;
                float v0 = acc[i][j][rr*2 + 0];
                float v1 = acc[i][j][rr*2 + 1];
                if (EPI == EPI_SWIGLU) {
                    float sw = v0 / (1.f + expf(-v0)) * v1;
                    size_t oo = (size_t)m*(ldc >> 1) + (n >> 1);
                    split1(sw, Oh[oo], Ol[oo]);
                    continue;
                }
                size_t off = (size_t)m*ldc + n;
                if (EPI == EPI_BIAS_RES_AT) {
                    if (SPLITK == 1 || blockIdx.z == 0) { v0 += bias[n]; v1 += bias[n+1]; }
                    atomicAdd(C + off,     v0);
                    atomicAdd(C + off + 1, v1);
                } else if (EPI == EPI_RES_AT) {
                    atomicAdd(C + off,     v0);
                    atomicAdd(C + off + 1, v1);
                } else if (EPI == EPI_NONE) {
                    *(float2*)(C + off) = make_float2(v0, v1);
                }
            }
        }
    }
}

// ================== flash attention ==================
#define FA_SP 36
#define FA_TW (64*FA_SP)
#define FA_SMEM ((2*FA_TW + 2*4*FA_TW)*4)

__global__ __launch_bounds__(128, 2)
void flash_attn_kernel(float scale)
{
    extern __shared__ uint32_t sm[];
    const int tid  = threadIdx.x;
    const int warp = tid >> 5;
    const int lane = tid & 31;
    const int g = lane >> 2;
    const int c = lane & 3;
    const int mb = blockIdx.x;
    const int bh = blockIdx.y;
    const int b  = bh >> 4;
    const int hh = bh & 15;
    const int m0 = mb * 64;

    const uint32_t smb = (uint32_t)__cvta_generic_to_shared(sm);
    uint32_t* sQh = sm;
    uint32_t* sQl = sm + FA_TW;

    const size_t vbase = (size_t)bh * DH_ * S_;

    #pragma unroll
    for (int i = 0; i < 4; i++) {
        int f = tid + i*128;
        int r = f >> 3, c8 = f & 7;
        size_t go = ((size_t)(b*S_ + m0 + r))*D_ + hh*64 + c8*8;
        uint32_t so = (uint32_t)(r*FA_SP + c8*4)*4;
        CP_ASYNC16(smb + so,             s_q_h + go);
        CP_ASYNC16(smb + FA_TW*4 + so,   s_q_l + go);
    }

    auto cp_kv = [&](int kb, int s) {
        uint32_t kvb = smb + (2*FA_TW + s*4*FA_TW)*4;
        #pragma unroll
        for (int i = 0; i < 4; i++) {
            int f = tid + i*128;
            int r = f >> 3, c8 = f & 7;
            uint32_t so = (uint32_t)(r*FA_SP + c8*4)*4;
            size_t gok = ((size_t)(b*S_ + kb*64 + r))*D_ + hh*64 + c8*8;
            CP_ASYNC16(kvb + so,             s_k_h + gok);
            CP_ASYNC16(kvb + FA_TW*4 + so,   s_k_l + gok);
            size_t gov = vbase + (size_t)r*S_ + kb*64 + c8*8;
            CP_ASYNC16(kvb + 2*FA_TW*4 + so, s_vt_h + gov);
            CP_ASYNC16(kvb + 3*FA_TW*4 + so, s_vt_l + gov);
        }
        CP_COMMIT();
    };

    cp_kv(0, 0);
    CP_WAIT0();
    __syncthreads();

    float m_r[2] = {-INFINITY, -INFINITY};
    float l_r[2] = {0.f, 0.f};
    float Oa[8][4];
    #pragma unroll
    for (int j = 0; j < 8; j++)
        #pragma unroll
        for (int r = 0; r < 4; r++) Oa[j][r] = 0.f;

    const int mr = warp*16 + g;

    for (int kb = 0; kb <= mb; kb++) {
        const int cur = kb & 1;
        if (kb < mb) cp_kv(kb+1, cur ^ 1);

        float Sa[8][4];
        #pragma unroll
        for (int j = 0; j < 8; j++)
            #pragma unroll
            for (int r = 0; r < 4; r++) Sa[j][r] = 0.f;

        {
            const uint32_t* Bh = sm + 2*FA_TW + cur*4*FA_TW;
            const uint32_t* Bl = Bh + FA_TW;
            #pragma unroll
            for (int ks = 0; ks < 64; ks += 16) {
                const int kp = ks >> 1;
                uint32_t ah[4], al[4], bh[8][2], bl[8][2];
                ah[0] = sQh[mr*FA_SP     + kp + c];   al[0] = sQl[mr*FA_SP     + kp + c];
                ah[1] = sQh[(mr+8)*FA_SP + kp + c];   al[1] = sQl[(mr+8)*FA_SP + kp + c];
                ah[2] = sQh[mr*FA_SP     + kp + c+4]; al[2] = sQl[mr*FA_SP     + kp + c+4];
                ah[3] = sQh[(mr+8)*FA_SP + kp + c+4]; al[3] = sQl[(mr+8)*FA_SP + kp + c+4];
                #pragma unroll
                for (int j = 0; j < 8; j++) {
                    int nr = j*8 + g;
                    bh[j][0] = Bh[nr*FA_SP + kp + c];   bl[j][0] = Bl[nr*FA_SP + kp + c];
                    bh[j][1] = Bh[nr*FA_SP + kp + c+4]; bl[j][1] = Bl[nr*FA_SP + kp + c+4];
                }
                #pragma unroll
                for (int j = 0; j < 8; j++) mma_bf16(Sa[j], ah, bh[j]);
                #pragma unroll
                for (int j = 0; j < 8; j++) mma_bf16(Sa[j], ah, bl[j]);
                #pragma unroll
                for (int j = 0; j < 8; j++) mma_bf16(Sa[j], al, bh[j]);
            }
        }

        #pragma unroll
        for (int j = 0; j < 8; j++)
            #pragma unroll
            for (int r = 0; r < 4; r++) Sa[j][r] *= scale;
        if (kb == mb) {
            #pragma unroll
            for (int j = 0; j < 8; j++) {
                int col = kb*64 + j*8 + 2*c;
                #pragma unroll
                for (int rr = 0; rr < 2; rr++) {
                    int row = m0 + mr + rr*8;
                    if (col     > row) Sa[j][rr*2]   = -INFINITY;
                    if (col + 1 > row) Sa[j][rr*2+1] = -INFINITY;
                }
            }
        }

        #pragma unroll
        for (int rr = 0; rr < 2; rr++) {
            float mx = -INFINITY;
            #pragma unroll
            for (int j = 0; j < 8; j++)
                mx = fmaxf(mx, fmaxf(Sa[j][rr*2], Sa[j][rr*2+1]));
            mx = fmaxf(mx, __shfl_xor_sync(0xffffffffu, mx, 1));
            mx = fmaxf(mx, __shfl_xor_sync(0xffffffffu, mx, 2));
            float mnew  = fmaxf(m_r[rr], mx);
            float alpha = expf(m_r[rr] - mnew);
            float sum = 0.f;
            #pragma unroll
            for (int j = 0; j < 8; j++) {
                float p0 = expf(Sa[j][rr*2]   - mnew);
                float p1 = expf(Sa[j][rr*2+1] - mnew);
                Sa[j][rr*2] = p0; Sa[j][rr*2+1] = p1;
                sum += p0 + p1;
            }
            sum += __shfl_xor_sync(0xffffffffu, sum, 1);
            sum += __shfl_xor_sync(0xffffffffu, sum, 2);
            l_r[rr] = l_r[rr]*alpha + sum;
            m_r[rr] = mnew;
            #pragma unroll
            for (int j = 0; j < 8; j++) {
                Oa[j][rr*2]   *= alpha;
                Oa[j][rr*2+1] *= alpha;
            }
        }

        {
            const uint32_t* Vh = sm + 2*FA_TW + cur*4*FA_TW + 2*FA_TW;
            const uint32_t* Vl = Vh + FA_TW;
            #pragma unroll
            for (int ks = 0; ks < 64; ks += 16) {
                const int j0 = ks >> 3;
                const int kp = ks >> 1;
                uint32_t ph[4], pl[4];
                splitpack2(Sa[j0][0],   Sa[j0][1],   ph[0], pl[0]);
                splitpack2(Sa[j0][2],   Sa[j0][3],   ph[1], pl[1]);
                splitpack2(Sa[j0+1][0], Sa[j0+1][1], ph[2], pl[2]);
                splitpack2(Sa[j0+1][2], Sa[j0+1][3], ph[3], pl[3]);
                uint32_t bh[8][2], bl[8][2];
                #pragma unroll
                for (int j = 0; j < 8; j++) {
                    int nr = j*8 + g;
                    bh[j][0] = Vh[nr*FA_SP + kp + c];   bl[j][0] = Vl[nr*FA_SP + kp + c];
                    bh[j][1] = Vh[nr*FA_SP + kp + c+4]; bl[j][1] = Vl[nr*FA_SP + kp + c+4];
                }
                #pragma unroll
                for (int j = 0; j < 8; j++) mma_bf16(Oa[j], ph, bh[j]);
                #pragma unroll
                for (int j = 0; j < 8; j++) mma_bf16(Oa[j], ph, bl[j]);
                #pragma unroll
                for (int j = 0; j < 8; j++) mma_bf16(Oa[j], pl, bh[j]);
            }
        }

        if (kb < mb) CP_WAIT0();
        __syncthreads();
    }

    float inv0 = 1.f / l_r[0];
    float inv1 = 1.f / l_r[1];
    #pragma unroll
    for (int j = 0; j < 8; j++) {
        int d = j*8 + 2*c;
        size_t t0 = (size_t)(b*S_ + m0 + mr)*D_ + hh*64 + d;
        split_store2(s_y_h, s_y_l, t0,          Oa[j][0]*inv0, Oa[j][1]*inv0);
        split_store2(s_y_h, s_y_l, t0 + 8*D_,   Oa[j][2]*inv1, Oa[j][3]*inv1);
    }
}

// ---------------- host ----------------
template<int BM, int BN, int BK>
constexpr int smem_bytes() {
    return 2 * (2*BM*(BK/2+4) + 2*BN*(BK/2+4)) * 4;
}

extern "C" void kernel_launch(void* const* d_in, const int* in_sizes, int n_in,
                              void* d_out, int out_size) {
    const int*   x      = (const int*)  d_in[0];
    const float* emb    = (const float*)d_in[1];
    const float* wq     = (const float*)d_in[2];
    const float* bq     = (const float*)d_in[3];
    const float* wk     = (const float*)d_in[4];
    const float* bk     = (const float*)d_in[5];
    const float* wv     = (const float*)d_in[6];
    const float* bv     = (const float*)d_in[7];
    const float* wo     = (const float*)d_in[8];
    const float* bo     = (const float*)d_in[9];
    const float* w_gate = (const float*)d_in[10];
    const float* w_up   = (const float*)d_in[11];
    const float* w_down = (const float*)d_in[12];
    const float* ln1    = (const float*)d_in[13];
    const float* ln2    = (const float*)d_in[14];
    const float* norm_w = (const float*)d_in[15];
    float* out = (float*)d_out;

    float *h, *bqkv;
    cudaGetSymbolAddress((void**)&h,    g_h);
    cudaGetSymbolAddress((void**)&bqkv, g_bqkv);

    bf16 *wqkvh,*wqkvl,*woh,*wol,*wguh,*wgul,*wdh,*wdl,*embh,*embl;
    bf16 *hnh,*hnl,*vth,*vtl,*yh,*yl,*gah,*gal;
    cudaGetSymbolAddress((void**)&wqkvh, s_wqkv_h); cudaGetSymbolAddress((void**)&wqkvl, s_wqkv_l);
    cudaGetSymbolAddress((void**)&woh, s_wo_h);  cudaGetSymbolAddress((void**)&wol, s_wo_l);
    cudaGetSymbolAddress((void**)&wguh, s_wgu_h); cudaGetSymbolAddress((void**)&wgul, s_wgu_l);
    cudaGetSymbolAddress((void**)&wdh, s_wd_h);  cudaGetSymbolAddress((void**)&wdl, s_wd_l);
    cudaGetSymbolAddress((void**)&embh, s_emb_h); cudaGetSymbolAddress((void**)&embl, s_emb_l);
    cudaGetSymbolAddress((void**)&hnh, s_hn_h);  cudaGetSymbolAddress((void**)&hnl, s_hn_l);
    cudaGetSymbolAddress((void**)&vth, s_vt_h);  cudaGetSymbolAddress((void**)&vtl, s_vt_l);
    cudaGetSymbolAddress((void**)&yh,  s_y_h);   cudaGetSymbolAddress((void**)&yl,  s_y_l);
    cudaGetSymbolAddress((void**)&gah, s_ga_h);  cudaGetSymbolAddress((void**)&gal, s_ga_l);

    constexpr int SM_S = smem_bytes<128,128,32>();   // 81920
    constexpr int SM_P = smem_bytes<128,64,32>();    // 61440

    cudaFuncSetAttribute(gemm_tc<128,64,32,32,64,EPI_QKV,3,1>,         cudaFuncAttributeMaxDynamicSharedMemorySize, SM_P);
    cudaFuncSetAttribute(gemm_tc<128,64,32,64,32,EPI_BIAS_RES_AT,3,2>, cudaFuncAttributeMaxDynamicSharedMemorySize, SM_P);
    cudaFuncSetAttribute(gemm_tc<128,128,32,64,64,EPI_SWIGLU,2,1>,     cudaFuncAttributeMaxDynamicSharedMemorySize, SM_S);
    cudaFuncSetAttribute(gemm_tc<128,64,32,64,32,EPI_RES_AT,3,2>,      cudaFuncAttributeMaxDynamicSharedMemorySize, SM_P);
    cudaFuncSetAttribute(gemm_tc<128,128,32,64,64,EPI_NONE,2,1>,       cudaFuncAttributeMaxDynamicSharedMemorySize, SM_S);
    cudaFuncSetAttribute(flash_attn_kernel,                            cudaFuncAttributeMaxDynamicSharedMemorySize, FA_SMEM);

    // ---- prep ----
    auto split_launch = [](const float* src, bf16* dh, bf16* dl, size_t n) {
        int n4 = (int)(n / 4);
        split_kernel<<<(n4 + 255)/256, 256>>>(src, dh, dl, n4);
    };
    int nw4 = L_*D_*D_/4;
    split_pack_kernel<<<(nw4+255)/256, 256>>>(wq, wqkvh, wqkvl, 0);
    split_pack_kernel<<<(nw4+255)/256, 256>>>(wk, wqkvh, wqkvl, D_);
    split_pack_kernel<<<(nw4+255)/256, 256>>>(wv, wqkvh, wqkvl, 2*D_);
    pack_bias_kernel<<<(L_*3*D_+255)/256, 256>>>(bq, bk, bv, bqkv);
    split_launch(wo, woh, wol, (size_t)L_*D_*D_);
    int ngu4 = L_*DI_*D_/4;
    split_pack_gu_kernel<<<(ngu4+255)/256, 256>>>(w_gate, w_up, wguh, wgul);
    split_launch(w_down, wdh, wdl, (size_t)L_*D_*DI_);
    split_launch(emb, embh, embl, (size_t)V_*D_);

    embed_kernel<<<T_*D_/4/256, 256>>>(x, emb, h);
    rope_cache_kernel<<<(S_*32 + 255)/256, 256>>>();

    const dim3 gqkv(3*D_/64, T_/128, 1);
    const dim3 gpz(D_/64,  T_/128, 2);       // split-K x2: 512 blocks
    const dim3 ggu(2*DI_/128, T_/128, 1);
    const dim3 gfa(S_/64, B_*H_, 1);

    for (int l = 0; l < L_; l++) {
        rmsnorm_kernel<<<T_, 256>>>(h, ln1 + (size_t)l*D_, hnh, hnl);

        gemm_tc<128,64,32,32,64,EPI_QKV,3,1><<<gqkv,128,SM_P>>>(
            hnh, hnl, wqkvh + (size_t)l*3*D_*D_, wqkvl + (size_t)l*3*D_*D_,
            nullptr, vth, vtl, bqkv + (size_t)l*3*D_,
            T_, 3*D_, D_, D_, D_, 0);

        flash_attn_kernel<<<gfa, 128, FA_SMEM>>>(0.125f);

        gemm_tc<128,64,32,64,32,EPI_BIAS_RES_AT,3,2><<<gpz,128,SM_P>>>(
            yh, yl, woh + (size_t)l*D_*D_, wol + (size_t)l*D_*D_,
            h, nullptr, nullptr, bo + (size_t)l*D_,
            T_, D_, D_, D_, D_, D_);

        rmsnorm_kernel<<<T_, 256>>>(h, ln2 + (size_t)l*D_, hnh, hnl);

        gemm_tc<128,128,32,64,64,EPI_SWIGLU,2,1><<<ggu,128,SM_S>>>(
            hnh, hnl, wguh + (size_t)l*2*DI_*D_, wgul + (size_t)l*2*DI_*D_,
            nullptr, gah, gal, nullptr,
            T_, 2*DI_, D_, D_, D_, 2*DI_);

        gemm_tc<128,64,32,64,32,EPI_RES_AT,3,2><<<gpz,128,SM_P>>>(
            gah, gal, wdh + (size_t)l*D_*DI_, wdl + (size_t)l*D_*DI_,
            h, nullptr, nullptr, nullptr,
            T_, D_, DI_, DI_, DI_, D_);
    }

    rmsnorm_kernel<<<T_, 256>>>(h, norm_w, hnh, hnl);

    const dim3 gl(V_/128, T_/128, 1);
    gemm_tc<128,128,32,64,64,EPI_NONE,2,1><<<gl,128,SM_S>>>(
        hnh, hnl, embh, embl, out, nullptr, nullptr, nullptr,
        T_, V_, D_, D_, D_, V_);
}

// round 16
// speedup vs baseline: 1.5799x; 1.0247x over previous
#include <cuda_runtime.h>
#include <cuda_bf16.h>
#include <cstdint>
#include <math.h>

#define L_  8
#define D_  1024
#define H_  16
#define DH_ 64
#define DI_ 4096
#define V_  32000
#define B_  2
#define S_  1024
#define T_  (B_*S_)

typedef __nv_bfloat16 bf16;

// ---------------- fp32 scratch ----------------
__device__ float g_h   [T_*D_];
__device__ float g_cos [S_*32];
__device__ float g_sin [S_*32];
__device__ float g_bqkv[L_*3*D_];

// ---------------- split bf16 scratch (hi/lo) ----------------
__device__ bf16 s_wqkv_h[L_*3*D_*D_], s_wqkv_l[L_*3*D_*D_];
__device__ bf16 s_wo_h[L_*D_*D_],   s_wo_l[L_*D_*D_];
__device__ bf16 s_wgu_h[(size_t)L_*2*DI_*D_], s_wgu_l[(size_t)L_*2*DI_*D_];
__device__ bf16 s_wd_h[L_*D_*DI_],  s_wd_l[L_*D_*DI_];
__device__ bf16 s_emb_h[V_*D_],     s_emb_l[V_*D_];
__device__ bf16 s_hn_h[T_*D_],      s_hn_l[T_*D_];
__device__ bf16 s_q_h [T_*D_],      s_q_l [T_*D_];
__device__ bf16 s_k_h [T_*D_],      s_k_l [T_*D_];
__device__ bf16 s_vt_h[T_*D_],      s_vt_l[T_*D_];
__device__ bf16 s_y_h [T_*D_],      s_y_l [T_*D_];
__device__ bf16 s_ga_h[T_*DI_],     s_ga_l[T_*DI_];

// ---------------- helpers ----------------
__device__ __forceinline__ void split1(float v, bf16& h, bf16& l) {
    h = __float2bfloat16(v);
    l = __float2bfloat16(v - __bfloat162float(h));
}

__device__ __forceinline__ void split_store2(bf16* H, bf16* Lo, size_t off, float v0, float v1) {
    bf16 h0, l0, h1, l1;
    split1(v0, h0, l0);
    split1(v1, h1, l1);
    __nv_bfloat162 th; th.x = h0; th.y = h1;
    __nv_bfloat162 tl; tl.x = l0; tl.y = l1;
    *(__nv_bfloat162*)(H  + off) = th;
    *(__nv_bfloat162*)(Lo + off) = tl;
}

__device__ __forceinline__ void splitpack2(float a, float b, uint32_t& h, uint32_t& l) {
    bf16 ha, la, hb, lb;
    split1(a, ha, la);
    split1(b, hb, lb);
    h = ((uint32_t)__bfloat16_as_ushort(hb) << 16) | __bfloat16_as_ushort(ha);
    l = ((uint32_t)__bfloat16_as_ushort(lb) << 16) | __bfloat16_as_ushort(la);
}

__global__ void split_kernel(const float* __restrict__ x, bf16* __restrict__ h,
                             bf16* __restrict__ l, int n4) {
    int i = blockIdx.x * blockDim.x + threadIdx.x;
    if (i >= n4) return;
    float4 v = ((const float4*)x)[i];
    bf16 h0,l0,h1,l1,h2,l2,h3,l3;
    split1(v.x, h0, l0); split1(v.y, h1, l1);
    split1(v.z, h2, l2); split1(v.w, h3, l3);
    ((ushort4*)h)[i] = make_ushort4(__bfloat16_as_ushort(h0), __bfloat16_as_ushort(h1),
                                    __bfloat16_as_ushort(h2), __bfloat16_as_ushort(h3));
    ((ushort4*)l)[i] = make_ushort4(__bfloat16_as_ushort(l0), __bfloat16_as_ushort(l1),
                                    __bfloat16_as_ushort(l2), __bfloat16_as_ushort(l3));
}

__global__ void split_pack_kernel(const float* __restrict__ x, bf16* __restrict__ h,
                                  bf16* __restrict__ l, int row_off) {
    int i = blockIdx.x * blockDim.x + threadIdx.x;
    if (i >= L_*D_*D_/4) return;
    int lay = i / (D_*D_/4);
    int rem = i % (D_*D_/4);
    int r   = rem / (D_/4);
    int c4  = rem % (D_/4);
    float4 v = ((const float4*)x)[i];
    int d4 = lay*(3*D_*D_/4) + (row_off + r)*(D_/4) + c4;
    bf16 h0,l0,h1,l1,h2,l2,h3,l3;
    split1(v.x, h0, l0); split1(v.y, h1, l1);
    split1(v.z, h2, l2); split1(v.w, h3, l3);
    ((ushort4*)h)[d4] = make_ushort4(__bfloat16_as_ushort(h0), __bfloat16_as_ushort(h1),
                                     __bfloat16_as_ushort(h2), __bfloat16_as_ushort(h3));
    ((ushort4*)l)[d4] = make_ushort4(__bfloat16_as_ushort(l0), __bfloat16_as_ushort(l1),
                                     __bfloat16_as_ushort(l2), __bfloat16_as_ushort(l3));
}

__global__ void split_pack_gu_kernel(const float* __restrict__ wg, const float* __restrict__ wu,
                                     bf16* __restrict__ h, bf16* __restrict__ l) {
    int i = blockIdx.x * blockDim.x + threadIdx.x;
    if (i >= L_*DI_*D_/4) return;
    int lay = i / (DI_*D_/4);
    int rem = i % (DI_*D_/4);
    int r   = rem / (D_/4);
    int c4  = rem % (D_/4);
    float4 vg = ((const float4*)wg)[i];
    float4 vu = ((const float4*)wu)[i];
    size_t base = (size_t)lay*(2*DI_*D_/4);
    size_t dg = base + (size_t)(2*r)  *(D_/4) + c4;
    size_t du = base + (size_t)(2*r+1)*(D_/4) + c4;
    bf16 h0,l0,h1,l1,h2,l2,h3,l3;
    split1(vg.x, h0, l0); split1(vg.y, h1, l1);
    split1(vg.z, h2, l2); split1(vg.w, h3, l3);
    ((ushort4*)h)[dg] = make_ushort4(__bfloat16_as_ushort(h0), __bfloat16_as_ushort(h1),
                                     __bfloat16_as_ushort(h2), __bfloat16_as_ushort(h3));
    ((ushort4*)l)[dg] = make_ushort4(__bfloat16_as_ushort(l0), __bfloat16_as_ushort(l1),
                                     __bfloat16_as_ushort(l2), __bfloat16_as_ushort(l3));
    split1(vu.x, h0, l0); split1(vu.y, h1, l1);
    split1(vu.z, h2, l2); split1(vu.w, h3, l3);
    ((ushort4*)h)[du] = make_ushort4(__bfloat16_as_ushort(h0), __bfloat16_as_ushort(h1),
                                     __bfloat16_as_ushort(h2), __bfloat16_as_ushort(h3));
    ((ushort4*)l)[du] = make_ushort4(__bfloat16_as_ushort(l0), __bfloat16_as_ushort(l1),
                                     __bfloat16_as_ushort(l2), __bfloat16_as_ushort(l3));
}

__global__ void pack_bias_kernel(const float* __restrict__ bq, const float* __restrict__ bk,
                                 const float* __restrict__ bv, float* __restrict__ dst) {
    int i = blockIdx.x * blockDim.x + threadIdx.x;
    if (i >= L_*3*D_) return;
    int lay = i / (3*D_);
    int j   = i % (3*D_);
    float v = (j < D_) ? bq[lay*D_ + j]
            : (j < 2*D_) ? bk[lay*D_ + j - D_]
            : bv[lay*D_ + j - 2*D_];
    dst[i] = v;
}

// ---------------- small kernels ----------------
__global__ void embed_kernel(const int* __restrict__ x, const float* __restrict__ emb,
                             float* __restrict__ h) {
    int i = blockIdx.x * blockDim.x + threadIdx.x;
    int t = i / (D_/4);
    int c = i % (D_/4);
    float4 v = *(const float4*)(emb + (size_t)x[t]*D_ + c*4);
    *(float4*)(h + (size_t)t*D_ + c*4) = v;
}

__global__ void rope_cache_kernel() {
    int i = blockIdx.x * blockDim.x + threadIdx.x;
    if (i >= S_*32) return;
    int s = i / 32, j = i % 32;
    double inv = pow(10000.0, -(double)j / 32.0);
    double ph = (double)s * inv;
    g_cos[i] = (float)cos(ph);
    g_sin[i] = (float)sin(ph);
}

__global__ void rmsnorm_kernel(const float* __restrict__ x, const float* __restrict__ w,
                               bf16* __restrict__ oh, bf16* __restrict__ ol) {
    int t = blockIdx.x;
    int tid = threadIdx.x;
    const float* xp = x + (size_t)t*D_;
    float v[4];
    float s = 0.f;
    #pragma unroll
    for (int i = 0; i < 4; i++) { v[i] = xp[tid + i*256]; s += v[i]*v[i]; }
    #pragma unroll
    for (int off = 16; off; off >>= 1) s += __shfl_xor_sync(0xffffffffu, s, off);
    __shared__ float red[8];
    if ((tid & 31) == 0) red[tid >> 5] = s;
    __syncthreads();
    if (tid < 32) {
        float s2 = (tid < 8) ? red[tid] : 0.f;
        #pragma unroll
        for (int off = 4; off; off >>= 1) s2 += __shfl_xor_sync(0xffffffffu, s2, off);
        if (tid == 0) red[0] = s2;
    }
    __syncthreads();
    float r = rsqrtf(red[0] * (1.f/(float)D_) + 1e-6f);
    size_t base = (size_t)t*D_;
    #pragma unroll
    for (int i = 0; i < 4; i++) {
        int idx = tid + i*256;
        split1(w[idx] * v[i] * r, oh[base+idx], ol[base+idx]);
    }
}

// ---------------- bf16x3 GEMM on pre-split operands ----------------
enum { EPI_NONE = 0, EPI_BIAS_RES_AT = 2, EPI_RES_AT = 3,
       EPI_QKV = 8, EPI_SWIGLU = 9 };

__device__ __forceinline__ void mma_bf16(float* d, const uint32_t* a, const uint32_t* b) {
    asm volatile(
        "mma.sync.aligned.m16n8k16.row.col.f32.bf16.bf16.f32 "
        "{%0,%1,%2,%3}, {%4,%5,%6,%7}, {%8,%9}, {%0,%1,%2,%3};\n"
        : "+f"(d[0]), "+f"(d[1]), "+f"(d[2]), "+f"(d[3])
        : "r"(a[0]), "r"(a[1]), "r"(a[2]), "r"(a[3]),
          "r"(b[0]), "r"(b[1]));
}

#define CP_ASYNC16(dst, src) \
    asm volatile("cp.async.cg.shared.global [%0], [%1], 16;" :: "r"(dst), "l"(src))
#define CP_COMMIT() asm volatile("cp.async.commit_group;" ::: "memory")
#define CP_WAIT0()  asm volatile("cp.async.wait_group 0;"  ::: "memory")

// SPLITK: blockIdx.z indexes a K-range of size K/SPLITK; atomic epilogues accumulate.
template<int BM, int BN, int BK, int WM, int WN, int EPI, int MINB, int SPLITK>
__global__ __launch_bounds__((BM/WM)*(BN/WN)*32, MINB)
void gemm_tc(const bf16* __restrict__ Agh, const bf16* __restrict__ Agl,
             const bf16* __restrict__ Bgh, const bf16* __restrict__ Bgl,
             float* __restrict__ C, bf16* __restrict__ Oh, bf16* __restrict__ Ol,
             const float* __restrict__ bias,
             int M, int N, int K, int lda, int ldb, int ldc)
{
    constexpr int WARPS_N = BN/WN;
    constexpr int THREADS = (BM/WM)*(BN/WN)*32;
    constexpr int MT = WM/16;
    constexpr int NT = WN/8;
    constexpr int SP = BK/2 + 4;
    constexpr int SZA = BM*SP;
    constexpr int SZB = BN*SP;
    constexpr int STAGE = 2*SZA + 2*SZB;
    constexpr int NCA = (BM*BK/8)/THREADS;
    constexpr int NCB = (BN*BK/8)/THREADS;

    extern __shared__ uint32_t smem_u[];

    const int tid = threadIdx.x;
    const int m0 = blockIdx.y * BM;
    const int n0 = blockIdx.x * BN;
    const int KS   = K / SPLITK;
    const int Kofs = blockIdx.z * KS;

    const int warp = tid >> 5;
    const int lane = tid & 31;
    const int g = lane >> 2;
    const int c = lane & 3;
    const int wn = warp % WARPS_N;
    const int wm = warp / WARPS_N;

    float acc[MT][NT][4];
    #pragma unroll
    for (int i = 0; i < MT; i++)
        #pragma unroll
        for (int j = 0; j < NT; j++)
            #pragma unroll
            for (int r = 0; r < 4; r++) acc[i][j][r] = 0.f;

    const int nk = KS / BK;

    const uint32_t smb = (uint32_t)__cvta_generic_to_shared(smem_u);
    auto cp_tile = [&](int kt, int s) {
        const uint32_t Ah = smb + s*STAGE*4;
        const uint32_t Al = Ah + SZA*4;
        const uint32_t Bh = Al + SZA*4;
        const uint32_t Bl = Bh + SZB*4;
        #pragma unroll
        for (int i = 0; i < NCA; i++) {
            int f  = tid + i*THREADS;
            int r  = f / (BK/8);
            int c8 = f % (BK/8);
            size_t   go = (size_t)(m0+r)*lda + Kofs + kt + c8*8;
            uint32_t so = (uint32_t)(r*SP + c8*4)*4;
            CP_ASYNC16(Ah + so, Agh + go);
            CP_ASYNC16(Al + so, Agl + go);
        }
        #pragma unroll
        for (int i = 0; i < NCB; i++) {
            int f  = tid + i*THREADS;
            int r  = f / (BK/8);
            int c8 = f % (BK/8);
            size_t   go = (size_t)(n0+r)*ldb + Kofs + kt + c8*8;
            uint32_t so = (uint32_t)(r*SP + c8*4)*4;
            CP_ASYNC16(Bh + so, Bgh + go);
            CP_ASYNC16(Bl + so, Bgl + go);
        }
        CP_COMMIT();
    };

    auto compute_stage = [&](int cur) {
        const uint32_t* Ah = smem_u + cur*STAGE;
        const uint32_t* Al = Ah + SZA;
        const uint32_t* Bh = Al + SZA;
        const uint32_t* Bl = Bh + SZB;
        #pragma unroll
        for (int ks = 0; ks < BK; ks += 16) {
            const int kp = ks >> 1;
            uint32_t ah[MT][4], al[MT][4], bh[NT][2], bl[NT][2];
            #pragma unroll
            for (int i = 0; i < MT; i++) {
                int mr = wm*WM + i*16 + g;
                ah[i][0] = Ah[mr*SP     + kp + c];   al[i][0] = Al[mr*SP     + kp + c];
                ah[i][1] = Ah[(mr+8)*SP + kp + c];   al[i][1] = Al[(mr+8)*SP + kp + c];
                ah[i][2] = Ah[mr*SP     + kp + c+4]; al[i][2] = Al[mr*SP     + kp + c+4];
                ah[i][3] = Ah[(mr+8)*SP + kp + c+4]; al[i][3] = Al[(mr+8)*SP + kp + c+4];
            }
            #pragma unroll
            for (int j = 0; j < NT; j++) {
                int nr = wn*WN + j*8 + g;
                bh[j][0] = Bh[nr*SP + kp + c];   bl[j][0] = Bl[nr*SP + kp + c];
                bh[j][1] = Bh[nr*SP + kp + c+4]; bl[j][1] = Bl[nr*SP + kp + c+4];
            }
            #pragma unroll
            for (int i = 0; i < MT; i++)
                #pragma unroll
                for (int j = 0; j < NT; j++)
                    mma_bf16(acc[i][j], ah[i], bh[j]);
            #pragma unroll
            for (int i = 0; i < MT; i++)
                #pragma unroll
                for (int j = 0; j < NT; j++)
                    mma_bf16(acc[i][j], ah[i], bl[j]);
            #pragma unroll
            for (int i = 0; i < MT; i++)
                #pragma unroll
                for (int j = 0; j < NT; j++)
                    mma_bf16(acc[i][j], al[i], bh[j]);
        }
    };

    cp_tile(0, 0);
    CP_WAIT0();
    __syncthreads();

    for (int t = 0; t < nk; t++) {
        const int cur = t & 1;
        if (t + 1 < nk) cp_tile((t+1)*BK, cur ^ 1);
        compute_stage(cur);
        if (t + 1 < nk) CP_WAIT0();
        __syncthreads();
    }

    // ---------------- epilogues ----------------
    if (EPI == EPI_QKV) {
        if (n0 < 2*D_) {
            const bool isq = (n0 < D_);
            #pragma unroll
            for (int i = 0; i < MT; i++) {
                #pragma unroll
                for (int jj = 0; jj < NT/2; jj++) {
                    #pragma unroll
                    for (int rr = 0; rr < 2; rr++) {
                        int m = m0 + wm*WM + i*16 + g + rr*8;
                        int s = m & (S_-1);
                        #pragma unroll
                        for (int t2 = 0; t2 < 2; t2++) {
                            int n = n0 + jj*8 + 2*c + t2;
                            float a  = acc[i][jj]  [rr*2+t2] + bias[n];
                            float bb = acc[i][jj+4][rr*2+t2] + bias[n+32];
                            int d = n & 63;
                            float co = g_cos[s*32 + d];
                            float si = g_sin[s*32 + d];
                            float r0 = a*co - bb*si;
                            float r1 = bb*co + a*si;
                            int col = isq ? (n & (D_-1)) : (n - D_);
                            size_t o = (size_t)m*D_ + col;
                            if (isq) {
                                split1(r0, s_q_h[o],    s_q_l[o]);
                                split1(r1, s_q_h[o+32], s_q_l[o+32]);
                            } else {
                                split1(r0, s_k_h[o],    s_k_l[o]);
                                split1(r1, s_k_h[o+32], s_k_l[o+32]);
                            }
                        }
                    }
                }
            }
        } else {
            #pragma unroll
            for (int i = 0; i < MT; i++) {
                #pragma unroll
                for (int j = 0; j < NT; j++) {
                    int n = n0 + wn*WN + j*8 + 2*c;
                    #pragma unroll
                    for (int rr = 0; rr < 2; rr++) {
                        int m = m0 + wm*WM + i*16 + g + rr*8;
                        float v0 = acc[i][j][rr*2]   + bias[n];
                        float v1 = acc[i][j][rr*2+1] + bias[n+1];
                        int dg = n - 2*D_;
                        int hh = dg >> 6, dd = dg & 63;
                        int b  = m >> 10, s = m & 1023;
                        size_t o0 = (((size_t)b*H_ + hh)*DH_ + dd)*S_ + s;
                        split1(v0, Oh[o0],    Ol[o0]);
                        split1(v1, Oh[o0+S_], Ol[o0+S_]);
                    }
                }
            }
        }
        return;
    }

    #pragma unroll
    for (int i = 0; i < MT; i++) {
        #pragma unroll
        for (int j = 0; j < NT; j++) {
            int n = n0 + wn*WN + j*8 + 2*c;
            #pragma unroll
            for (int rr = 0; rr < 2; rr++) {
                int m = m0 + wm*WM + i*16 + g + rr*8;
                float v0 = acc[i][j][rr*2 + 0];
                float v1 = acc[i][j][rr*2 + 1];
                if (EPI == EPI_SWIGLU) {
                    float sw = v0 / (1.f + expf(-v0)) * v1;
                    size_t oo = (size_t)m*(ldc >> 1) + (n >> 1);
                    split1(sw, Oh[oo], Ol[oo]);
                    continue;
                }
                size_t off = (size_t)m*ldc + n;
                if (EPI == EPI_BIAS_RES_AT) {
                    if (SPLITK == 1 || blockIdx.z == 0) { v0 += bias[n]; v1 += bias[n+1]; }
                    atomicAdd(C + off,     v0);
                    atomicAdd(C + off + 1, v1);
                } else if (EPI == EPI_RES_AT) {
                    atomicAdd(C + off,     v0);
                    atomicAdd(C + off + 1, v1);
                } else if (EPI == EPI_NONE) {
                    *(float2*)(C + off) = make_float2(v0, v1);
                }
            }
        }
    }
}

// ================== flash attention ==================
#define FA_SP 36
#define FA_TW (64*FA_SP)
#define FA_SMEM ((2*FA_TW + 2*4*FA_TW)*4)

__global__ __launch_bounds__(128, 2)
void flash_attn_kernel(float scale)
{
    extern __shared__ uint32_t sm[];
    const int tid  = threadIdx.x;
    const int warp = tid >> 5;
    const int lane = tid & 31;
    const int g = lane >> 2;
    const int c = lane & 3;
    const int mb = gridDim.x - 1 - blockIdx.x;   // LPT: longest (diagonal-heavy) blocks first
    const int bh = blockIdx.y;
    const int b  = bh >> 4;
    const int hh = bh & 15;
    const int m0 = mb * 64;

    const uint32_t smb = (uint32_t)__cvta_generic_to_shared(sm);
    uint32_t* sQh = sm;
    uint32_t* sQl = sm + FA_TW;

    const size_t vbase = (size_t)bh * DH_ * S_;

    #pragma unroll
    for (int i = 0; i < 4; i++) {
        int f = tid + i*128;
        int r = f >> 3, c8 = f & 7;
        size_t go = ((size_t)(b*S_ + m0 + r))*D_ + hh*64 + c8*8;
        uint32_t so = (uint32_t)(r*FA_SP + c8*4)*4;
        CP_ASYNC16(smb + so,             s_q_h + go);
        CP_ASYNC16(smb + FA_TW*4 + so,   s_q_l + go);
    }

    auto cp_kv = [&](int kb, int s) {
        uint32_t kvb = smb + (2*FA_TW + s*4*FA_TW)*4;
        #pragma unroll
        for (int i = 0; i < 4; i++) {
            int f = tid + i*128;
            int r = f >> 3, c8 = f & 7;
            uint32_t so = (uint32_t)(r*FA_SP + c8*4)*4;
            size_t gok = ((size_t)(b*S_ + kb*64 + r))*D_ + hh*64 + c8*8;
            CP_ASYNC16(kvb + so,             s_k_h + gok);
            CP_ASYNC16(kvb + FA_TW*4 + so,   s_k_l + gok);
            size_t gov = vbase + (size_t)r*S_ + kb*64 + c8*8;
            CP_ASYNC16(kvb + 2*FA_TW*4 + so, s_vt_h + gov);
            CP_ASYNC16(kvb + 3*FA_TW*4 + so, s_vt_l + gov);
        }
        CP_COMMIT();
    };

    cp_kv(0, 0);
    CP_WAIT0();
    __syncthreads();

    float m_r[2] = {-INFINITY, -INFINITY};
    float l_r[2] = {0.f, 0.f};
    float Oa[8][4];
    #pragma unroll
    for (int j = 0; j < 8; j++)
        #pragma unroll
        for (int r = 0; r < 4; r++) Oa[j][r] = 0.f;

    const int mr = warp*16 + g;

    for (int kb = 0; kb <= mb; kb++) {
        const int cur = kb & 1;
        if (kb < mb) cp_kv(kb+1, cur ^ 1);

        float Sa[8][4];
        #pragma unroll
        for (int j = 0; j < 8; j++)
            #pragma unroll
            for (int r = 0; r < 4; r++) Sa[j][r] = 0.f;

        {
            const uint32_t* Bh = sm + 2*FA_TW + cur*4*FA_TW;
            const uint32_t* Bl = Bh + FA_TW;
            #pragma unroll
            for (int ks = 0; ks < 64; ks += 16) {
                const int kp = ks >> 1;
                uint32_t ah[4], al[4], bh[8][2], bl[8][2];
                ah[0] = sQh[mr*FA_SP     + kp + c];   al[0] = sQl[mr*FA_SP     + kp + c];
                ah[1] = sQh[(mr+8)*FA_SP + kp + c];   al[1] = sQl[(mr+8)*FA_SP + kp + c];
                ah[2] = sQh[mr*FA_SP     + kp + c+4]; al[2] = sQl[mr*FA_SP     + kp + c+4];
                ah[3] = sQh[(mr+8)*FA_SP + kp + c+4]; al[3] = sQl[(mr+8)*FA_SP + kp + c+4];
                #pragma unroll
                for (int j = 0; j < 8; j++) {
                    int nr = j*8 + g;
                    bh[j][0] = Bh[nr*FA_SP + kp + c];   bl[j][0] = Bl[nr*FA_SP + kp + c];
                    bh[j][1] = Bh[nr*FA_SP + kp + c+4]; bl[j][1] = Bl[nr*FA_SP + kp + c+4];
                }
                #pragma unroll
                for (int j = 0; j < 8; j++) mma_bf16(Sa[j], ah, bh[j]);
                #pragma unroll
                for (int j = 0; j < 8; j++) mma_bf16(Sa[j], ah, bl[j]);
                #pragma unroll
                for (int j = 0; j < 8; j++) mma_bf16(Sa[j], al, bh[j]);
            }
        }

        #pragma unroll
        for (int j = 0; j < 8; j++)
            #pragma unroll
            for (int r = 0; r < 4; r++) Sa[j][r] *= scale;
        if (kb == mb) {
            #pragma unroll
            for (int j = 0; j < 8; j++) {
                int col = kb*64 + j*8 + 2*c;
                #pragma unroll
                for (int rr = 0; rr < 2; rr++) {
                    int row = m0 + mr + rr*8;
                    if (col     > row) Sa[j][rr*2]   = -INFINITY;
                    if (col + 1 > row) Sa[j][rr*2+1] = -INFINITY;
                }
            }
        }

        #pragma unroll
        for (int rr = 0; rr < 2; rr++) {
            float mx = -INFINITY;
            #pragma unroll
            for (int j = 0; j < 8; j++)
                mx = fmaxf(mx, fmaxf(Sa[j][rr*2], Sa[j][rr*2+1]));
            mx = fmaxf(mx, __shfl_xor_sync(0xffffffffu, mx, 1));
            mx = fmaxf(mx, __shfl_xor_sync(0xffffffffu, mx, 2));
            float mnew  = fmaxf(m_r[rr], mx);
            float alpha = expf(m_r[rr] - mnew);
            float sum = 0.f;
            #pragma unroll
            for (int j = 0; j < 8; j++) {
                float p0 = expf(Sa[j][rr*2]   - mnew);
                float p1 = expf(Sa[j][rr*2+1] - mnew);
                Sa[j][rr*2] = p0; Sa[j][rr*2+1] = p1;
                sum += p0 + p1;
            }
            sum += __shfl_xor_sync(0xffffffffu, sum, 1);
            sum += __shfl_xor_sync(0xffffffffu, sum, 2);
            l_r[rr] = l_r[rr]*alpha + sum;
            m_r[rr] = mnew;
            #pragma unroll
            for (int j = 0; j < 8; j++) {
                Oa[j][rr*2]   *= alpha;
                Oa[j][rr*2+1] *= alpha;
            }
        }

        {
            const uint32_t* Vh = sm + 2*FA_TW + cur*4*FA_TW + 2*FA_TW;
            const uint32_t* Vl = Vh + FA_TW;
            #pragma unroll
            for (int ks = 0; ks < 64; ks += 16) {
                const int j0 = ks >> 3;
                const int kp = ks >> 1;
                uint32_t ph[4], pl[4];
                splitpack2(Sa[j0][0],   Sa[j0][1],   ph[0], pl[0]);
                splitpack2(Sa[j0][2],   Sa[j0][3],   ph[1], pl[1]);
                splitpack2(Sa[j0+1][0], Sa[j0+1][1], ph[2], pl[2]);
                splitpack2(Sa[j0+1][2], Sa[j0+1][3], ph[3], pl[3]);
                uint32_t bh[8][2], bl[8][2];
                #pragma unroll
                for (int j = 0; j < 8; j++) {
                    int nr = j*8 + g;
                    bh[j][0] = Vh[nr*FA_SP + kp + c];   bl[j][0] = Vl[nr*FA_SP + kp + c];
                    bh[j][1] = Vh[nr*FA_SP + kp + c+4]; bl[j][1] = Vl[nr*FA_SP + kp + c+4];
                }
                #pragma unroll
                for (int j = 0; j < 8; j++) mma_bf16(Oa[j], ph, bh[j]);
                #pragma unroll
                for (int j = 0; j < 8; j++) mma_bf16(Oa[j], ph, bl[j]);
                #pragma unroll
                for (int j = 0; j < 8; j++) mma_bf16(Oa[j], pl, bh[j]);
            }
        }

        if (kb < mb) CP_WAIT0();
        __syncthreads();
    }

    float inv0 = 1.f / l_r[0];
    float inv1 = 1.f / l_r[1];
    #pragma unroll
    for (int j = 0; j < 8; j++) {
        int d = j*8 + 2*c;
        size_t t0 = (size_t)(b*S_ + m0 + mr)*D_ + hh*64 + d;
        split_store2(s_y_h, s_y_l, t0,          Oa[j][0]*inv0, Oa[j][1]*inv0);
        split_store2(s_y_h, s_y_l, t0 + 8*D_,   Oa[j][2]*inv1, Oa[j][3]*inv1);
    }
}

// ---------------- host ----------------
template<int BM, int BN, int BK>
constexpr int smem_bytes() {
    return 2 * (2*BM*(BK/2+4) + 2*BN*(BK/2+4)) * 4;
}

extern "C" void kernel_launch(void* const* d_in, const int* in_sizes, int n_in,
                              void* d_out, int out_size) {
    const int*   x      = (const int*)  d_in[0];
    const float* emb    = (const float*)d_in[1];
    const float* wq     = (const float*)d_in[2];
    const float* bq     = (const float*)d_in[3];
    const float* wk     = (const float*)d_in[4];
    const float* bk     = (const float*)d_in[5];
    const float* wv     = (const float*)d_in[6];
    const float* bv     = (const float*)d_in[7];
    const float* wo     = (const float*)d_in[8];
    const float* bo     = (const float*)d_in[9];
    const float* w_gate = (const float*)d_in[10];
    const float* w_up   = (const float*)d_in[11];
    const float* w_down = (const float*)d_in[12];
    const float* ln1    = (const float*)d_in[13];
    const float* ln2    = (const float*)d_in[14];
    const float* norm_w = (const float*)d_in[15];
    float* out = (float*)d_out;

    float *h, *bqkv;
    cudaGetSymbolAddress((void**)&h,    g_h);
    cudaGetSymbolAddress((void**)&bqkv, g_bqkv);

    bf16 *wqkvh,*wqkvl,*woh,*wol,*wguh,*wgul,*wdh,*wdl,*embh,*embl;
    bf16 *hnh,*hnl,*vth,*vtl,*yh,*yl,*gah,*gal;
    cudaGetSymbolAddress((void**)&wqkvh, s_wqkv_h); cudaGetSymbolAddress((void**)&wqkvl, s_wqkv_l);
    cudaGetSymbolAddress((void**)&woh, s_wo_h);  cudaGetSymbolAddress((void**)&wol, s_wo_l);
    cudaGetSymbolAddress((void**)&wguh, s_wgu_h); cudaGetSymbolAddress((void**)&wgul, s_wgu_l);
    cudaGetSymbolAddress((void**)&wdh, s_wd_h);  cudaGetSymbolAddress((void**)&wdl, s_wd_l);
    cudaGetSymbolAddress((void**)&embh, s_emb_h); cudaGetSymbolAddress((void**)&embl, s_emb_l);
    cudaGetSymbolAddress((void**)&hnh, s_hn_h);  cudaGetSymbolAddress((void**)&hnl, s_hn_l);
    cudaGetSymbolAddress((void**)&vth, s_vt_h);  cudaGetSymbolAddress((void**)&vtl, s_vt_l);
    cudaGetSymbolAddress((void**)&yh,  s_y_h);   cudaGetSymbolAddress((void**)&yl,  s_y_l);
    cudaGetSymbolAddress((void**)&gah, s_ga_h);  cudaGetSymbolAddress((void**)&gal, s_ga_l);

    constexpr int SM_S = smem_bytes<128,128,32>();   // 81920
    constexpr int SM_P = smem_bytes<128,64,32>();    // 61440

    cudaFuncSetAttribute(gemm_tc<128,64,32,32,64,EPI_QKV,3,1>,         cudaFuncAttributeMaxDynamicSharedMemorySize, SM_P);
    cudaFuncSetAttribute(gemm_tc<128,64,32,64,32,EPI_BIAS_RES_AT,3,2>, cudaFuncAttributeMaxDynamicSharedMemorySize, SM_P);
    cudaFuncSetAttribute(gemm_tc<128,128,32,64,64,EPI_SWIGLU,2,1>,     cudaFuncAttributeMaxDynamicSharedMemorySize, SM_S);
    cudaFuncSetAttribute(gemm_tc<128,64,32,64,32,EPI_RES_AT,3,4>,      cudaFuncAttributeMaxDynamicSharedMemorySize, SM_P);
    cudaFuncSetAttribute(gemm_tc<128,128,32,64,64,EPI_NONE,2,1>,       cudaFuncAttributeMaxDynamicSharedMemorySize, SM_S);
    cudaFuncSetAttribute(flash_attn_kernel,                            cudaFuncAttributeMaxDynamicSharedMemorySize, FA_SMEM);

    // ---- prep ----
    auto split_launch = [](const float* src, bf16* dh, bf16* dl, size_t n) {
        int n4 = (int)(n / 4);
        split_kernel<<<(n4 + 255)/256, 256>>>(src, dh, dl, n4);
    };
    int nw4 = L_*D_*D_/4;
    split_pack_kernel<<<(nw4+255)/256, 256>>>(wq, wqkvh, wqkvl, 0);
    split_pack_kernel<<<(nw4+255)/256, 256>>>(wk, wqkvh, wqkvl, D_);
    split_pack_kernel<<<(nw4+255)/256, 256>>>(wv, wqkvh, wqkvl, 2*D_);
    pack_bias_kernel<<<(L_*3*D_+255)/256, 256>>>(bq, bk, bv, bqkv);
    split_launch(wo, woh, wol, (size_t)L_*D_*D_);
    int ngu4 = L_*DI_*D_/4;
    split_pack_gu_kernel<<<(ngu4+255)/256, 256>>>(w_gate, w_up, wguh, wgul);
    split_launch(w_down, wdh, wdl, (size_t)L_*D_*DI_);
    split_launch(emb, embh, embl, (size_t)V_*D_);

    embed_kernel<<<T_*D_/4/256, 256>>>(x, emb, h);
    rope_cache_kernel<<<(S_*32 + 255)/256, 256>>>();

    const dim3 gqkv(3*D_/64, T_/128, 1);
    const dim3 gpz2(D_/64,  T_/128, 2);      // wo: split-K x2
    const dim3 gpz4(D_/64,  T_/128, 4);      // down: split-K x4
    const dim3 ggu(2*DI_/128, T_/128, 1);
    const dim3 gfa(S_/64, B_*H_, 1);

    for (int l = 0; l < L_; l++) {
        rmsnorm_kernel<<<T_, 256>>>(h, ln1 + (size_t)l*D_, hnh, hnl);

        gemm_tc<128,64,32,32,64,EPI_QKV,3,1><<<gqkv,128,SM_P>>>(
            hnh, hnl, wqkvh + (size_t)l*3*D_*D_, wqkvl + (size_t)l*3*D_*D_,
            nullptr, vth, vtl, bqkv + (size_t)l*3*D_,
            T_, 3*D_, D_, D_, D_, 0);

        flash_attn_kernel<<<gfa, 128, FA_SMEM>>>(0.125f);

        gemm_tc<128,64,32,64,32,EPI_BIAS_RES_AT,3,2><<<gpz2,128,SM_P>>>(
            yh, yl, woh + (size_t)l*D_*D_, wol + (size_t)l*D_*D_,
            h, nullptr, nullptr, bo + (size_t)l*D_,
            T_, D_, D_, D_, D_, D_);

        rmsnorm_kernel<<<T_, 256>>>(h, ln2 + (size_t)l*D_, hnh, hnl);

        gemm_tc<128,128,32,64,64,EPI_SWIGLU,2,1><<<ggu,128,SM_S>>>(
            hnh, hnl, wguh + (size_t)l*2*DI_*D_, wgul + (size_t)l*2*DI_*D_,
            nullptr, gah, gal, nullptr,
            T_, 2*DI_, D_, D_, D_, 2*DI_);

        gemm_tc<128,64,32,64,32,EPI_RES_AT,3,4><<<gpz4,128,SM_P>>>(
            gah, gal, wdh + (size_t)l*D_*DI_, wdl + (size_t)l*D_*DI_,
            h, nullptr, nullptr, nullptr,
            T_, D_, DI_, DI_, DI_, D_);
    }

    rmsnorm_kernel<<<T_, 256>>>(h, norm_w, hnh, hnl);

    const dim3 gl(V_/128, T_/128, 1);
    gemm_tc<128,128,32,64,64,EPI_NONE,2,1><<<gl,128,SM_S>>>(
        hnh, hnl, embh, embl, out, nullptr, nullptr, nullptr,
        T_, V_, D_, D_, D_, V_);
}